// round 3
// baseline (speedup 1.0000x reference)
#include <cuda_runtime.h>
#include <math.h>

#define BB 2
#define SS_ 2048
#define DD 512
#define HH 8
#define DKV 64
#define DFF 2048
#define NTOK (BB*SS_)          // 4096
#define EPS 1e-5f

typedef unsigned long long ull;

// ---------------- packed f32x2 helpers (sm_103a FFMA2) ---------------------
__device__ __forceinline__ ull pk2(float x, float y) {
    ull r; asm("mov.b64 %0, {%1, %2};" : "=l"(r) : "f"(x), "f"(y)); return r;
}
__device__ __forceinline__ void fma2(ull& d, ull a, ull b) {
    asm("fma.rn.f32x2 %0, %1, %2, %0;" : "+l"(d) : "l"(a), "l"(b));
}
__device__ __forceinline__ float2 upk(ull p) {
    float2 v; asm("mov.b64 {%0, %1}, %2;" : "=f"(v.x), "=f"(v.y) : "l"(p)); return v;
}

// ------------------------------ scratch (device globals) -------------------
__device__ float g_qb[BB*HH*SS_*DKV];      // [B,H,S,64]
__device__ float g_kb[BB*HH*SS_*DKV];
__device__ float g_vb[BB*HH*SS_*DKV];
__device__ float g_ctx[NTOK*DD];
__device__ float g_t1[NTOK*DD];
__device__ float g_ao[NTOK*DD];
__device__ float g_h[NTOK*DFF];
__device__ float g_t2[NTOK*DD];
__device__ int   g_maskmode;               // 0 = int32 mask, 1 = uint8 mask

// ------------------------------ mask dtype detection -----------------------
__global__ void detect_mask_kernel(const unsigned int* __restrict__ m)
{
    if (threadIdx.x == 0 && blockIdx.x == 0) {
        int mode = 0;
        for (int i = 0; i < 4096; i++) {
            if (m[i] > 1u) { mode = 1; break; }
        }
        g_maskmode = mode;
    }
}

// ------------------------------ GEMM body (FFMA2) --------------------------
// 128x128 tile, 8x8 per thread, BK=8. A staged DUPLICATED (pairs) in smem.
__device__ __forceinline__ void gemm128_body(
    const float* __restrict__ A, const float* __restrict__ W,
    const float* __restrict__ bias, const float* __restrict__ resid,
    float* __restrict__ C, int N, int K, int doRelu, int headStore,
    int rowBase, int colBase, float (*Asd)[264], float (*Bs)[128])
{
    int tid = threadIdx.x;
    int ty = tid >> 4, tx = tid & 15;

    int a_m = tid >> 1;            // 0..127
    int a_k4 = (tid & 1) * 4;      // 0 or 4
    int b_k = tid >> 5;            // 0..7
    int b_n4 = (tid & 31) * 4;     // 0..124

    const float* Ap = A + (size_t)(rowBase + a_m) * K + a_k4;
    const float* Wp = W + colBase + b_n4;

    ull acc[8][4];
#pragma unroll
    for (int i = 0; i < 8; i++)
#pragma unroll
        for (int j = 0; j < 4; j++) acc[i][j] = 0ull;

    for (int k0 = 0; k0 < K; k0 += 8) {
        float4 av = *(const float4*)(Ap + k0);
        float4 bv = *(const float4*)(Wp + (size_t)(k0 + b_k) * N);
        __syncthreads();
        *(float2*)&Asd[a_k4 + 0][2 * a_m] = make_float2(av.x, av.x);
        *(float2*)&Asd[a_k4 + 1][2 * a_m] = make_float2(av.y, av.y);
        *(float2*)&Asd[a_k4 + 2][2 * a_m] = make_float2(av.z, av.z);
        *(float2*)&Asd[a_k4 + 3][2 * a_m] = make_float2(av.w, av.w);
        *(float4*)&Bs[b_k][b_n4] = bv;
        __syncthreads();
#pragma unroll
        for (int kk = 0; kk < 8; kk++) {
            ull a2[8], b2[4];
#pragma unroll
            for (int i = 0; i < 8; i++)
                a2[i] = *(const ull*)&Asd[kk][2 * (ty * 8 + i)];
#pragma unroll
            for (int j = 0; j < 4; j++)
                b2[j] = *(const ull*)&Bs[kk][tx * 8 + 2 * j];
#pragma unroll
            for (int i = 0; i < 8; i++)
#pragma unroll
                for (int j = 0; j < 4; j++) fma2(acc[i][j], a2[i], b2[j]);
        }
    }

#pragma unroll
    for (int i = 0; i < 8; i++) {
        int row = rowBase + ty * 8 + i;
#pragma unroll
        for (int j2 = 0; j2 < 4; j2++) {
            float2 c2 = upk(acc[i][j2]);
            float cc[2] = {c2.x, c2.y};
#pragma unroll
            for (int e = 0; e < 2; e++) {
                int col = colBase + tx * 8 + 2 * j2 + e;
                float c = cc[e] + bias[col];
                if (resid) c += resid[(size_t)row * N + col];
                if (doRelu) c = fmaxf(c, 0.f);
                if (headStore) {
                    int b_ = row / SS_, s_ = row % SS_;
                    int h_ = col >> 6, d_ = col & 63;
                    C[(((size_t)(b_ * HH + h_)) * SS_ + s_) * 64 + d_] = c;
                } else {
                    C[(size_t)row * N + col] = c;
                }
            }
        }
    }
}

__global__ __launch_bounds__(256) void sgemm_kernel(
    const float* __restrict__ A, const float* __restrict__ W,
    const float* __restrict__ bias, const float* __restrict__ resid,
    float* __restrict__ C, int N, int K, int doRelu, int headStore)
{
    __shared__ float Asd[8][264];
    __shared__ float Bs[8][128];
    gemm128_body(A, W, bias, resid, C, N, K, doRelu, headStore,
                 blockIdx.y * 128, blockIdx.x * 128, Asd, Bs);
}

// Fused QKV: grid.x = 12 (sel = x>>2, colBase = (x&3)*128)
__global__ __launch_bounds__(256) void qkv_kernel(
    const float* __restrict__ A,
    const float* __restrict__ Wq, const float* __restrict__ bq,
    const float* __restrict__ Wk, const float* __restrict__ bk,
    const float* __restrict__ Wv, const float* __restrict__ bv,
    float* __restrict__ q, float* __restrict__ k, float* __restrict__ v)
{
    __shared__ float Asd[8][264];
    __shared__ float Bs[8][128];
    int sel = blockIdx.x >> 2;
    const float* W = (sel == 0) ? Wq : (sel == 1) ? Wk : Wv;
    const float* bias = (sel == 0) ? bq : (sel == 1) ? bk : bv;
    float* C = (sel == 0) ? q : (sel == 1) ? k : v;
    gemm128_body(A, W, bias, nullptr, C, DD, DD, 0, 1,
                 blockIdx.y * 128, (blockIdx.x & 3) * 128, Asd, Bs);
}

// ------------------------------ fused attention ---------------------------
// grid (S/16, B*H), 256 threads. 16 query rows/CTA, full 2048 keys in SMEM.
#define SSP 2052
#define ATTN_SMEM_FLOATS (16*SSP + 16384 + 2048 + 16)
#define ATTN_SMEM_BYTES  (ATTN_SMEM_FLOATS * 4)

__global__ __launch_bounds__(256) void attn_kernel(
    const float* __restrict__ q, const float* __restrict__ k,
    const float* __restrict__ v, const void* __restrict__ mask,
    float* __restrict__ attn, float* __restrict__ ctx)
{
    extern __shared__ float smem[];
    float* ss  = smem;                 // 16 x SSP (scores / exp values)
    float* kvs = smem + 16 * SSP;      // 16384: k^T [64][132] or v [2][128][64]
    float* qsd = kvs + 16384;          // 2048: q DUPLICATED [16][128]; reused as pbuf
    float* invs = qsd + 2048;          // 16: per-row 1/sum

    int tid = threadIdx.x;
    int bh = blockIdx.y;
    int b_ = bh >> 3;
    int h_ = bh & 7;
    int row0 = blockIdx.x * 16;
    int maskmode = g_maskmode;

    const float* qptr = q + ((size_t)bh * SS_ + row0) * 64;
    const float* kptr = k + (size_t)bh * SS_ * 64;
    const float* vptr = v + (size_t)bh * SS_ * 64;
    const int* maskp32 = (const int*)mask + (size_t)b_ * SS_ * SS_;
    const unsigned char* maskp8 = (const unsigned char*)mask + (size_t)b_ * SS_ * SS_;

    // stage q duplicated: qsd[row][2d] = qsd[row][2d+1] = q[row][d]
    {
        float4 qv = ((const float4*)qptr)[tid];
        int row = tid >> 4;
        int d0 = (tid & 15) << 2;
        float* dst = qsd + row * 128 + 2 * d0;
        *(float4*)dst = make_float4(qv.x, qv.x, qv.y, qv.y);
        *(float4*)(dst + 4) = make_float4(qv.z, qv.z, qv.w, qv.w);
    }
    __syncthreads();

    int wy = tid >> 5;                 // warp -> rows (wy, wy+8)
    int lx = tid & 31;                 // lane -> 4 consecutive cols

    // ---------------- scores: 16 tiles of 128 keys (FFMA2) ----------------
    for (int ct = 0; ct < 16; ct++) {
        __syncthreads();
#pragma unroll
        for (int t = 0; t < 8; t++) {
            int idx = tid + t * 256;
            int col = idx >> 4;
            int d4 = (idx & 15) << 2;
            float4 kv4 = *(const float4*)(kptr + (size_t)(ct * 128 + col) * 64 + d4);
            kvs[(d4 + 0) * 132 + col] = kv4.x;
            kvs[(d4 + 1) * 132 + col] = kv4.y;
            kvs[(d4 + 2) * 132 + col] = kv4.z;
            kvs[(d4 + 3) * 132 + col] = kv4.w;
        }
        __syncthreads();

        ull acc00 = 0ull, acc01 = 0ull, acc10 = 0ull, acc11 = 0ull;
#pragma unroll 8
        for (int d = 0; d < 64; d++) {
            ull q0 = *(const ull*)&qsd[wy * 128 + 2 * d];
            ull q1 = *(const ull*)&qsd[(wy + 8) * 128 + 2 * d];
            ull k01 = *(const ull*)&kvs[d * 132 + lx * 4];
            ull k23 = *(const ull*)&kvs[d * 132 + lx * 4 + 2];
            fma2(acc00, q0, k01); fma2(acc01, q0, k23);
            fma2(acc10, q1, k01); fma2(acc11, q1, k23);
        }
        float2 a0lo = upk(acc00), a0hi = upk(acc01);
        float2 a1lo = upk(acc10), a1hi = upk(acc11);
        float a0[4] = {a0lo.x, a0lo.y, a0hi.x, a0hi.y};
        float a1[4] = {a1lo.x, a1lo.y, a1hi.x, a1hi.y};

        int c0 = ct * 128 + lx * 4;
        int m0x, m0y, m0z, m0w, m1x, m1y, m1z, m1w;
        if (maskmode == 0) {
            int4 mi0 = *(const int4*)(maskp32 + (size_t)(row0 + wy) * SS_ + c0);
            int4 mi1 = *(const int4*)(maskp32 + (size_t)(row0 + wy + 8) * SS_ + c0);
            m0x = mi0.x; m0y = mi0.y; m0z = mi0.z; m0w = mi0.w;
            m1x = mi1.x; m1y = mi1.y; m1z = mi1.z; m1w = mi1.w;
        } else {
            uchar4 mb0 = *(const uchar4*)(maskp8 + (size_t)(row0 + wy) * SS_ + c0);
            uchar4 mb1 = *(const uchar4*)(maskp8 + (size_t)(row0 + wy + 8) * SS_ + c0);
            m0x = mb0.x; m0y = mb0.y; m0z = mb0.z; m0w = mb0.w;
            m1x = mb1.x; m1y = mb1.y; m1z = mb1.z; m1w = mb1.w;
        }
        float4 s0v, s1v;
        s0v.x = m0x ? -1e9f : a0[0] * 0.125f;
        s0v.y = m0y ? -1e9f : a0[1] * 0.125f;
        s0v.z = m0z ? -1e9f : a0[2] * 0.125f;
        s0v.w = m0w ? -1e9f : a0[3] * 0.125f;
        s1v.x = m1x ? -1e9f : a1[0] * 0.125f;
        s1v.y = m1y ? -1e9f : a1[1] * 0.125f;
        s1v.z = m1z ? -1e9f : a1[2] * 0.125f;
        s1v.w = m1w ? -1e9f : a1[3] * 0.125f;
        *(float4*)&ss[wy * SSP + c0] = s0v;
        *(float4*)&ss[(wy + 8) * SSP + c0] = s1v;
    }

    // ---------------- softmax -------------------------------------------
    float mx0 = -1e30f, mx1 = -1e30f;
#pragma unroll
    for (int ct = 0; ct < 16; ct++) {
        int c0 = ct * 128 + lx * 4;
        float4 x0 = *(float4*)&ss[wy * SSP + c0];
        float4 x1 = *(float4*)&ss[(wy + 8) * SSP + c0];
        mx0 = fmaxf(mx0, fmaxf(fmaxf(x0.x, x0.y), fmaxf(x0.z, x0.w)));
        mx1 = fmaxf(mx1, fmaxf(fmaxf(x1.x, x1.y), fmaxf(x1.z, x1.w)));
    }
#pragma unroll
    for (int o = 16; o; o >>= 1) {
        mx0 = fmaxf(mx0, __shfl_xor_sync(0xffffffffu, mx0, o));
        mx1 = fmaxf(mx1, __shfl_xor_sync(0xffffffffu, mx1, o));
    }
    float sm0 = 0.f, sm1 = 0.f;
#pragma unroll
    for (int ct = 0; ct < 16; ct++) {
        int c0 = ct * 128 + lx * 4;
        float4 x0 = *(float4*)&ss[wy * SSP + c0];
        float4 x1 = *(float4*)&ss[(wy + 8) * SSP + c0];
        x0.x = __expf(x0.x - mx0); x0.y = __expf(x0.y - mx0);
        x0.z = __expf(x0.z - mx0); x0.w = __expf(x0.w - mx0);
        x1.x = __expf(x1.x - mx1); x1.y = __expf(x1.y - mx1);
        x1.z = __expf(x1.z - mx1); x1.w = __expf(x1.w - mx1);
        sm0 += x0.x + x0.y + x0.z + x0.w;
        sm1 += x1.x + x1.y + x1.z + x1.w;
        *(float4*)&ss[wy * SSP + c0] = x0;
        *(float4*)&ss[(wy + 8) * SSP + c0] = x1;
    }
#pragma unroll
    for (int o = 16; o; o >>= 1) {
        sm0 += __shfl_xor_sync(0xffffffffu, sm0, o);
        sm1 += __shfl_xor_sync(0xffffffffu, sm1, o);
    }
    float inv0 = 1.f / sm0, inv1 = 1.f / sm1;
    if (lx == 0) { invs[wy] = inv0; invs[wy + 8] = inv1; }

    if (attn) {
#pragma unroll
        for (int ct = 0; ct < 16; ct++) {
            int c0 = ct * 128 + lx * 4;
            float4 x0 = *(float4*)&ss[wy * SSP + c0];
            float4 x1 = *(float4*)&ss[(wy + 8) * SSP + c0];
            x0.x *= inv0; x0.y *= inv0; x0.z *= inv0; x0.w *= inv0;
            x1.x *= inv1; x1.y *= inv1; x1.z *= inv1; x1.w *= inv1;
            *(float4*)(attn + ((size_t)bh * SS_ + row0 + wy) * SS_ + c0) = x0;
            *(float4*)(attn + ((size_t)bh * SS_ + row0 + wy + 8) * SS_ + c0) = x1;
        }
    }

    // ---------------- attn @ V (FFMA2, kk-split halves) -------------------
    int g = tid >> 7;
    int t = tid & 127;
    int tyv = t >> 4;
    int cv = (t & 15) << 2;
    ull vacc00 = 0ull, vacc01 = 0ull, vacc10 = 0ull, vacc11 = 0ull;

    for (int step = 0; step < 8; step++) {
        __syncthreads();
#pragma unroll
        for (int t2 = 0; t2 < 16; t2++) {
            int idx = tid + t2 * 256;
            int gg = idx >> 11;
            int rem = idx & 2047;
            int kk = rem >> 4;
            int c4 = (rem & 15) << 2;
            int tile = gg ? (step + 8) : step;
            *(float4*)&kvs[gg * 8192 + kk * 64 + c4] =
                *(const float4*)(vptr + (size_t)(tile * 128 + kk) * 64 + c4);
        }
        __syncthreads();
        int colbase = (g ? (step + 8) : step) * 128;
#pragma unroll 8
        for (int kk = 0; kk < 128; kk++) {
            float p0 = ss[tyv * SSP + colbase + kk];
            float p1 = ss[(tyv + 8) * SSP + colbase + kk];
            ull p0d = pk2(p0, p0);
            ull p1d = pk2(p1, p1);
            ull v01 = *(const ull*)&kvs[g * 8192 + kk * 64 + cv];
            ull v23 = *(const ull*)&kvs[g * 8192 + kk * 64 + cv + 2];
            fma2(vacc00, p0d, v01); fma2(vacc01, p0d, v23);
            fma2(vacc10, p1d, v01); fma2(vacc11, p1d, v23);
        }
    }
    float2 l0 = upk(vacc00), h0 = upk(vacc01);
    float2 l1 = upk(vacc10), h1 = upk(vacc11);
    float vacc0[4] = {l0.x, l0.y, h0.x, h0.y};
    float vacc1[4] = {l1.x, l1.y, h1.x, h1.y};

    __syncthreads();                   // q (qsd) no longer needed; reuse as pbuf
    float* pbuf = qsd;
    if (g == 1) {
        float* p = pbuf + t * 8;
        p[0] = vacc0[0]; p[1] = vacc0[1]; p[2] = vacc0[2]; p[3] = vacc0[3];
        p[4] = vacc1[0]; p[5] = vacc1[1]; p[6] = vacc1[2]; p[7] = vacc1[3];
    }
    __syncthreads();
    if (g == 0) {
        float* p = pbuf + t * 8;
        float i0 = invs[tyv], i1 = invs[tyv + 8];
        float4 o0, o1;
        o0.x = (vacc0[0] + p[0]) * i0; o0.y = (vacc0[1] + p[1]) * i0;
        o0.z = (vacc0[2] + p[2]) * i0; o0.w = (vacc0[3] + p[3]) * i0;
        o1.x = (vacc1[0] + p[4]) * i1; o1.y = (vacc1[1] + p[5]) * i1;
        o1.z = (vacc1[2] + p[6]) * i1; o1.w = (vacc1[3] + p[7]) * i1;
        int gr0 = row0 + tyv, gr1 = row0 + tyv + 8;
        *(float4*)&ctx[((size_t)(b_ * SS_ + gr0)) * DD + h_ * 64 + cv] = o0;
        *(float4*)&ctx[((size_t)(b_ * SS_ + gr1)) * DD + h_ * 64 + cv] = o1;
    }
}

// ------------------------------ layernorm over rows of 512 -----------------
__global__ __launch_bounds__(128) void ln_kernel(
    const float* __restrict__ x, const float* __restrict__ gamma,
    const float* __restrict__ beta, float* __restrict__ out)
{
    int row = blockIdx.x;
    int tid = threadIdx.x;
    __shared__ float red[4];
    float4 v = ((const float4*)(x + (size_t)row * DD))[tid];
    float s = v.x + v.y + v.z + v.w;
#pragma unroll
    for (int o = 16; o; o >>= 1) s += __shfl_xor_sync(0xffffffffu, s, o);
    if ((tid & 31) == 0) red[tid >> 5] = s;
    __syncthreads();
    float mu = (red[0] + red[1] + red[2] + red[3]) * (1.f / DD);
    float dx = v.x - mu, dy = v.y - mu, dz = v.z - mu, dw = v.w - mu;
    float s2 = dx * dx + dy * dy + dz * dz + dw * dw;
#pragma unroll
    for (int o = 16; o; o >>= 1) s2 += __shfl_xor_sync(0xffffffffu, s2, o);
    __syncthreads();
    if ((tid & 31) == 0) red[tid >> 5] = s2;
    __syncthreads();
    float var = (red[0] + red[1] + red[2] + red[3]) * (1.f / DD);
    float inv = rsqrtf(var + EPS);
    float4 gg = ((const float4*)gamma)[tid];
    float4 bb = ((const float4*)beta)[tid];
    float4 o;
    o.x = dx * inv * gg.x + bb.x;
    o.y = dy * inv * gg.y + bb.y;
    o.z = dz * inv * gg.z + bb.z;
    o.w = dw * inv * gg.w + bb.w;
    *(float4*)(out + (size_t)row * DD + tid * 4) = o;
}

// ------------------------------ launch -------------------------------------
extern "C" void kernel_launch(void* const* d_in, const int* in_sizes, int n_in,
                              void* d_out, int out_size)
{
    const float* x   = (const float*)d_in[0];
    const void*  mask = d_in[1];
    const float* Wq  = (const float*)d_in[2];
    const float* bq  = (const float*)d_in[3];
    const float* Wk  = (const float*)d_in[4];
    const float* bk  = (const float*)d_in[5];
    const float* Wv  = (const float*)d_in[6];
    const float* bv  = (const float*)d_in[7];
    const float* Wo  = (const float*)d_in[8];
    const float* bo  = (const float*)d_in[9];
    const float* ln1g = (const float*)d_in[10];
    const float* ln1b = (const float*)d_in[11];
    const float* W1  = (const float*)d_in[12];
    const float* b1  = (const float*)d_in[13];
    const float* W2  = (const float*)d_in[14];
    const float* b2  = (const float*)d_in[15];
    const float* ln2g = (const float*)d_in[16];
    const float* ln2b = (const float*)d_in[17];

    float* out = (float*)d_out;
    const long OUT_ELEMS = (long)BB * SS_ * DD;
    const long ATTN_ELEMS = (long)BB * HH * SS_ * SS_;
    float* attn_ptr = ((long)out_size >= OUT_ELEMS + ATTN_ELEMS)
                        ? (out + OUT_ELEMS) : nullptr;

    float *qp, *kp, *vp, *ctxp, *t1p, *aop, *hp, *t2p;
    cudaGetSymbolAddress((void**)&qp, g_qb);
    cudaGetSymbolAddress((void**)&kp, g_kb);
    cudaGetSymbolAddress((void**)&vp, g_vb);
    cudaGetSymbolAddress((void**)&ctxp, g_ctx);
    cudaGetSymbolAddress((void**)&t1p, g_t1);
    cudaGetSymbolAddress((void**)&aop, g_ao);
    cudaGetSymbolAddress((void**)&hp, g_h);
    cudaGetSymbolAddress((void**)&t2p, g_t2);

    cudaFuncSetAttribute(attn_kernel,
                         cudaFuncAttributeMaxDynamicSharedMemorySize,
                         ATTN_SMEM_BYTES);

    dim3 blk(256);
    detect_mask_kernel<<<1, 32>>>((const unsigned int*)mask);
    // fused QKV projections (384 CTAs)
    qkv_kernel<<<dim3(12, 32), blk>>>(x, Wq, bq, Wk, bk, Wv, bv, qp, kp, vp);
    // fused attention
    attn_kernel<<<dim3(SS_ / 16, BB * HH), blk, ATTN_SMEM_BYTES>>>(
        qp, kp, vp, mask, attn_ptr, ctxp);
    // Wo projection + residual, then LN1
    sgemm_kernel<<<dim3(4, 32), blk>>>(ctxp, Wo, bo, x, t1p, DD, DD, 0, 0);
    ln_kernel<<<NTOK, 128>>>(t1p, ln1g, ln1b, aop);
    // FFN
    sgemm_kernel<<<dim3(16, 32), blk>>>(aop, W1, b1, nullptr, hp, DFF, DD, 1, 0);
    sgemm_kernel<<<dim3(4, 32), blk>>>(hp, W2, b2, aop, t2p, DD, DFF, 0, 0);
    ln_kernel<<<NTOK, 128>>>(t2p, ln2g, ln2b, out);
}

// round 5
// speedup vs baseline: 1.6034x; 1.6034x over previous
#include <cuda_runtime.h>
#include <math.h>

#define BB 2
#define SS_ 2048
#define DD 512
#define HH 8
#define DFF 2048
#define NTOK (BB*SS_)          // 4096
#define EPS 1e-5f

typedef unsigned long long ull;
typedef unsigned int u32;

// ---------------- tf32 mma helpers (sm_80+ mma.sync) -----------------------
__device__ __forceinline__ u32 f2tf(float x) {
    u32 r; asm("cvt.rna.tf32.f32 %0, %1;" : "=r"(r) : "f"(x)); return r;
}
__device__ __forceinline__ void mma8(float4& d, u32 a0, u32 a1, u32 a2, u32 a3,
                                     u32 b0, u32 b1) {
    asm("mma.sync.aligned.m16n8k8.row.col.f32.tf32.tf32.f32 "
        "{%0,%1,%2,%3},{%4,%5,%6,%7},{%8,%9},{%0,%1,%2,%3};"
        : "+f"(d.x), "+f"(d.y), "+f"(d.z), "+f"(d.w)
        : "r"(a0), "r"(a1), "r"(a2), "r"(a3), "r"(b0), "r"(b1));
}
__device__ __forceinline__ void ld2(u32& lo, u32& hi, const u32* p) {
    ull v = *(const ull*)p; lo = (u32)v; hi = (u32)(v >> 32);
}

// ------------------------------ scratch ------------------------------------
__device__ float g_qb[BB*HH*SS_*64];
__device__ float g_kb[BB*HH*SS_*64];
__device__ float g_vb[BB*HH*SS_*64];
__device__ float g_ctx[NTOK*DD];
__device__ float g_t1[NTOK*DD];
__device__ float g_ao[NTOK*DD];
__device__ float g_h[NTOK*DFF];
__device__ float g_t2[NTOK*DD];
__device__ int   g_maskmode;               // 0 = int32 mask, 1 = uint8 mask

__global__ void detect_mask_kernel(const unsigned int* __restrict__ m)
{
    if (threadIdx.x == 0 && blockIdx.x == 0) {
        int mode = 0;
        for (int i = 0; i < 4096; i++) {
            if (m[i] > 1u) { mode = 1; break; }
        }
        g_maskmode = mode;
    }
}

// ------------------------------ tf32 GEMM ----------------------------------
// C[M,N] = A[M,K] @ W[K,N]. CTA tile 128x128, BK=16, 256 thr = 8 warps (4x2),
// warp tile 32x64. Fragments staged in paired layouts for LDS.64.
#define APS 130     // Ap row stride (u32)
#define BPS 10      // Bp row stride (u32)

__device__ __forceinline__ void gemm_tc_body(
    const float* __restrict__ A, const float* __restrict__ W,
    const float* __restrict__ bias, const float* __restrict__ resid,
    float* __restrict__ C, int N, int K, int doRelu, int headStore,
    int rowBase, int colBase, u32* Ap, u32* Bp)
{
    int tid = threadIdx.x;
    int w = tid >> 5, t = tid & 31;
    int wr = w >> 1, wc = w & 1;       // 4 warp-rows x 2 warp-cols
    int tq = t >> 2, tr = t & 3;

    float4 acc[2][8];
#pragma unroll
    for (int f = 0; f < 2; f++)
#pragma unroll
        for (int nf = 0; nf < 8; nf++) acc[f][nf] = make_float4(0.f,0.f,0.f,0.f);

    // staging: A rows (thread -> one row, 8 k's), B (thread -> one n, 8 k's)
    int ar = tid >> 1;
    int akh = (tid & 1) * 8;
    int aslot = 2 * ((ar >> 4) * 8 + (ar & 7)) + ((ar >> 3) & 1);
    const float* Aptr = A + (size_t)(rowBase + ar) * K + akh;
    int bn = tid & 127;
    int bkh = tid >> 7;
    const float* Wptr = W + (size_t)(bkh * 8) * N + colBase + bn;

    for (int k0 = 0; k0 < K; k0 += 16) {
        float4 av0 = *(const float4*)(Aptr + k0);
        float4 av1 = *(const float4*)(Aptr + k0 + 4);
        float bv[8];
#pragma unroll
        for (int i = 0; i < 8; i++) bv[i] = Wptr[(size_t)(k0 + i) * N];
        __syncthreads();
        Ap[(akh + 0) * APS + aslot] = f2tf(av0.x);
        Ap[(akh + 1) * APS + aslot] = f2tf(av0.y);
        Ap[(akh + 2) * APS + aslot] = f2tf(av0.z);
        Ap[(akh + 3) * APS + aslot] = f2tf(av0.w);
        Ap[(akh + 4) * APS + aslot] = f2tf(av1.x);
        Ap[(akh + 5) * APS + aslot] = f2tf(av1.y);
        Ap[(akh + 6) * APS + aslot] = f2tf(av1.z);
        Ap[(akh + 7) * APS + aslot] = f2tf(av1.w);
#pragma unroll
        for (int i = 0; i < 8; i++)
            Bp[(bkh * 128 + bn) * BPS + 2 * (i & 3) + (i >> 2)] = f2tf(bv[i]);
        __syncthreads();
#pragma unroll
        for (int kh = 0; kh < 2; kh++) {
            u32 a0[2], a1[2], a2[2], a3[2];
#pragma unroll
            for (int f = 0; f < 2; f++) {
                int gp = (wr * 2 + f) * 8 + tq;
                ld2(a0[f], a1[f], &Ap[(kh * 8 + tr) * APS + 2 * gp]);
                ld2(a2[f], a3[f], &Ap[(kh * 8 + tr + 4) * APS + 2 * gp]);
            }
#pragma unroll
            for (int nf = 0; nf < 8; nf++) {
                int n = wc * 64 + nf * 8 + tq;
                u32 b0, b1;
                ld2(b0, b1, &Bp[(kh * 128 + n) * BPS + 2 * tr]);
#pragma unroll
                for (int f = 0; f < 2; f++)
                    mma8(acc[f][nf], a0[f], a1[f], a2[f], a3[f], b0, b1);
            }
        }
    }

    // epilogue
#pragma unroll
    for (int f = 0; f < 2; f++) {
        int row = rowBase + wr * 32 + f * 16 + tq;
#pragma unroll
        for (int nf = 0; nf < 8; nf++) {
            int col = colBase + wc * 64 + nf * 8 + tr * 2;
            float b0 = bias[col], b1 = bias[col + 1];
            float c00 = acc[f][nf].x + b0, c01 = acc[f][nf].y + b1;
            float c10 = acc[f][nf].z + b0, c11 = acc[f][nf].w + b1;
            if (resid) {
                float2 r0 = *(const float2*)(resid + (size_t)row * N + col);
                float2 r1 = *(const float2*)(resid + (size_t)(row + 8) * N + col);
                c00 += r0.x; c01 += r0.y; c10 += r1.x; c11 += r1.y;
            }
            if (doRelu) {
                c00 = fmaxf(c00, 0.f); c01 = fmaxf(c01, 0.f);
                c10 = fmaxf(c10, 0.f); c11 = fmaxf(c11, 0.f);
            }
            if (headStore) {
                int h_ = col >> 6, d_ = col & 63;
                int b0_ = row / SS_, s0_ = row % SS_;
                *(float2*)&C[(((size_t)(b0_ * HH + h_)) * SS_ + s0_) * 64 + d_] =
                    make_float2(c00, c01);
                int b1_ = (row + 8) / SS_, s1_ = (row + 8) % SS_;
                *(float2*)&C[(((size_t)(b1_ * HH + h_)) * SS_ + s1_) * 64 + d_] =
                    make_float2(c10, c11);
            } else {
                *(float2*)&C[(size_t)row * N + col] = make_float2(c00, c01);
                *(float2*)&C[(size_t)(row + 8) * N + col] = make_float2(c10, c11);
            }
        }
    }
}

__global__ __launch_bounds__(256, 2) void sgemm_kernel(
    const float* __restrict__ A, const float* __restrict__ W,
    const float* __restrict__ bias, const float* __restrict__ resid,
    float* __restrict__ C, int N, int K, int doRelu, int headStore)
{
    __shared__ u32 Ap[16 * APS];
    __shared__ u32 Bp[256 * BPS];
    gemm_tc_body(A, W, bias, resid, C, N, K, doRelu, headStore,
                 blockIdx.y * 128, blockIdx.x * 128, Ap, Bp);
}

__global__ __launch_bounds__(256, 2) void qkv_kernel(
    const float* __restrict__ A,
    const float* __restrict__ Wq, const float* __restrict__ bq,
    const float* __restrict__ Wk, const float* __restrict__ bk,
    const float* __restrict__ Wv, const float* __restrict__ bv,
    float* __restrict__ q, float* __restrict__ k, float* __restrict__ v)
{
    __shared__ u32 Ap[16 * APS];
    __shared__ u32 Bp[256 * BPS];
    int sel = blockIdx.x >> 2;
    const float* W = (sel == 0) ? Wq : (sel == 1) ? Wk : Wv;
    const float* bias = (sel == 0) ? bq : (sel == 1) ? bk : bv;
    float* C = (sel == 0) ? q : (sel == 1) ? k : v;
    gemm_tc_body(A, W, bias, nullptr, C, DD, DD, 0, 1,
                 blockIdx.y * 128, (blockIdx.x & 3) * 128, Ap, Bp);
}

// ------------------------------ fused attention (tf32 mma) -----------------
// grid (S/16, B*H), 256 thr. 16 query rows, 2048-col score strip in SMEM.
#define SSP 2052
#define KPS 68
#define UNION_FLOATS 10240   // max(Kp 128*68=8704, Vp 16*640=10240, red 8192)
#define ATTN_SMEM_FLOATS (16*SSP + UNION_FLOATS + 16*68 + 16)
#define ATTN_SMEM_BYTES  (ATTN_SMEM_FLOATS * 4)

__global__ __launch_bounds__(256) void attn_kernel(
    const float* __restrict__ q, const float* __restrict__ k,
    const float* __restrict__ v, const void* __restrict__ mask,
    float* __restrict__ attn, float* __restrict__ ctx)
{
    extern __shared__ float smem[];
    float* ss   = smem;                      // 16 x 2052 scores
    float* un   = smem + 16 * SSP;           // union region
    float* qs   = un + UNION_FLOATS;         // 16 x 68 staged q
    float* invs = qs + 16 * 68;              // 16

    u32*  Kp  = (u32*)un;                    // [128][68] tf32 (d-paired)
    u32*  Vp  = (u32*)un;                    // [16][64][10] tf32 (key-paired)
    float* red = un;                         // [8][16][64] partials

    int tid = threadIdx.x;
    int w = tid >> 5, t = tid & 31;
    int tq = t >> 2, tr = t & 3;
    int bh = blockIdx.y, b_ = bh >> 3, h_ = bh & 7;
    int row0 = blockIdx.x * 16;
    int mm = g_maskmode;

    const float* qptr = q + ((size_t)bh * SS_ + row0) * 64;
    const float* kptr = k + (size_t)bh * SS_ * 64;
    const float* vptr = v + (size_t)bh * SS_ * 64;
    const int* mp32 = (const int*)mask + (size_t)b_ * SS_ * SS_;
    const unsigned char* mp8 = (const unsigned char*)mask + (size_t)b_ * SS_ * SS_;

    // stage Q 16x64
    {
        int r = tid >> 4, c = tid & 15;
        ((float4*)(qs + r * 68))[c] = ((const float4*)(qptr + r * 64))[c];
    }
    __syncthreads();

    // Q fragments held in registers for all of phase 1
    u32 qa0[8], qa1[8], qa2[8], qa3[8];
#pragma unroll
    for (int j = 0; j < 8; j++) {
        qa0[j] = f2tf(qs[tq * 68 + j * 8 + tr]);
        qa1[j] = f2tf(qs[(tq + 8) * 68 + j * 8 + tr]);
        qa2[j] = f2tf(qs[tq * 68 + j * 8 + tr + 4]);
        qa3[j] = f2tf(qs[(tq + 8) * 68 + j * 8 + tr + 4]);
    }

    // ---------------- phase 1: scores via mma ----------------
    int skey = tid >> 1;
    int sdh = (tid & 1) * 32;
    for (int ct = 0; ct < 16; ct++) {
        __syncthreads();
        const float* kt = kptr + (size_t)(ct * 128 + skey) * 64 + sdh;
#pragma unroll
        for (int g = 0; g < 4; g++) {
            float4 a = *(const float4*)(kt + g * 8);
            float4 b = *(const float4*)(kt + g * 8 + 4);
            u32* dst = Kp + skey * KPS + sdh + g * 8;
            dst[0] = f2tf(a.x); dst[1] = f2tf(b.x);
            dst[2] = f2tf(a.y); dst[3] = f2tf(b.y);
            dst[4] = f2tf(a.z); dst[5] = f2tf(b.z);
            dst[6] = f2tf(a.w); dst[7] = f2tf(b.w);
        }
        __syncthreads();

        float4 acc0 = make_float4(0.f,0.f,0.f,0.f);
        float4 acc1 = make_float4(0.f,0.f,0.f,0.f);
        int kb0 = w * 16 + tq, kb1 = w * 16 + 8 + tq;
#pragma unroll
        for (int j = 0; j < 8; j++) {
            u32 b0, b1, c0, c1;
            ld2(b0, b1, &Kp[kb0 * KPS + j * 8 + 2 * tr]);
            ld2(c0, c1, &Kp[kb1 * KPS + j * 8 + 2 * tr]);
            mma8(acc0, qa0[j], qa1[j], qa2[j], qa3[j], b0, b1);
            mma8(acc1, qa0[j], qa1[j], qa2[j], qa3[j], c0, c1);
        }
        int r0g = row0 + tq, r1g = row0 + tq + 8;
#pragma unroll
        for (int nf = 0; nf < 2; nf++) {
            float4 a = nf ? acc1 : acc0;
            int c = ct * 128 + w * 16 + nf * 8 + tr * 2;
            int m0a, m0b, m1a, m1b;
            if (mm == 0) {
                int2 u = *(const int2*)(mp32 + (size_t)r0g * SS_ + c);
                int2 v2 = *(const int2*)(mp32 + (size_t)r1g * SS_ + c);
                m0a = u.x; m0b = u.y; m1a = v2.x; m1b = v2.y;
            } else {
                uchar2 u = *(const uchar2*)(mp8 + (size_t)r0g * SS_ + c);
                uchar2 v2 = *(const uchar2*)(mp8 + (size_t)r1g * SS_ + c);
                m0a = u.x; m0b = u.y; m1a = v2.x; m1b = v2.y;
            }
            float2 s0, s1;
            s0.x = m0a ? -1e9f : a.x * 0.125f;
            s0.y = m0b ? -1e9f : a.y * 0.125f;
            s1.x = m1a ? -1e9f : a.z * 0.125f;
            s1.y = m1b ? -1e9f : a.w * 0.125f;
            *(float2*)&ss[tq * SSP + c] = s0;
            *(float2*)&ss[(tq + 8) * SSP + c] = s1;
        }
    }
    __syncthreads();

    // ---------------- phase 2: softmax (fp32, warp owns rows w, w+8) -------
    {
        int wy = w, lx = t;
        float mx0 = -1e30f, mx1 = -1e30f;
#pragma unroll
        for (int ct = 0; ct < 16; ct++) {
            int c0 = ct * 128 + lx * 4;
            float4 x0 = *(float4*)&ss[wy * SSP + c0];
            float4 x1 = *(float4*)&ss[(wy + 8) * SSP + c0];
            mx0 = fmaxf(mx0, fmaxf(fmaxf(x0.x, x0.y), fmaxf(x0.z, x0.w)));
            mx1 = fmaxf(mx1, fmaxf(fmaxf(x1.x, x1.y), fmaxf(x1.z, x1.w)));
        }
#pragma unroll
        for (int o = 16; o; o >>= 1) {
            mx0 = fmaxf(mx0, __shfl_xor_sync(0xffffffffu, mx0, o));
            mx1 = fmaxf(mx1, __shfl_xor_sync(0xffffffffu, mx1, o));
        }
        float sm0 = 0.f, sm1 = 0.f;
#pragma unroll
        for (int ct = 0; ct < 16; ct++) {
            int c0 = ct * 128 + lx * 4;
            float4 x0 = *(float4*)&ss[wy * SSP + c0];
            float4 x1 = *(float4*)&ss[(wy + 8) * SSP + c0];
            x0.x = __expf(x0.x - mx0); x0.y = __expf(x0.y - mx0);
            x0.z = __expf(x0.z - mx0); x0.w = __expf(x0.w - mx0);
            x1.x = __expf(x1.x - mx1); x1.y = __expf(x1.y - mx1);
            x1.z = __expf(x1.z - mx1); x1.w = __expf(x1.w - mx1);
            sm0 += x0.x + x0.y + x0.z + x0.w;
            sm1 += x1.x + x1.y + x1.z + x1.w;
            *(float4*)&ss[wy * SSP + c0] = x0;
            *(float4*)&ss[(wy + 8) * SSP + c0] = x1;
        }
#pragma unroll
        for (int o = 16; o; o >>= 1) {
            sm0 += __shfl_xor_sync(0xffffffffu, sm0, o);
            sm1 += __shfl_xor_sync(0xffffffffu, sm1, o);
        }
        float inv0 = 1.f / sm0, inv1 = 1.f / sm1;
        if (lx == 0) { invs[wy] = inv0; invs[wy + 8] = inv1; }
        if (attn) {
#pragma unroll
            for (int ct = 0; ct < 16; ct++) {
                int c0 = ct * 128 + lx * 4;
                float4 x0 = *(float4*)&ss[wy * SSP + c0];
                float4 x1 = *(float4*)&ss[(wy + 8) * SSP + c0];
                x0.x *= inv0; x0.y *= inv0; x0.z *= inv0; x0.w *= inv0;
                x1.x *= inv1; x1.y *= inv1; x1.z *= inv1; x1.w *= inv1;
                *(float4*)(attn + ((size_t)bh * SS_ + row0 + wy) * SS_ + c0) = x0;
                *(float4*)(attn + ((size_t)bh * SS_ + row0 + wy + 8) * SS_ + c0) = x1;
            }
        }
    }

    // ---------------- phase 3: P @ V via mma ----------------
    float4 pv[8];
#pragma unroll
    for (int nf = 0; nf < 8; nf++) pv[nf] = make_float4(0.f,0.f,0.f,0.f);

    for (int ct = 0; ct < 16; ct++) {
        __syncthreads();
#pragma unroll
        for (int ii = 0; ii < 8; ii++) {
            int lin = tid + ii * 256;
            int key = lin >> 4, d0 = (lin & 15) * 4;
            float4 vv = *(const float4*)(vptr + (size_t)(ct * 128 + key) * 64 + d0);
            int kg = key >> 3, kl = key & 7;
            int slot = 2 * (kl & 3) + (kl >> 2);
            u32* dst = Vp + kg * 640 + d0 * 10 + slot;
            dst[0]  = f2tf(vv.x);
            dst[10] = f2tf(vv.y);
            dst[20] = f2tf(vv.z);
            dst[30] = f2tf(vv.w);
        }
        __syncthreads();
#pragma unroll
        for (int g2 = 0; g2 < 2; g2++) {
            int kg = w * 2 + g2;
            int kc = ct * 128 + kg * 8;
            u32 a0 = f2tf(ss[tq * SSP + kc + tr]);
            u32 a1 = f2tf(ss[(tq + 8) * SSP + kc + tr]);
            u32 a2 = f2tf(ss[tq * SSP + kc + tr + 4]);
            u32 a3 = f2tf(ss[(tq + 8) * SSP + kc + tr + 4]);
#pragma unroll
            for (int nf = 0; nf < 8; nf++) {
                u32 b0, b1;
                ld2(b0, b1, &Vp[kg * 640 + (nf * 8 + tq) * 10 + 2 * tr]);
                mma8(pv[nf], a0, a1, a2, a3, b0, b1);
            }
        }
    }
    __syncthreads();
    // write partials and reduce across warps
#pragma unroll
    for (int nf = 0; nf < 8; nf++) {
        int c = nf * 8 + tr * 2;
        *(float2*)&red[w * 1024 + tq * 64 + c] = make_float2(pv[nf].x, pv[nf].y);
        *(float2*)&red[w * 1024 + (tq + 8) * 64 + c] = make_float2(pv[nf].z, pv[nf].w);
    }
    __syncthreads();
    {
        int i = tid * 4;
        int r = i >> 6;
        float4 s = make_float4(0.f,0.f,0.f,0.f);
#pragma unroll
        for (int ww = 0; ww < 8; ww++) {
            float4 p = *(float4*)&red[ww * 1024 + i];
            s.x += p.x; s.y += p.y; s.z += p.z; s.w += p.w;
        }
        float iv = invs[r];
        s.x *= iv; s.y *= iv; s.z *= iv; s.w *= iv;
        int col = i & 63;
        *(float4*)&ctx[((size_t)(b_ * SS_ + row0 + r)) * DD + h_ * 64 + col] = s;
    }
}

// ------------------------------ layernorm ----------------------------------
__global__ __launch_bounds__(128) void ln_kernel(
    const float* __restrict__ x, const float* __restrict__ gamma,
    const float* __restrict__ beta, float* __restrict__ out)
{
    int row = blockIdx.x;
    int tid = threadIdx.x;
    __shared__ float red[4];
    float4 v = ((const float4*)(x + (size_t)row * DD))[tid];
    float s = v.x + v.y + v.z + v.w;
#pragma unroll
    for (int o = 16; o; o >>= 1) s += __shfl_xor_sync(0xffffffffu, s, o);
    if ((tid & 31) == 0) red[tid >> 5] = s;
    __syncthreads();
    float mu = (red[0] + red[1] + red[2] + red[3]) * (1.f / DD);
    float dx = v.x - mu, dy = v.y - mu, dz = v.z - mu, dw = v.w - mu;
    float s2 = dx * dx + dy * dy + dz * dz + dw * dw;
#pragma unroll
    for (int o = 16; o; o >>= 1) s2 += __shfl_xor_sync(0xffffffffu, s2, o);
    __syncthreads();
    if ((tid & 31) == 0) red[tid >> 5] = s2;
    __syncthreads();
    float var = (red[0] + red[1] + red[2] + red[3]) * (1.f / DD);
    float inv = rsqrtf(var + EPS);
    float4 gg = ((const float4*)gamma)[tid];
    float4 bb = ((const float4*)beta)[tid];
    float4 o;
    o.x = dx * inv * gg.x + bb.x;
    o.y = dy * inv * gg.y + bb.y;
    o.z = dz * inv * gg.z + bb.z;
    o.w = dw * inv * gg.w + bb.w;
    *(float4*)(out + (size_t)row * DD + tid * 4) = o;
}

// ------------------------------ launch -------------------------------------
extern "C" void kernel_launch(void* const* d_in, const int* in_sizes, int n_in,
                              void* d_out, int out_size)
{
    const float* x   = (const float*)d_in[0];
    const void*  mask = d_in[1];
    const float* Wq  = (const float*)d_in[2];
    const float* bq  = (const float*)d_in[3];
    const float* Wk  = (const float*)d_in[4];
    const float* bk  = (const float*)d_in[5];
    const float* Wv  = (const float*)d_in[6];
    const float* bv  = (const float*)d_in[7];
    const float* Wo  = (const float*)d_in[8];
    const float* bo  = (const float*)d_in[9];
    const float* ln1g = (const float*)d_in[10];
    const float* ln1b = (const float*)d_in[11];
    const float* W1  = (const float*)d_in[12];
    const float* b1  = (const float*)d_in[13];
    const float* W2  = (const float*)d_in[14];
    const float* b2  = (const float*)d_in[15];
    const float* ln2g = (const float*)d_in[16];
    const float* ln2b = (const float*)d_in[17];

    float* out = (float*)d_out;
    const long OUT_ELEMS = (long)BB * SS_ * DD;
    const long ATTN_ELEMS = (long)BB * HH * SS_ * SS_;
    float* attn_ptr = ((long)out_size >= OUT_ELEMS + ATTN_ELEMS)
                        ? (out + OUT_ELEMS) : nullptr;

    float *qp, *kp, *vp, *ctxp, *t1p, *aop, *hp, *t2p;
    cudaGetSymbolAddress((void**)&qp, g_qb);
    cudaGetSymbolAddress((void**)&kp, g_kb);
    cudaGetSymbolAddress((void**)&vp, g_vb);
    cudaGetSymbolAddress((void**)&ctxp, g_ctx);
    cudaGetSymbolAddress((void**)&t1p, g_t1);
    cudaGetSymbolAddress((void**)&aop, g_ao);
    cudaGetSymbolAddress((void**)&hp, g_h);
    cudaGetSymbolAddress((void**)&t2p, g_t2);

    cudaFuncSetAttribute(attn_kernel,
                         cudaFuncAttributeMaxDynamicSharedMemorySize,
                         ATTN_SMEM_BYTES);

    dim3 blk(256);
    detect_mask_kernel<<<1, 32>>>((const unsigned int*)mask);
    qkv_kernel<<<dim3(12, 32), blk>>>(x, Wq, bq, Wk, bk, Wv, bv, qp, kp, vp);
    attn_kernel<<<dim3(SS_ / 16, BB * HH), blk, ATTN_SMEM_BYTES>>>(
        qp, kp, vp, mask, attn_ptr, ctxp);
    sgemm_kernel<<<dim3(4, 32), blk>>>(ctxp, Wo, bo, x, t1p, DD, DD, 0, 0);
    ln_kernel<<<NTOK, 128>>>(t1p, ln1g, ln1b, aop);
    sgemm_kernel<<<dim3(16, 32), blk>>>(aop, W1, b1, nullptr, hp, DFF, DD, 1, 0);
    sgemm_kernel<<<dim3(4, 32), blk>>>(hp, W2, b2, aop, t2p, DD, DFF, 0, 0);
    ln_kernel<<<NTOK, 128>>>(t2p, ln2g, ln2b, out);
}

// round 6
// speedup vs baseline: 1.6222x; 1.0117x over previous
#include <cuda_runtime.h>
#include <math.h>

#define BB 2
#define SS_ 2048
#define DD 512
#define HH 8
#define DFF 2048
#define NTOK (BB*SS_)          // 4096
#define EPS 1e-5f

typedef unsigned long long ull;
typedef unsigned int u32;

// ---------------- tf32 mma helpers (sm_80+ mma.sync) -----------------------
__device__ __forceinline__ u32 f2tf(float x) {
    u32 r; asm("cvt.rna.tf32.f32 %0, %1;" : "=r"(r) : "f"(x)); return r;
}
__device__ __forceinline__ void mma8(float4& d, u32 a0, u32 a1, u32 a2, u32 a3,
                                     u32 b0, u32 b1) {
    asm("mma.sync.aligned.m16n8k8.row.col.f32.tf32.tf32.f32 "
        "{%0,%1,%2,%3},{%4,%5,%6,%7},{%8,%9},{%0,%1,%2,%3};"
        : "+f"(d.x), "+f"(d.y), "+f"(d.z), "+f"(d.w)
        : "r"(a0), "r"(a1), "r"(a2), "r"(a3), "r"(b0), "r"(b1));
}
__device__ __forceinline__ void ld2(u32& lo, u32& hi, const u32* p) {
    ull v = *(const ull*)p; lo = (u32)v; hi = (u32)(v >> 32);
}

// ------------------------------ scratch ------------------------------------
__device__ float g_qb[BB*HH*SS_*64];
__device__ float g_kb[BB*HH*SS_*64];
__device__ float g_vb[BB*HH*SS_*64];
__device__ float g_ctx[NTOK*DD];
__device__ float g_t1[NTOK*DD];
__device__ float g_ao[NTOK*DD];
__device__ float g_h[NTOK*DFF];
__device__ float g_t2[NTOK*DD];
__device__ int   g_maskmode;               // 0 = int32 mask, 1 = uint8 mask

__global__ void detect_mask_kernel(const unsigned int* __restrict__ m)
{
    if (threadIdx.x == 0 && blockIdx.x == 0) {
        int mode = 0;
        for (int i = 0; i < 4096; i++) {
            if (m[i] > 1u) { mode = 1; break; }
        }
        g_maskmode = mode;
    }
}

// ------------------------------ tf32 GEMM (double-buffered) ----------------
// C[M,N] = A[M,K] @ W[K,N]. CTA tile 128x128, BK=16, 256 thr = 8 warps (4x2),
// warp tile 32x64. Register prefetch of next k-chunk overlaps LDG with mma.
#define APS 130     // Ap row stride (u32)
#define BPS 10      // Bp row stride (u32)

__device__ __forceinline__ void gemm_tc_body(
    const float* __restrict__ A, const float* __restrict__ W,
    const float* __restrict__ bias, const float* __restrict__ resid,
    float* __restrict__ C, int N, int K, int doRelu, int headStore,
    int rowBase, int colBase, u32* Ap, u32* Bp)
{
    int tid = threadIdx.x;
    int w = tid >> 5, t = tid & 31;
    int wr = w >> 1, wc = w & 1;       // 4 warp-rows x 2 warp-cols
    int tq = t >> 2, tr = t & 3;

    float4 acc[2][8];
#pragma unroll
    for (int f = 0; f < 2; f++)
#pragma unroll
        for (int nf = 0; nf < 8; nf++) acc[f][nf] = make_float4(0.f,0.f,0.f,0.f);

    int ar = tid >> 1;
    int akh = (tid & 1) * 8;
    int aslot = 2 * ((ar >> 4) * 8 + (ar & 7)) + ((ar >> 3) & 1);
    const float* Aptr = A + (size_t)(rowBase + ar) * K + akh;
    int bn = tid & 127;
    int bkh = tid >> 7;
    const float* Wptr = W + (size_t)(bkh * 8) * N + colBase + bn;

    // prefetch first chunk
    float4 av0 = *(const float4*)(Aptr);
    float4 av1 = *(const float4*)(Aptr + 4);
    float bv[8];
#pragma unroll
    for (int i = 0; i < 8; i++) bv[i] = Wptr[(size_t)i * N];

    for (int k0 = 0; k0 < K; k0 += 16) {
        __syncthreads();
        Ap[(akh + 0) * APS + aslot] = f2tf(av0.x);
        Ap[(akh + 1) * APS + aslot] = f2tf(av0.y);
        Ap[(akh + 2) * APS + aslot] = f2tf(av0.z);
        Ap[(akh + 3) * APS + aslot] = f2tf(av0.w);
        Ap[(akh + 4) * APS + aslot] = f2tf(av1.x);
        Ap[(akh + 5) * APS + aslot] = f2tf(av1.y);
        Ap[(akh + 6) * APS + aslot] = f2tf(av1.z);
        Ap[(akh + 7) * APS + aslot] = f2tf(av1.w);
#pragma unroll
        for (int i = 0; i < 8; i++)
            Bp[(bkh * 128 + bn) * BPS + 2 * (i & 3) + (i >> 2)] = f2tf(bv[i]);
        __syncthreads();

        // issue next-chunk LDGs NOW; latency overlaps the mma section below.
        // Branchless: last iteration re-loads the same chunk (L1 hit, unused).
        int kn = (k0 + 16 < K) ? (k0 + 16) : k0;
        av0 = *(const float4*)(Aptr + kn);
        av1 = *(const float4*)(Aptr + kn + 4);
#pragma unroll
        for (int i = 0; i < 8; i++) bv[i] = Wptr[(size_t)(kn + i) * N];

#pragma unroll
        for (int kh = 0; kh < 2; kh++) {
            u32 a0[2], a1[2], a2[2], a3[2];
#pragma unroll
            for (int f = 0; f < 2; f++) {
                int gp = (wr * 2 + f) * 8 + tq;
                ld2(a0[f], a1[f], &Ap[(kh * 8 + tr) * APS + 2 * gp]);
                ld2(a2[f], a3[f], &Ap[(kh * 8 + tr + 4) * APS + 2 * gp]);
            }
#pragma unroll
            for (int nf = 0; nf < 8; nf++) {
                int n = wc * 64 + nf * 8 + tq;
                u32 b0, b1;
                ld2(b0, b1, &Bp[(kh * 128 + n) * BPS + 2 * tr]);
#pragma unroll
                for (int f = 0; f < 2; f++)
                    mma8(acc[f][nf], a0[f], a1[f], a2[f], a3[f], b0, b1);
            }
        }
    }

    // epilogue
#pragma unroll
    for (int f = 0; f < 2; f++) {
        int row = rowBase + wr * 32 + f * 16 + tq;
#pragma unroll
        for (int nf = 0; nf < 8; nf++) {
            int col = colBase + wc * 64 + nf * 8 + tr * 2;
            float b0 = bias[col], b1 = bias[col + 1];
            float c00 = acc[f][nf].x + b0, c01 = acc[f][nf].y + b1;
            float c10 = acc[f][nf].z + b0, c11 = acc[f][nf].w + b1;
            if (resid) {
                float2 r0 = *(const float2*)(resid + (size_t)row * N + col);
                float2 r1 = *(const float2*)(resid + (size_t)(row + 8) * N + col);
                c00 += r0.x; c01 += r0.y; c10 += r1.x; c11 += r1.y;
            }
            if (doRelu) {
                c00 = fmaxf(c00, 0.f); c01 = fmaxf(c01, 0.f);
                c10 = fmaxf(c10, 0.f); c11 = fmaxf(c11, 0.f);
            }
            if (headStore) {
                int h_ = col >> 6, d_ = col & 63;
                int b0_ = row / SS_, s0_ = row % SS_;
                *(float2*)&C[(((size_t)(b0_ * HH + h_)) * SS_ + s0_) * 64 + d_] =
                    make_float2(c00, c01);
                int b1_ = (row + 8) / SS_, s1_ = (row + 8) % SS_;
                *(float2*)&C[(((size_t)(b1_ * HH + h_)) * SS_ + s1_) * 64 + d_] =
                    make_float2(c10, c11);
            } else {
                *(float2*)&C[(size_t)row * N + col] = make_float2(c00, c01);
                *(float2*)&C[(size_t)(row + 8) * N + col] = make_float2(c10, c11);
            }
        }
    }
}

__global__ __launch_bounds__(256, 2) void sgemm_kernel(
    const float* __restrict__ A, const float* __restrict__ W,
    const float* __restrict__ bias, const float* __restrict__ resid,
    float* __restrict__ C, int N, int K, int doRelu, int headStore)
{
    __shared__ u32 Ap[16 * APS];
    __shared__ u32 Bp[256 * BPS];
    gemm_tc_body(A, W, bias, resid, C, N, K, doRelu, headStore,
                 blockIdx.y * 128, blockIdx.x * 128, Ap, Bp);
}

__global__ __launch_bounds__(256, 2) void qkv_kernel(
    const float* __restrict__ A,
    const float* __restrict__ Wq, const float* __restrict__ bq,
    const float* __restrict__ Wk, const float* __restrict__ bk,
    const float* __restrict__ Wv, const float* __restrict__ bv,
    float* __restrict__ q, float* __restrict__ k, float* __restrict__ v)
{
    __shared__ u32 Ap[16 * APS];
    __shared__ u32 Bp[256 * BPS];
    int sel = blockIdx.x >> 2;
    const float* W = (sel == 0) ? Wq : (sel == 1) ? Wk : Wv;
    const float* bias = (sel == 0) ? bq : (sel == 1) ? bk : bv;
    float* C = (sel == 0) ? q : (sel == 1) ? k : v;
    gemm_tc_body(A, W, bias, nullptr, C, DD, DD, 0, 1,
                 blockIdx.y * 128, (blockIdx.x & 3) * 128, Ap, Bp);
}

// ------------------------------ fused attention (tf32 mma, prefetched) -----
// grid (S/16, B*H), 256 thr. 16 query rows, 2048-col score strip in SMEM.
#define SSP 2052
#define KPS 68
#define UNION_FLOATS 10240   // max(Kp 128*68=8704, Vp 16*640=10240, red 8192)
#define ATTN_SMEM_FLOATS (16*SSP + UNION_FLOATS + 16*68 + 16)
#define ATTN_SMEM_BYTES  (ATTN_SMEM_FLOATS * 4)

__global__ __launch_bounds__(256) void attn_kernel(
    const float* __restrict__ q, const float* __restrict__ k,
    const float* __restrict__ v, const void* __restrict__ mask,
    float* __restrict__ attn, float* __restrict__ ctx)
{
    extern __shared__ float smem[];
    float* ss   = smem;                      // 16 x 2052 scores
    float* un   = smem + 16 * SSP;           // union region
    float* qs   = un + UNION_FLOATS;         // 16 x 68 staged q
    float* invs = qs + 16 * 68;              // 16

    u32*  Kp  = (u32*)un;                    // [128][68] tf32 (d-paired)
    u32*  Vp  = (u32*)un;                    // [16][64][10] tf32 (key-paired)
    float* red = un;                         // [8][16][64] partials

    int tid = threadIdx.x;
    int w = tid >> 5, t = tid & 31;
    int tq = t >> 2, tr = t & 3;
    int bh = blockIdx.y, b_ = bh >> 3, h_ = bh & 7;
    int row0 = blockIdx.x * 16;
    int mm = g_maskmode;

    const float* qptr = q + ((size_t)bh * SS_ + row0) * 64;
    const float* kptr = k + (size_t)bh * SS_ * 64;
    const float* vptr = v + (size_t)bh * SS_ * 64;
    const int* mp32 = (const int*)mask + (size_t)b_ * SS_ * SS_;
    const unsigned char* mp8 = (const unsigned char*)mask + (size_t)b_ * SS_ * SS_;

    // stage Q 16x64
    {
        int r = tid >> 4, c = tid & 15;
        ((float4*)(qs + r * 68))[c] = ((const float4*)(qptr + r * 64))[c];
    }
    __syncthreads();

    // Q fragments held in registers for all of phase 1
    u32 qa0[8], qa1[8], qa2[8], qa3[8];
#pragma unroll
    for (int j = 0; j < 8; j++) {
        qa0[j] = f2tf(qs[tq * 68 + j * 8 + tr]);
        qa1[j] = f2tf(qs[(tq + 8) * 68 + j * 8 + tr]);
        qa2[j] = f2tf(qs[tq * 68 + j * 8 + tr + 4]);
        qa3[j] = f2tf(qs[(tq + 8) * 68 + j * 8 + tr + 4]);
    }

    // ---------------- phase 1: scores via mma (K tiles prefetched) ---------
    int skey = tid >> 1;
    int sdh = (tid & 1) * 32;
    float4 kbuf[8];
    {
        const float* kt = kptr + (size_t)skey * 64 + sdh;
#pragma unroll
        for (int g = 0; g < 4; g++) {
            kbuf[2*g]   = *(const float4*)(kt + g * 8);
            kbuf[2*g+1] = *(const float4*)(kt + g * 8 + 4);
        }
    }
    for (int ct = 0; ct < 16; ct++) {
        __syncthreads();
#pragma unroll
        for (int g = 0; g < 4; g++) {
            float4 a = kbuf[2*g], b = kbuf[2*g+1];
            u32* dst = Kp + skey * KPS + sdh + g * 8;
            dst[0] = f2tf(a.x); dst[1] = f2tf(b.x);
            dst[2] = f2tf(a.y); dst[3] = f2tf(b.y);
            dst[4] = f2tf(a.z); dst[5] = f2tf(b.z);
            dst[6] = f2tf(a.w); dst[7] = f2tf(b.w);
        }
        __syncthreads();

        // prefetch next K tile (branchless; last iter re-loads current)
        {
            int ctn = (ct < 15) ? (ct + 1) : ct;
            const float* kt = kptr + (size_t)(ctn * 128 + skey) * 64 + sdh;
#pragma unroll
            for (int g = 0; g < 4; g++) {
                kbuf[2*g]   = *(const float4*)(kt + g * 8);
                kbuf[2*g+1] = *(const float4*)(kt + g * 8 + 4);
            }
        }

        float4 acc0 = make_float4(0.f,0.f,0.f,0.f);
        float4 acc1 = make_float4(0.f,0.f,0.f,0.f);
        int kb0 = w * 16 + tq, kb1 = w * 16 + 8 + tq;
#pragma unroll
        for (int j = 0; j < 8; j++) {
            u32 b0, b1, c0, c1;
            ld2(b0, b1, &Kp[kb0 * KPS + j * 8 + 2 * tr]);
            ld2(c0, c1, &Kp[kb1 * KPS + j * 8 + 2 * tr]);
            mma8(acc0, qa0[j], qa1[j], qa2[j], qa3[j], b0, b1);
            mma8(acc1, qa0[j], qa1[j], qa2[j], qa3[j], c0, c1);
        }
        int r0g = row0 + tq, r1g = row0 + tq + 8;
#pragma unroll
        for (int nf = 0; nf < 2; nf++) {
            float4 a = nf ? acc1 : acc0;
            int c = ct * 128 + w * 16 + nf * 8 + tr * 2;
            int m0a, m0b, m1a, m1b;
            if (mm == 0) {
                int2 u = *(const int2*)(mp32 + (size_t)r0g * SS_ + c);
                int2 v2 = *(const int2*)(mp32 + (size_t)r1g * SS_ + c);
                m0a = u.x; m0b = u.y; m1a = v2.x; m1b = v2.y;
            } else {
                uchar2 u = *(const uchar2*)(mp8 + (size_t)r0g * SS_ + c);
                uchar2 v2 = *(const uchar2*)(mp8 + (size_t)r1g * SS_ + c);
                m0a = u.x; m0b = u.y; m1a = v2.x; m1b = v2.y;
            }
            float2 s0, s1;
            s0.x = m0a ? -1e9f : a.x * 0.125f;
            s0.y = m0b ? -1e9f : a.y * 0.125f;
            s1.x = m1a ? -1e9f : a.z * 0.125f;
            s1.y = m1b ? -1e9f : a.w * 0.125f;
            *(float2*)&ss[tq * SSP + c] = s0;
            *(float2*)&ss[(tq + 8) * SSP + c] = s1;
        }
    }
    __syncthreads();

    // ---------------- phase 2: softmax (fp32, warp owns rows w, w+8) -------
    {
        int wy = w, lx = t;
        float mx0 = -1e30f, mx1 = -1e30f;
#pragma unroll
        for (int ct = 0; ct < 16; ct++) {
            int c0 = ct * 128 + lx * 4;
            float4 x0 = *(float4*)&ss[wy * SSP + c0];
            float4 x1 = *(float4*)&ss[(wy + 8) * SSP + c0];
            mx0 = fmaxf(mx0, fmaxf(fmaxf(x0.x, x0.y), fmaxf(x0.z, x0.w)));
            mx1 = fmaxf(mx1, fmaxf(fmaxf(x1.x, x1.y), fmaxf(x1.z, x1.w)));
        }
#pragma unroll
        for (int o = 16; o; o >>= 1) {
            mx0 = fmaxf(mx0, __shfl_xor_sync(0xffffffffu, mx0, o));
            mx1 = fmaxf(mx1, __shfl_xor_sync(0xffffffffu, mx1, o));
        }
        float sm0 = 0.f, sm1 = 0.f;
#pragma unroll
        for (int ct = 0; ct < 16; ct++) {
            int c0 = ct * 128 + lx * 4;
            float4 x0 = *(float4*)&ss[wy * SSP + c0];
            float4 x1 = *(float4*)&ss[(wy + 8) * SSP + c0];
            x0.x = __expf(x0.x - mx0); x0.y = __expf(x0.y - mx0);
            x0.z = __expf(x0.z - mx0); x0.w = __expf(x0.w - mx0);
            x1.x = __expf(x1.x - mx1); x1.y = __expf(x1.y - mx1);
            x1.z = __expf(x1.z - mx1); x1.w = __expf(x1.w - mx1);
            sm0 += x0.x + x0.y + x0.z + x0.w;
            sm1 += x1.x + x1.y + x1.z + x1.w;
            *(float4*)&ss[wy * SSP + c0] = x0;
            *(float4*)&ss[(wy + 8) * SSP + c0] = x1;
        }
#pragma unroll
        for (int o = 16; o; o >>= 1) {
            sm0 += __shfl_xor_sync(0xffffffffu, sm0, o);
            sm1 += __shfl_xor_sync(0xffffffffu, sm1, o);
        }
        float inv0 = 1.f / sm0, inv1 = 1.f / sm1;
        if (lx == 0) { invs[wy] = inv0; invs[wy + 8] = inv1; }
        if (attn) {
#pragma unroll
            for (int ct = 0; ct < 16; ct++) {
                int c0 = ct * 128 + lx * 4;
                float4 x0 = *(float4*)&ss[wy * SSP + c0];
                float4 x1 = *(float4*)&ss[(wy + 8) * SSP + c0];
                x0.x *= inv0; x0.y *= inv0; x0.z *= inv0; x0.w *= inv0;
                x1.x *= inv1; x1.y *= inv1; x1.z *= inv1; x1.w *= inv1;
                *(float4*)(attn + ((size_t)bh * SS_ + row0 + wy) * SS_ + c0) = x0;
                *(float4*)(attn + ((size_t)bh * SS_ + row0 + wy + 8) * SS_ + c0) = x1;
            }
        }
    }

    // ---------------- phase 3: P @ V via mma (V tiles prefetched) ----------
    float4 pv[8];
#pragma unroll
    for (int nf = 0; nf < 8; nf++) pv[nf] = make_float4(0.f,0.f,0.f,0.f);

    float4 vbuf[8];
#pragma unroll
    for (int ii = 0; ii < 8; ii++) {
        int lin = tid + ii * 256;
        int key = lin >> 4, d0 = (lin & 15) * 4;
        vbuf[ii] = *(const float4*)(vptr + (size_t)key * 64 + d0);
    }
    for (int ct = 0; ct < 16; ct++) {
        __syncthreads();
#pragma unroll
        for (int ii = 0; ii < 8; ii++) {
            int lin = tid + ii * 256;
            int key = lin >> 4, d0 = (lin & 15) * 4;
            float4 vv = vbuf[ii];
            int kg = key >> 3, kl = key & 7;
            int slot = 2 * (kl & 3) + (kl >> 2);
            u32* dst = Vp + kg * 640 + d0 * 10 + slot;
            dst[0]  = f2tf(vv.x);
            dst[10] = f2tf(vv.y);
            dst[20] = f2tf(vv.z);
            dst[30] = f2tf(vv.w);
        }
        __syncthreads();

        // prefetch next V tile
        {
            int ctn = (ct < 15) ? (ct + 1) : ct;
#pragma unroll
            for (int ii = 0; ii < 8; ii++) {
                int lin = tid + ii * 256;
                int key = lin >> 4, d0 = (lin & 15) * 4;
                vbuf[ii] = *(const float4*)(vptr + (size_t)(ctn * 128 + key) * 64 + d0);
            }
        }

#pragma unroll
        for (int g2 = 0; g2 < 2; g2++) {
            int kg = w * 2 + g2;
            int kc = ct * 128 + kg * 8;
            u32 a0 = f2tf(ss[tq * SSP + kc + tr]);
            u32 a1 = f2tf(ss[(tq + 8) * SSP + kc + tr]);
            u32 a2 = f2tf(ss[tq * SSP + kc + tr + 4]);
            u32 a3 = f2tf(ss[(tq + 8) * SSP + kc + tr + 4]);
#pragma unroll
            for (int nf = 0; nf < 8; nf++) {
                u32 b0, b1;
                ld2(b0, b1, &Vp[kg * 640 + (nf * 8 + tq) * 10 + 2 * tr]);
                mma8(pv[nf], a0, a1, a2, a3, b0, b1);
            }
        }
    }
    __syncthreads();
    // write partials and reduce across warps
#pragma unroll
    for (int nf = 0; nf < 8; nf++) {
        int c = nf * 8 + tr * 2;
        *(float2*)&red[w * 1024 + tq * 64 + c] = make_float2(pv[nf].x, pv[nf].y);
        *(float2*)&red[w * 1024 + (tq + 8) * 64 + c] = make_float2(pv[nf].z, pv[nf].w);
    }
    __syncthreads();
    {
        int i = tid * 4;
        int r = i >> 6;
        float4 s = make_float4(0.f,0.f,0.f,0.f);
#pragma unroll
        for (int ww = 0; ww < 8; ww++) {
            float4 p = *(float4*)&red[ww * 1024 + i];
            s.x += p.x; s.y += p.y; s.z += p.z; s.w += p.w;
        }
        float iv = invs[r];
        s.x *= iv; s.y *= iv; s.z *= iv; s.w *= iv;
        int col = i & 63;
        *(float4*)&ctx[((size_t)(b_ * SS_ + row0 + r)) * DD + h_ * 64 + col] = s;
    }
}

// ------------------------------ layernorm ----------------------------------
__global__ __launch_bounds__(128) void ln_kernel(
    const float* __restrict__ x, const float* __restrict__ gamma,
    const float* __restrict__ beta, float* __restrict__ out)
{
    int row = blockIdx.x;
    int tid = threadIdx.x;
    __shared__ float red[4];
    float4 v = ((const float4*)(x + (size_t)row * DD))[tid];
    float s = v.x + v.y + v.z + v.w;
#pragma unroll
    for (int o = 16; o; o >>= 1) s += __shfl_xor_sync(0xffffffffu, s, o);
    if ((tid & 31) == 0) red[tid >> 5] = s;
    __syncthreads();
    float mu = (red[0] + red[1] + red[2] + red[3]) * (1.f / DD);
    float dx = v.x - mu, dy = v.y - mu, dz = v.z - mu, dw = v.w - mu;
    float s2 = dx * dx + dy * dy + dz * dz + dw * dw;
#pragma unroll
    for (int o = 16; o; o >>= 1) s2 += __shfl_xor_sync(0xffffffffu, s2, o);
    __syncthreads();
    if ((tid & 31) == 0) red[tid >> 5] = s2;
    __syncthreads();
    float var = (red[0] + red[1] + red[2] + red[3]) * (1.f / DD);
    float inv = rsqrtf(var + EPS);
    float4 gg = ((const float4*)gamma)[tid];
    float4 bb = ((const float4*)beta)[tid];
    float4 o;
    o.x = dx * inv * gg.x + bb.x;
    o.y = dy * inv * gg.y + bb.y;
    o.z = dz * inv * gg.z + bb.z;
    o.w = dw * inv * gg.w + bb.w;
    *(float4*)(out + (size_t)row * DD + tid * 4) = o;
}

// ------------------------------ launch -------------------------------------
extern "C" void kernel_launch(void* const* d_in, const int* in_sizes, int n_in,
                              void* d_out, int out_size)
{
    const float* x   = (const float*)d_in[0];
    const void*  mask = d_in[1];
    const float* Wq  = (const float*)d_in[2];
    const float* bq  = (const float*)d_in[3];
    const float* Wk  = (const float*)d_in[4];
    const float* bk  = (const float*)d_in[5];
    const float* Wv  = (const float*)d_in[6];
    const float* bv  = (const float*)d_in[7];
    const float* Wo  = (const float*)d_in[8];
    const float* bo  = (const float*)d_in[9];
    const float* ln1g = (const float*)d_in[10];
    const float* ln1b = (const float*)d_in[11];
    const float* W1  = (const float*)d_in[12];
    const float* b1  = (const float*)d_in[13];
    const float* W2  = (const float*)d_in[14];
    const float* b2  = (const float*)d_in[15];
    const float* ln2g = (const float*)d_in[16];
    const float* ln2b = (const float*)d_in[17];

    float* out = (float*)d_out;
    const long OUT_ELEMS = (long)BB * SS_ * DD;
    const long ATTN_ELEMS = (long)BB * HH * SS_ * SS_;
    float* attn_ptr = ((long)out_size >= OUT_ELEMS + ATTN_ELEMS)
                        ? (out + OUT_ELEMS) : nullptr;

    float *qp, *kp, *vp, *ctxp, *t1p, *aop, *hp, *t2p;
    cudaGetSymbolAddress((void**)&qp, g_qb);
    cudaGetSymbolAddress((void**)&kp, g_kb);
    cudaGetSymbolAddress((void**)&vp, g_vb);
    cudaGetSymbolAddress((void**)&ctxp, g_ctx);
    cudaGetSymbolAddress((void**)&t1p, g_t1);
    cudaGetSymbolAddress((void**)&aop, g_ao);
    cudaGetSymbolAddress((void**)&hp, g_h);
    cudaGetSymbolAddress((void**)&t2p, g_t2);

    cudaFuncSetAttribute(attn_kernel,
                         cudaFuncAttributeMaxDynamicSharedMemorySize,
                         ATTN_SMEM_BYTES);

    dim3 blk(256);
    detect_mask_kernel<<<1, 32>>>((const unsigned int*)mask);
    qkv_kernel<<<dim3(12, 32), blk>>>(x, Wq, bq, Wk, bk, Wv, bv, qp, kp, vp);
    attn_kernel<<<dim3(SS_ / 16, BB * HH), blk, ATTN_SMEM_BYTES>>>(
        qp, kp, vp, mask, attn_ptr, ctxp);
    sgemm_kernel<<<dim3(4, 32), blk>>>(ctxp, Wo, bo, x, t1p, DD, DD, 0, 0);
    ln_kernel<<<NTOK, 128>>>(t1p, ln1g, ln1b, aop);
    sgemm_kernel<<<dim3(16, 32), blk>>>(aop, W1, b1, nullptr, hp, DFF, DD, 1, 0);
    sgemm_kernel<<<dim3(4, 32), blk>>>(hp, W2, b2, aop, t2p, DD, DFF, 0, 0);
    ln_kernel<<<NTOK, 128>>>(t2p, ln2g, ln2b, out);
}

// round 7
// speedup vs baseline: 2.0700x; 1.2761x over previous
#include <cuda_runtime.h>
#include <math.h>

#define BB 2
#define SS_ 2048
#define DD 512
#define HH 8
#define DFF 2048
#define NTOK (BB*SS_)          // 4096
#define EPS 1e-5f

typedef unsigned long long ull;
typedef unsigned int u32;

// tf32 mma: HW reads high 19 bits; pass raw fp32 bits (CUTLASS-style).
__device__ __forceinline__ u32 fu(float x) { return __float_as_uint(x); }
__device__ __forceinline__ void mma8(float4& d, u32 a0, u32 a1, u32 a2, u32 a3,
                                     u32 b0, u32 b1) {
    asm("mma.sync.aligned.m16n8k8.row.col.f32.tf32.tf32.f32 "
        "{%0,%1,%2,%3},{%4,%5,%6,%7},{%8,%9},{%0,%1,%2,%3};"
        : "+f"(d.x), "+f"(d.y), "+f"(d.z), "+f"(d.w)
        : "r"(a0), "r"(a1), "r"(a2), "r"(a3), "r"(b0), "r"(b1));
}
__device__ __forceinline__ void ld2(u32& lo, u32& hi, const u32* p) {
    ull v = *(const ull*)p; lo = (u32)v; hi = (u32)(v >> 32);
}

// ------------------------------ scratch ------------------------------------
__device__ float g_qb[BB*HH*SS_*64];
__device__ float g_kb[BB*HH*SS_*64];
__device__ float g_vb[BB*HH*SS_*64];
__device__ float g_ctx[NTOK*DD];
__device__ float g_t1[NTOK*DD];
__device__ float g_ao[NTOK*DD];
__device__ float g_h[NTOK*DFF];
__device__ float g_t2[NTOK*DD];
__device__ int   g_maskmode;               // 0 = int32 mask, 1 = uint8 mask

__global__ void detect_mask_kernel(const unsigned int* __restrict__ m)
{
    if (threadIdx.x == 0 && blockIdx.x == 0) {
        int mode = 0;
        for (int i = 0; i < 4096; i++) {
            if (m[i] > 1u) { mode = 1; break; }
        }
        g_maskmode = mode;
    }
}

// ------------------------------ tf32 GEMM (2-stage smem pipeline) ----------
// C[M,N] = A[M,K] @ W[K,N]. CTA 128x128, BK=16, 8 warps (4x2), warp 32x64.
#define APS 130     // Ap row stride (u32)
#define BPS 10      // Bp row stride (u32)
#define ABUF (16*APS)
#define BBUF (256*BPS)

__device__ __forceinline__ void gemm_tc_body(
    const float* __restrict__ A, const float* __restrict__ W,
    const float* __restrict__ bias, const float* __restrict__ resid,
    float* __restrict__ C, int N, int K, int doRelu, int headStore,
    int rowBase, int colBase, u32* Ap, u32* Bp)
{
    int tid = threadIdx.x;
    int w = tid >> 5, t = tid & 31;
    int wr = w >> 1, wc = w & 1;
    int tq = t >> 2, tr = t & 3;

    float4 acc[2][8];
#pragma unroll
    for (int f = 0; f < 2; f++)
#pragma unroll
        for (int nf = 0; nf < 8; nf++) acc[f][nf] = make_float4(0.f,0.f,0.f,0.f);

    int ar = tid >> 1;
    int akh = (tid & 1) * 8;
    int aslot = 2 * ((ar >> 4) * 8 + (ar & 7)) + ((ar >> 3) & 1);
    const float* Aptr = A + (size_t)(rowBase + ar) * K + akh;
    int bn = tid & 127;
    int bkh = tid >> 7;
    const float* Wptr = W + (size_t)(bkh * 8) * N + colBase + bn;

    // prefetch chunk 0
    float4 av0 = *(const float4*)(Aptr);
    float4 av1 = *(const float4*)(Aptr + 4);
    float bv[8];
#pragma unroll
    for (int i = 0; i < 8; i++) bv[i] = Wptr[(size_t)i * N];

    int buf = 0;
    for (int k0 = 0; k0 < K; k0 += 16) {
        u32* Ab = Ap + buf * ABUF;
        u32* Bb = Bp + buf * BBUF;
        Ab[(akh + 0) * APS + aslot] = fu(av0.x);
        Ab[(akh + 1) * APS + aslot] = fu(av0.y);
        Ab[(akh + 2) * APS + aslot] = fu(av0.z);
        Ab[(akh + 3) * APS + aslot] = fu(av0.w);
        Ab[(akh + 4) * APS + aslot] = fu(av1.x);
        Ab[(akh + 5) * APS + aslot] = fu(av1.y);
        Ab[(akh + 6) * APS + aslot] = fu(av1.z);
        Ab[(akh + 7) * APS + aslot] = fu(av1.w);
#pragma unroll
        for (int i = 0; i < 8; i++)
            Bb[(bkh * 128 + bn) * BPS + 2 * (i & 3) + (i >> 2)] = fu(bv[i]);
        __syncthreads();

        // prefetch next chunk (branchless; last iter re-loads current)
        int kn = (k0 + 16 < K) ? (k0 + 16) : k0;
        av0 = *(const float4*)(Aptr + kn);
        av1 = *(const float4*)(Aptr + kn + 4);
#pragma unroll
        for (int i = 0; i < 8; i++) bv[i] = Wptr[(size_t)(kn + i) * N];

#pragma unroll
        for (int kh = 0; kh < 2; kh++) {
            u32 a0[2], a1[2], a2[2], a3[2];
#pragma unroll
            for (int f = 0; f < 2; f++) {
                int gp = (wr * 2 + f) * 8 + tq;
                ld2(a0[f], a1[f], &Ab[(kh * 8 + tr) * APS + 2 * gp]);
                ld2(a2[f], a3[f], &Ab[(kh * 8 + tr + 4) * APS + 2 * gp]);
            }
#pragma unroll
            for (int nf = 0; nf < 8; nf++) {
                int n = wc * 64 + nf * 8 + tq;
                u32 b0, b1;
                ld2(b0, b1, &Bb[(kh * 128 + n) * BPS + 2 * tr]);
#pragma unroll
                for (int f = 0; f < 2; f++)
                    mma8(acc[f][nf], a0[f], a1[f], a2[f], a3[f], b0, b1);
            }
        }
        buf ^= 1;
    }

#pragma unroll
    for (int f = 0; f < 2; f++) {
        int row = rowBase + wr * 32 + f * 16 + tq;
#pragma unroll
        for (int nf = 0; nf < 8; nf++) {
            int col = colBase + wc * 64 + nf * 8 + tr * 2;
            float b0 = bias[col], b1 = bias[col + 1];
            float c00 = acc[f][nf].x + b0, c01 = acc[f][nf].y + b1;
            float c10 = acc[f][nf].z + b0, c11 = acc[f][nf].w + b1;
            if (resid) {
                float2 r0 = *(const float2*)(resid + (size_t)row * N + col);
                float2 r1 = *(const float2*)(resid + (size_t)(row + 8) * N + col);
                c00 += r0.x; c01 += r0.y; c10 += r1.x; c11 += r1.y;
            }
            if (doRelu) {
                c00 = fmaxf(c00, 0.f); c01 = fmaxf(c01, 0.f);
                c10 = fmaxf(c10, 0.f); c11 = fmaxf(c11, 0.f);
            }
            if (headStore) {
                int h_ = col >> 6, d_ = col & 63;
                int b0_ = row / SS_, s0_ = row % SS_;
                *(float2*)&C[(((size_t)(b0_ * HH + h_)) * SS_ + s0_) * 64 + d_] =
                    make_float2(c00, c01);
                int b1_ = (row + 8) / SS_, s1_ = (row + 8) % SS_;
                *(float2*)&C[(((size_t)(b1_ * HH + h_)) * SS_ + s1_) * 64 + d_] =
                    make_float2(c10, c11);
            } else {
                *(float2*)&C[(size_t)row * N + col] = make_float2(c00, c01);
                *(float2*)&C[(size_t)(row + 8) * N + col] = make_float2(c10, c11);
            }
        }
    }
}

__global__ __launch_bounds__(256, 2) void sgemm_kernel(
    const float* __restrict__ A, const float* __restrict__ W,
    const float* __restrict__ bias, const float* __restrict__ resid,
    float* __restrict__ C, int N, int K, int doRelu, int headStore)
{
    __shared__ u32 Ap[2 * ABUF];
    __shared__ u32 Bp[2 * BBUF];
    gemm_tc_body(A, W, bias, resid, C, N, K, doRelu, headStore,
                 blockIdx.y * 128, blockIdx.x * 128, Ap, Bp);
}

__global__ __launch_bounds__(256, 2) void qkv_kernel(
    const float* __restrict__ A,
    const float* __restrict__ Wq, const float* __restrict__ bq,
    const float* __restrict__ Wk, const float* __restrict__ bk,
    const float* __restrict__ Wv, const float* __restrict__ bv,
    float* __restrict__ q, float* __restrict__ k, float* __restrict__ v)
{
    __shared__ u32 Ap[2 * ABUF];
    __shared__ u32 Bp[2 * BBUF];
    int sel = blockIdx.x >> 2;
    const float* W = (sel == 0) ? Wq : (sel == 1) ? Wk : Wv;
    const float* bias = (sel == 0) ? bq : (sel == 1) ? bk : bv;
    float* C = (sel == 0) ? q : (sel == 1) ? k : v;
    gemm_tc_body(A, W, bias, nullptr, C, DD, DD, 0, 1,
                 blockIdx.y * 128, (blockIdx.x & 3) * 128, Ap, Bp);
}

// ------------------------------ fused attention (direct-LDG fragments) -----
// grid (S/16, B*H), 256 thr = 8 warps. 16 query rows; 2048-col strip in smem.
// Phase 1: warps split keys; B-fragments of K loaded straight from gmem.
// Phase 3: warps split dims (w*8..w*8+7); V fragments straight from gmem;
//          no cross-warp reduction needed.
#define SSP 2052
#define ATTN_SMEM_FLOATS (16*SSP + 16*68 + 16)
#define ATTN_SMEM_BYTES  (ATTN_SMEM_FLOATS * 4)

__global__ __launch_bounds__(256) void attn_kernel(
    const float* __restrict__ q, const float* __restrict__ k,
    const float* __restrict__ v, const void* __restrict__ mask,
    float* __restrict__ attn, float* __restrict__ ctx)
{
    extern __shared__ float smem[];
    float* ss   = smem;                      // 16 x 2052 scores
    float* qs   = smem + 16 * SSP;           // 16 x 68 staged q
    float* invs = qs + 16 * 68;              // 16

    int tid = threadIdx.x;
    int w = tid >> 5, t = tid & 31;
    int tq = t >> 2, tr = t & 3;
    int bh = blockIdx.y, b_ = bh >> 3, h_ = bh & 7;
    int row0 = blockIdx.x * 16;
    int mm = g_maskmode;

    const float* qptr = q + ((size_t)bh * SS_ + row0) * 64;
    const float* kptr = k + (size_t)bh * SS_ * 64;
    const float* vptr = v + (size_t)bh * SS_ * 64;
    const int* mp32 = (const int*)mask + (size_t)b_ * SS_ * SS_;
    const unsigned char* mp8 = (const unsigned char*)mask + (size_t)b_ * SS_ * SS_;

    // stage Q 16x64
    {
        int r = tid >> 4, c = tid & 15;
        ((float4*)(qs + r * 68))[c] = ((const float4*)(qptr + r * 64))[c];
    }
    __syncthreads();

    // Q fragments in registers (raw fp32 bits)
    u32 qa0[8], qa1[8], qa2[8], qa3[8];
#pragma unroll
    for (int j = 0; j < 8; j++) {
        qa0[j] = fu(qs[tq * 68 + j * 8 + tr]);
        qa1[j] = fu(qs[(tq + 8) * 68 + j * 8 + tr]);
        qa2[j] = fu(qs[tq * 68 + j * 8 + tr + 4]);
        qa3[j] = fu(qs[(tq + 8) * 68 + j * 8 + tr + 4]);
    }

    // ---------------- phase 1: scores, K fragments direct from gmem --------
    for (int nb = 0; nb < 16; nb++) {
        int key0 = nb * 128 + w * 16 + tq;       // group 0 key for this lane
        const float* kb0 = kptr + (size_t)key0 * 64 + tr;
        const float* kb1 = kb0 + 8 * 64;         // group 1 (+8 keys)
        float4 acc0 = make_float4(0.f,0.f,0.f,0.f);
        float4 acc1 = make_float4(0.f,0.f,0.f,0.f);
#pragma unroll
        for (int j = 0; j < 8; j++) {
            u32 b0 = fu(kb0[j * 8]);
            u32 b1 = fu(kb0[j * 8 + 4]);
            u32 c0 = fu(kb1[j * 8]);
            u32 c1 = fu(kb1[j * 8 + 4]);
            mma8(acc0, qa0[j], qa1[j], qa2[j], qa3[j], b0, b1);
            mma8(acc1, qa0[j], qa1[j], qa2[j], qa3[j], c0, c1);
        }
        int r0g = row0 + tq, r1g = row0 + tq + 8;
#pragma unroll
        for (int nf = 0; nf < 2; nf++) {
            float4 a = nf ? acc1 : acc0;
            int c = nb * 128 + w * 16 + nf * 8 + tr * 2;
            int m0a, m0b, m1a, m1b;
            if (mm == 0) {
                int2 u = *(const int2*)(mp32 + (size_t)r0g * SS_ + c);
                int2 v2 = *(const int2*)(mp32 + (size_t)r1g * SS_ + c);
                m0a = u.x; m0b = u.y; m1a = v2.x; m1b = v2.y;
            } else {
                uchar2 u = *(const uchar2*)(mp8 + (size_t)r0g * SS_ + c);
                uchar2 v2 = *(const uchar2*)(mp8 + (size_t)r1g * SS_ + c);
                m0a = u.x; m0b = u.y; m1a = v2.x; m1b = v2.y;
            }
            float2 s0, s1;
            s0.x = m0a ? -1e9f : a.x * 0.125f;
            s0.y = m0b ? -1e9f : a.y * 0.125f;
            s1.x = m1a ? -1e9f : a.z * 0.125f;
            s1.y = m1b ? -1e9f : a.w * 0.125f;
            *(float2*)&ss[tq * SSP + c] = s0;
            *(float2*)&ss[(tq + 8) * SSP + c] = s1;
        }
    }
    __syncthreads();

    // ---------------- phase 2: softmax (warp owns rows w, w+8) -------------
    {
        int wy = w, lx = t;
        float mx0 = -1e30f, mx1 = -1e30f;
#pragma unroll
        for (int ct = 0; ct < 16; ct++) {
            int c0 = ct * 128 + lx * 4;
            float4 x0 = *(float4*)&ss[wy * SSP + c0];
            float4 x1 = *(float4*)&ss[(wy + 8) * SSP + c0];
            mx0 = fmaxf(mx0, fmaxf(fmaxf(x0.x, x0.y), fmaxf(x0.z, x0.w)));
            mx1 = fmaxf(mx1, fmaxf(fmaxf(x1.x, x1.y), fmaxf(x1.z, x1.w)));
        }
#pragma unroll
        for (int o = 16; o; o >>= 1) {
            mx0 = fmaxf(mx0, __shfl_xor_sync(0xffffffffu, mx0, o));
            mx1 = fmaxf(mx1, __shfl_xor_sync(0xffffffffu, mx1, o));
        }
        float sm0 = 0.f, sm1 = 0.f;
#pragma unroll
        for (int ct = 0; ct < 16; ct++) {
            int c0 = ct * 128 + lx * 4;
            float4 x0 = *(float4*)&ss[wy * SSP + c0];
            float4 x1 = *(float4*)&ss[(wy + 8) * SSP + c0];
            x0.x = __expf(x0.x - mx0); x0.y = __expf(x0.y - mx0);
            x0.z = __expf(x0.z - mx0); x0.w = __expf(x0.w - mx0);
            x1.x = __expf(x1.x - mx1); x1.y = __expf(x1.y - mx1);
            x1.z = __expf(x1.z - mx1); x1.w = __expf(x1.w - mx1);
            sm0 += x0.x + x0.y + x0.z + x0.w;
            sm1 += x1.x + x1.y + x1.z + x1.w;
            *(float4*)&ss[wy * SSP + c0] = x0;   // keep e (unnormalized)
            *(float4*)&ss[(wy + 8) * SSP + c0] = x1;
        }
#pragma unroll
        for (int o = 16; o; o >>= 1) {
            sm0 += __shfl_xor_sync(0xffffffffu, sm0, o);
            sm1 += __shfl_xor_sync(0xffffffffu, sm1, o);
        }
        float inv0 = 1.f / sm0, inv1 = 1.f / sm1;
        if (lx == 0) { invs[wy] = inv0; invs[wy + 8] = inv1; }
        if (attn) {
#pragma unroll
            for (int ct = 0; ct < 16; ct++) {
                int c0 = ct * 128 + lx * 4;
                float4 x0 = *(float4*)&ss[wy * SSP + c0];
                float4 x1 = *(float4*)&ss[(wy + 8) * SSP + c0];
                x0.x *= inv0; x0.y *= inv0; x0.z *= inv0; x0.w *= inv0;
                x1.x *= inv1; x1.y *= inv1; x1.z *= inv1; x1.w *= inv1;
                *(float4*)(attn + ((size_t)bh * SS_ + row0 + wy) * SS_ + c0) = x0;
                *(float4*)(attn + ((size_t)bh * SS_ + row0 + wy + 8) * SS_ + c0) = x1;
            }
        }
    }
    __syncthreads();

    // ---------------- phase 3: P @ V, warps split dims; V direct from gmem -
    {
        int d0 = w * 8;                          // this warp's 8 output dims
        float4 acc = make_float4(0.f,0.f,0.f,0.f);
        const float* vb = vptr + d0 + tq;        // lane's dim column
#pragma unroll 8
        for (int kc = 0; kc < 2048; kc += 8) {
            u32 a0 = fu(ss[tq * SSP + kc + tr]);
            u32 a1 = fu(ss[(tq + 8) * SSP + kc + tr]);
            u32 a2 = fu(ss[tq * SSP + kc + tr + 4]);
            u32 a3 = fu(ss[(tq + 8) * SSP + kc + tr + 4]);
            u32 b0 = fu(vb[(size_t)(kc + tr) * 64]);
            u32 b1 = fu(vb[(size_t)(kc + tr + 4) * 64]);
            mma8(acc, a0, a1, a2, a3, b0, b1);
        }
        float i0 = invs[tq], i1 = invs[tq + 8];
        int col = h_ * 64 + d0 + tr * 2;
        *(float2*)&ctx[((size_t)(b_ * SS_ + row0 + tq)) * DD + col] =
            make_float2(acc.x * i0, acc.y * i0);
        *(float2*)&ctx[((size_t)(b_ * SS_ + row0 + tq + 8)) * DD + col] =
            make_float2(acc.z * i1, acc.w * i1);
    }
}

// ------------------------------ layernorm ----------------------------------
__global__ __launch_bounds__(128) void ln_kernel(
    const float* __restrict__ x, const float* __restrict__ gamma,
    const float* __restrict__ beta, float* __restrict__ out)
{
    int row = blockIdx.x;
    int tid = threadIdx.x;
    __shared__ float red[4];
    float4 v = ((const float4*)(x + (size_t)row * DD))[tid];
    float s = v.x + v.y + v.z + v.w;
#pragma unroll
    for (int o = 16; o; o >>= 1) s += __shfl_xor_sync(0xffffffffu, s, o);
    if ((tid & 31) == 0) red[tid >> 5] = s;
    __syncthreads();
    float mu = (red[0] + red[1] + red[2] + red[3]) * (1.f / DD);
    float dx = v.x - mu, dy = v.y - mu, dz = v.z - mu, dw = v.w - mu;
    float s2 = dx * dx + dy * dy + dz * dz + dw * dw;
#pragma unroll
    for (int o = 16; o; o >>= 1) s2 += __shfl_xor_sync(0xffffffffu, s2, o);
    __syncthreads();
    if ((tid & 31) == 0) red[tid >> 5] = s2;
    __syncthreads();
    float var = (red[0] + red[1] + red[2] + red[3]) * (1.f / DD);
    float inv = rsqrtf(var + EPS);
    float4 gg = ((const float4*)gamma)[tid];
    float4 bb = ((const float4*)beta)[tid];
    float4 o;
    o.x = dx * inv * gg.x + bb.x;
    o.y = dy * inv * gg.y + bb.y;
    o.z = dz * inv * gg.z + bb.z;
    o.w = dw * inv * gg.w + bb.w;
    *(float4*)(out + (size_t)row * DD + tid * 4) = o;
}

// ------------------------------ launch -------------------------------------
extern "C" void kernel_launch(void* const* d_in, const int* in_sizes, int n_in,
                              void* d_out, int out_size)
{
    const float* x   = (const float*)d_in[0];
    const void*  mask = d_in[1];
    const float* Wq  = (const float*)d_in[2];
    const float* bq  = (const float*)d_in[3];
    const float* Wk  = (const float*)d_in[4];
    const float* bk  = (const float*)d_in[5];
    const float* Wv  = (const float*)d_in[6];
    const float* bv  = (const float*)d_in[7];
    const float* Wo  = (const float*)d_in[8];
    const float* bo  = (const float*)d_in[9];
    const float* ln1g = (const float*)d_in[10];
    const float* ln1b = (const float*)d_in[11];
    const float* W1  = (const float*)d_in[12];
    const float* b1  = (const float*)d_in[13];
    const float* W2  = (const float*)d_in[14];
    const float* b2  = (const float*)d_in[15];
    const float* ln2g = (const float*)d_in[16];
    const float* ln2b = (const float*)d_in[17];

    float* out = (float*)d_out;
    const long OUT_ELEMS = (long)BB * SS_ * DD;
    const long ATTN_ELEMS = (long)BB * HH * SS_ * SS_;
    float* attn_ptr = ((long)out_size >= OUT_ELEMS + ATTN_ELEMS)
                        ? (out + OUT_ELEMS) : nullptr;

    float *qp, *kp, *vp, *ctxp, *t1p, *aop, *hp, *t2p;
    cudaGetSymbolAddress((void**)&qp, g_qb);
    cudaGetSymbolAddress((void**)&kp, g_kb);
    cudaGetSymbolAddress((void**)&vp, g_vb);
    cudaGetSymbolAddress((void**)&ctxp, g_ctx);
    cudaGetSymbolAddress((void**)&t1p, g_t1);
    cudaGetSymbolAddress((void**)&aop, g_ao);
    cudaGetSymbolAddress((void**)&hp, g_h);
    cudaGetSymbolAddress((void**)&t2p, g_t2);

    cudaFuncSetAttribute(attn_kernel,
                         cudaFuncAttributeMaxDynamicSharedMemorySize,
                         ATTN_SMEM_BYTES);

    dim3 blk(256);
    detect_mask_kernel<<<1, 32>>>((const unsigned int*)mask);
    qkv_kernel<<<dim3(12, 32), blk>>>(x, Wq, bq, Wk, bk, Wv, bv, qp, kp, vp);
    attn_kernel<<<dim3(SS_ / 16, BB * HH), blk, ATTN_SMEM_BYTES>>>(
        qp, kp, vp, mask, attn_ptr, ctxp);
    sgemm_kernel<<<dim3(4, 32), blk>>>(ctxp, Wo, bo, x, t1p, DD, DD, 0, 0);
    ln_kernel<<<NTOK, 128>>>(t1p, ln1g, ln1b, aop);
    sgemm_kernel<<<dim3(16, 32), blk>>>(aop, W1, b1, nullptr, hp, DFF, DD, 1, 0);
    sgemm_kernel<<<dim3(4, 32), blk>>>(hp, W2, b2, aop, t2p, DD, DFF, 0, 0);
    ln_kernel<<<NTOK, 128>>>(t2p, ln2g, ln2b, out);
}

// round 8
// speedup vs baseline: 2.1433x; 1.0354x over previous
#include <cuda_runtime.h>
#include <math.h>

#define BB 2
#define SS_ 2048
#define DD 512
#define HH 8
#define DFF 2048
#define NTOK (BB*SS_)          // 4096
#define EPS 1e-5f

typedef unsigned long long ull;
typedef unsigned int u32;

// tf32 mma: HW reads high 19 bits; pass raw fp32 bits (CUTLASS-style).
__device__ __forceinline__ u32 fu(float x) { return __float_as_uint(x); }
__device__ __forceinline__ void mma8(float4& d, u32 a0, u32 a1, u32 a2, u32 a3,
                                     u32 b0, u32 b1) {
    asm("mma.sync.aligned.m16n8k8.row.col.f32.tf32.tf32.f32 "
        "{%0,%1,%2,%3},{%4,%5,%6,%7},{%8,%9},{%0,%1,%2,%3};"
        : "+f"(d.x), "+f"(d.y), "+f"(d.z), "+f"(d.w)
        : "r"(a0), "r"(a1), "r"(a2), "r"(a3), "r"(b0), "r"(b1));
}
__device__ __forceinline__ void ld2(u32& lo, u32& hi, const u32* p) {
    ull v = *(const ull*)p; lo = (u32)v; hi = (u32)(v >> 32);
}

// ------------------------------ scratch ------------------------------------
__device__ float g_qb[BB*HH*SS_*64];
__device__ float g_kb[BB*HH*SS_*64];
__device__ float g_vb[BB*HH*SS_*64];
__device__ float g_ctx[NTOK*DD];
__device__ float g_t1[NTOK*DD];
__device__ float g_ao[NTOK*DD];
__device__ float g_h[NTOK*DFF];
__device__ float g_t2[NTOK*DD];
__device__ int   g_maskmode;               // 0 = int32 mask, 1 = uint8 mask

__global__ void detect_mask_kernel(const unsigned int* __restrict__ m)
{
    if (threadIdx.x == 0 && blockIdx.x == 0) {
        int mode = 0;
        for (int i = 0; i < 4096; i++) {
            if (m[i] > 1u) { mode = 1; break; }
        }
        g_maskmode = mode;
    }
}

// ------------------------------ tf32 GEMM (2-stage smem pipeline) ----------
#define APS 130     // Ap row stride (u32)
#define BPS 10      // Bp row stride (u32)
#define ABUF (16*APS)
#define BBUF (256*BPS)

__device__ __forceinline__ void gemm_tc_body(
    const float* __restrict__ A, const float* __restrict__ W,
    const float* __restrict__ bias, const float* __restrict__ resid,
    float* __restrict__ C, int N, int K, int doRelu, int headStore,
    int rowBase, int colBase, u32* Ap, u32* Bp)
{
    int tid = threadIdx.x;
    int w = tid >> 5, t = tid & 31;
    int wr = w >> 1, wc = w & 1;
    int tq = t >> 2, tr = t & 3;

    float4 acc[2][8];
#pragma unroll
    for (int f = 0; f < 2; f++)
#pragma unroll
        for (int nf = 0; nf < 8; nf++) acc[f][nf] = make_float4(0.f,0.f,0.f,0.f);

    int ar = tid >> 1;
    int akh = (tid & 1) * 8;
    int aslot = 2 * ((ar >> 4) * 8 + (ar & 7)) + ((ar >> 3) & 1);
    const float* Aptr = A + (size_t)(rowBase + ar) * K + akh;
    int bn = tid & 127;
    int bkh = tid >> 7;
    const float* Wptr = W + (size_t)(bkh * 8) * N + colBase + bn;

    float4 av0 = *(const float4*)(Aptr);
    float4 av1 = *(const float4*)(Aptr + 4);
    float bv[8];
#pragma unroll
    for (int i = 0; i < 8; i++) bv[i] = Wptr[(size_t)i * N];

    int buf = 0;
    for (int k0 = 0; k0 < K; k0 += 16) {
        u32* Ab = Ap + buf * ABUF;
        u32* Bb = Bp + buf * BBUF;
        Ab[(akh + 0) * APS + aslot] = fu(av0.x);
        Ab[(akh + 1) * APS + aslot] = fu(av0.y);
        Ab[(akh + 2) * APS + aslot] = fu(av0.z);
        Ab[(akh + 3) * APS + aslot] = fu(av0.w);
        Ab[(akh + 4) * APS + aslot] = fu(av1.x);
        Ab[(akh + 5) * APS + aslot] = fu(av1.y);
        Ab[(akh + 6) * APS + aslot] = fu(av1.z);
        Ab[(akh + 7) * APS + aslot] = fu(av1.w);
#pragma unroll
        for (int i = 0; i < 8; i++)
            Bb[(bkh * 128 + bn) * BPS + 2 * (i & 3) + (i >> 2)] = fu(bv[i]);
        __syncthreads();

        int kn = (k0 + 16 < K) ? (k0 + 16) : k0;
        av0 = *(const float4*)(Aptr + kn);
        av1 = *(const float4*)(Aptr + kn + 4);
#pragma unroll
        for (int i = 0; i < 8; i++) bv[i] = Wptr[(size_t)(kn + i) * N];

#pragma unroll
        for (int kh = 0; kh < 2; kh++) {
            u32 a0[2], a1[2], a2[2], a3[2];
#pragma unroll
            for (int f = 0; f < 2; f++) {
                int gp = (wr * 2 + f) * 8 + tq;
                ld2(a0[f], a1[f], &Ab[(kh * 8 + tr) * APS + 2 * gp]);
                ld2(a2[f], a3[f], &Ab[(kh * 8 + tr + 4) * APS + 2 * gp]);
            }
#pragma unroll
            for (int nf = 0; nf < 8; nf++) {
                int n = wc * 64 + nf * 8 + tq;
                u32 b0, b1;
                ld2(b0, b1, &Bb[(kh * 128 + n) * BPS + 2 * tr]);
#pragma unroll
                for (int f = 0; f < 2; f++)
                    mma8(acc[f][nf], a0[f], a1[f], a2[f], a3[f], b0, b1);
            }
        }
        buf ^= 1;
    }

#pragma unroll
    for (int f = 0; f < 2; f++) {
        int row = rowBase + wr * 32 + f * 16 + tq;
#pragma unroll
        for (int nf = 0; nf < 8; nf++) {
            int col = colBase + wc * 64 + nf * 8 + tr * 2;
            float b0 = bias[col], b1 = bias[col + 1];
            float c00 = acc[f][nf].x + b0, c01 = acc[f][nf].y + b1;
            float c10 = acc[f][nf].z + b0, c11 = acc[f][nf].w + b1;
            if (resid) {
                float2 r0 = *(const float2*)(resid + (size_t)row * N + col);
                float2 r1 = *(const float2*)(resid + (size_t)(row + 8) * N + col);
                c00 += r0.x; c01 += r0.y; c10 += r1.x; c11 += r1.y;
            }
            if (doRelu) {
                c00 = fmaxf(c00, 0.f); c01 = fmaxf(c01, 0.f);
                c10 = fmaxf(c10, 0.f); c11 = fmaxf(c11, 0.f);
            }
            if (headStore) {
                int h_ = col >> 6, d_ = col & 63;
                int b0_ = row / SS_, s0_ = row % SS_;
                *(float2*)&C[(((size_t)(b0_ * HH + h_)) * SS_ + s0_) * 64 + d_] =
                    make_float2(c00, c01);
                int b1_ = (row + 8) / SS_, s1_ = (row + 8) % SS_;
                *(float2*)&C[(((size_t)(b1_ * HH + h_)) * SS_ + s1_) * 64 + d_] =
                    make_float2(c10, c11);
            } else {
                *(float2*)&C[(size_t)row * N + col] = make_float2(c00, c01);
                *(float2*)&C[(size_t)(row + 8) * N + col] = make_float2(c10, c11);
            }
        }
    }
}

__global__ __launch_bounds__(256, 2) void sgemm_kernel(
    const float* __restrict__ A, const float* __restrict__ W,
    const float* __restrict__ bias, const float* __restrict__ resid,
    float* __restrict__ C, int N, int K, int doRelu, int headStore)
{
    __shared__ u32 Ap[2 * ABUF];
    __shared__ u32 Bp[2 * BBUF];
    gemm_tc_body(A, W, bias, resid, C, N, K, doRelu, headStore,
                 blockIdx.y * 128, blockIdx.x * 128, Ap, Bp);
}

__global__ __launch_bounds__(256, 2) void qkv_kernel(
    const float* __restrict__ A,
    const float* __restrict__ Wq, const float* __restrict__ bq,
    const float* __restrict__ Wk, const float* __restrict__ bk,
    const float* __restrict__ Wv, const float* __restrict__ bv,
    float* __restrict__ q, float* __restrict__ k, float* __restrict__ v)
{
    __shared__ u32 Ap[2 * ABUF];
    __shared__ u32 Bp[2 * BBUF];
    int sel = blockIdx.x >> 2;
    const float* W = (sel == 0) ? Wq : (sel == 1) ? Wk : Wv;
    const float* bias = (sel == 0) ? bq : (sel == 1) ? bk : bv;
    float* C = (sel == 0) ? q : (sel == 1) ? k : v;
    gemm_tc_body(A, W, bias, nullptr, C, DD, DD, 0, 1,
                 blockIdx.y * 128, (blockIdx.x & 3) * 128, Ap, Bp);
}

// ------------------------------ fused attention ----------------------------
// grid (S/16, B*H), 256 thr = 8 warps. Direct-LDG fragments; widened chains:
// phase 1 does 2 key-blocks per iteration (4 accs), phase 3 splits keys in
// two independent halves (2 accs).
#define SSP 2052
#define ATTN_SMEM_FLOATS (16*SSP + 16*68 + 16)
#define ATTN_SMEM_BYTES  (ATTN_SMEM_FLOATS * 4)

__global__ __launch_bounds__(256) void attn_kernel(
    const float* __restrict__ q, const float* __restrict__ k,
    const float* __restrict__ v, const void* __restrict__ mask,
    float* __restrict__ attn, float* __restrict__ ctx)
{
    extern __shared__ float smem[];
    float* ss   = smem;                      // 16 x 2052 scores
    float* qs   = smem + 16 * SSP;           // 16 x 68 staged q
    float* invs = qs + 16 * 68;              // 16

    int tid = threadIdx.x;
    int w = tid >> 5, t = tid & 31;
    int tq = t >> 2, tr = t & 3;
    int bh = blockIdx.y, b_ = bh >> 3, h_ = bh & 7;
    int row0 = blockIdx.x * 16;
    int mm = g_maskmode;

    const float* qptr = q + ((size_t)bh * SS_ + row0) * 64;
    const float* kptr = k + (size_t)bh * SS_ * 64;
    const float* vptr = v + (size_t)bh * SS_ * 64;
    const int* mp32 = (const int*)mask + (size_t)b_ * SS_ * SS_;
    const unsigned char* mp8 = (const unsigned char*)mask + (size_t)b_ * SS_ * SS_;

    // stage Q 16x64
    {
        int r = tid >> 4, c = tid & 15;
        ((float4*)(qs + r * 68))[c] = ((const float4*)(qptr + r * 64))[c];
    }
    __syncthreads();

    // Q fragments in registers (raw fp32 bits)
    u32 qa0[8], qa1[8], qa2[8], qa3[8];
#pragma unroll
    for (int j = 0; j < 8; j++) {
        qa0[j] = fu(qs[tq * 68 + j * 8 + tr]);
        qa1[j] = fu(qs[(tq + 8) * 68 + j * 8 + tr]);
        qa2[j] = fu(qs[tq * 68 + j * 8 + tr + 4]);
        qa3[j] = fu(qs[(tq + 8) * 68 + j * 8 + tr + 4]);
    }

    // ---------------- phase 1: scores; 2 key-blocks per iteration ----------
    int r0g = row0 + tq, r1g = row0 + tq + 8;
    for (int nb = 0; nb < 16; nb += 2) {
        int key0 = nb * 128 + w * 16 + tq;
        const float* p0 = kptr + (size_t)key0 * 64 + tr;   // nb,   group 0
        const float* p1 = p0 + 8 * 64;                     // nb,   group 1
        const float* p2 = p0 + 128 * 64;                   // nb+1, group 0
        const float* p3 = p0 + 136 * 64;                   // nb+1, group 1
        float4 A0 = make_float4(0.f,0.f,0.f,0.f), A1 = A0, B0 = A0, B1 = A0;
#pragma unroll
        for (int j = 0; j < 8; j++) {
            u32 b0 = fu(p0[j * 8]),  b1 = fu(p0[j * 8 + 4]);
            u32 c0 = fu(p1[j * 8]),  c1 = fu(p1[j * 8 + 4]);
            u32 d0 = fu(p2[j * 8]),  d1 = fu(p2[j * 8 + 4]);
            u32 e0 = fu(p3[j * 8]),  e1 = fu(p3[j * 8 + 4]);
            mma8(A0, qa0[j], qa1[j], qa2[j], qa3[j], b0, b1);
            mma8(A1, qa0[j], qa1[j], qa2[j], qa3[j], c0, c1);
            mma8(B0, qa0[j], qa1[j], qa2[j], qa3[j], d0, d1);
            mma8(B1, qa0[j], qa1[j], qa2[j], qa3[j], e0, e1);
        }
#pragma unroll
        for (int s = 0; s < 4; s++) {
            float4 a = (s == 0) ? A0 : (s == 1) ? A1 : (s == 2) ? B0 : B1;
            int c = (nb + (s >> 1)) * 128 + w * 16 + (s & 1) * 8 + tr * 2;
            int m0a, m0b, m1a, m1b;
            if (mm == 0) {
                int2 u = *(const int2*)(mp32 + (size_t)r0g * SS_ + c);
                int2 v2 = *(const int2*)(mp32 + (size_t)r1g * SS_ + c);
                m0a = u.x; m0b = u.y; m1a = v2.x; m1b = v2.y;
            } else {
                uchar2 u = *(const uchar2*)(mp8 + (size_t)r0g * SS_ + c);
                uchar2 v2 = *(const uchar2*)(mp8 + (size_t)r1g * SS_ + c);
                m0a = u.x; m0b = u.y; m1a = v2.x; m1b = v2.y;
            }
            float2 s0, s1;
            s0.x = m0a ? -1e9f : a.x * 0.125f;
            s0.y = m0b ? -1e9f : a.y * 0.125f;
            s1.x = m1a ? -1e9f : a.z * 0.125f;
            s1.y = m1b ? -1e9f : a.w * 0.125f;
            *(float2*)&ss[tq * SSP + c] = s0;
            *(float2*)&ss[(tq + 8) * SSP + c] = s1;
        }
    }
    __syncthreads();

    // ---------------- phase 2: softmax (warp owns rows w, w+8) -------------
    {
        int wy = w, lx = t;
        float mx0 = -1e30f, mx1 = -1e30f;
#pragma unroll
        for (int ct = 0; ct < 16; ct++) {
            int c0 = ct * 128 + lx * 4;
            float4 x0 = *(float4*)&ss[wy * SSP + c0];
            float4 x1 = *(float4*)&ss[(wy + 8) * SSP + c0];
            mx0 = fmaxf(mx0, fmaxf(fmaxf(x0.x, x0.y), fmaxf(x0.z, x0.w)));
            mx1 = fmaxf(mx1, fmaxf(fmaxf(x1.x, x1.y), fmaxf(x1.z, x1.w)));
        }
#pragma unroll
        for (int o = 16; o; o >>= 1) {
            mx0 = fmaxf(mx0, __shfl_xor_sync(0xffffffffu, mx0, o));
            mx1 = fmaxf(mx1, __shfl_xor_sync(0xffffffffu, mx1, o));
        }
        float sm0 = 0.f, sm1 = 0.f;
#pragma unroll
        for (int ct = 0; ct < 16; ct++) {
            int c0 = ct * 128 + lx * 4;
            float4 x0 = *(float4*)&ss[wy * SSP + c0];
            float4 x1 = *(float4*)&ss[(wy + 8) * SSP + c0];
            x0.x = __expf(x0.x - mx0); x0.y = __expf(x0.y - mx0);
            x0.z = __expf(x0.z - mx0); x0.w = __expf(x0.w - mx0);
            x1.x = __expf(x1.x - mx1); x1.y = __expf(x1.y - mx1);
            x1.z = __expf(x1.z - mx1); x1.w = __expf(x1.w - mx1);
            sm0 += x0.x + x0.y + x0.z + x0.w;
            sm1 += x1.x + x1.y + x1.z + x1.w;
            *(float4*)&ss[wy * SSP + c0] = x0;   // keep e (unnormalized)
            *(float4*)&ss[(wy + 8) * SSP + c0] = x1;
        }
#pragma unroll
        for (int o = 16; o; o >>= 1) {
            sm0 += __shfl_xor_sync(0xffffffffu, sm0, o);
            sm1 += __shfl_xor_sync(0xffffffffu, sm1, o);
        }
        float inv0 = 1.f / sm0, inv1 = 1.f / sm1;
        if (lx == 0) { invs[wy] = inv0; invs[wy + 8] = inv1; }
        if (attn) {
#pragma unroll
            for (int ct = 0; ct < 16; ct++) {
                int c0 = ct * 128 + lx * 4;
                float4 x0 = *(float4*)&ss[wy * SSP + c0];
                float4 x1 = *(float4*)&ss[(wy + 8) * SSP + c0];
                x0.x *= inv0; x0.y *= inv0; x0.z *= inv0; x0.w *= inv0;
                x1.x *= inv1; x1.y *= inv1; x1.z *= inv1; x1.w *= inv1;
                *(float4*)(attn + ((size_t)bh * SS_ + row0 + wy) * SS_ + c0) = x0;
                *(float4*)(attn + ((size_t)bh * SS_ + row0 + wy + 8) * SS_ + c0) = x1;
            }
        }
    }
    __syncthreads();

    // ---------------- phase 3: P @ V; two independent key-half chains ------
    {
        int d0 = w * 8;
        float4 aA = make_float4(0.f,0.f,0.f,0.f);
        float4 aB = make_float4(0.f,0.f,0.f,0.f);
        const float* vA = vptr + d0 + tq;                       // keys 0..1023
        const float* vB = vptr + (size_t)1024 * 64 + d0 + tq;   // keys 1024..2047
#pragma unroll 8
        for (int kc = 0; kc < 1024; kc += 8) {
            u32 a0 = fu(ss[tq * SSP + kc + tr]);
            u32 a1 = fu(ss[(tq + 8) * SSP + kc + tr]);
            u32 a2 = fu(ss[tq * SSP + kc + tr + 4]);
            u32 a3 = fu(ss[(tq + 8) * SSP + kc + tr + 4]);
            u32 b0 = fu(vA[(size_t)(kc + tr) * 64]);
            u32 b1 = fu(vA[(size_t)(kc + tr + 4) * 64]);
            mma8(aA, a0, a1, a2, a3, b0, b1);
            int k2 = kc + 1024;
            u32 c0 = fu(ss[tq * SSP + k2 + tr]);
            u32 c1 = fu(ss[(tq + 8) * SSP + k2 + tr]);
            u32 c2 = fu(ss[tq * SSP + k2 + tr + 4]);
            u32 c3 = fu(ss[(tq + 8) * SSP + k2 + tr + 4]);
            u32 e0 = fu(vB[(size_t)(kc + tr) * 64]);
            u32 e1 = fu(vB[(size_t)(kc + tr + 4) * 64]);
            mma8(aB, c0, c1, c2, c3, e0, e1);
        }
        float4 acc = make_float4(aA.x + aB.x, aA.y + aB.y,
                                 aA.z + aB.z, aA.w + aB.w);
        float i0 = invs[tq], i1 = invs[tq + 8];
        int col = h_ * 64 + d0 + tr * 2;
        *(float2*)&ctx[((size_t)(b_ * SS_ + row0 + tq)) * DD + col] =
            make_float2(acc.x * i0, acc.y * i0);
        *(float2*)&ctx[((size_t)(b_ * SS_ + row0 + tq + 8)) * DD + col] =
            make_float2(acc.z * i1, acc.w * i1);
    }
}

// ------------------------------ layernorm ----------------------------------
__global__ __launch_bounds__(128) void ln_kernel(
    const float* __restrict__ x, const float* __restrict__ gamma,
    const float* __restrict__ beta, float* __restrict__ out)
{
    int row = blockIdx.x;
    int tid = threadIdx.x;
    __shared__ float red[4];
    float4 v = ((const float4*)(x + (size_t)row * DD))[tid];
    float s = v.x + v.y + v.z + v.w;
#pragma unroll
    for (int o = 16; o; o >>= 1) s += __shfl_xor_sync(0xffffffffu, s, o);
    if ((tid & 31) == 0) red[tid >> 5] = s;
    __syncthreads();
    float mu = (red[0] + red[1] + red[2] + red[3]) * (1.f / DD);
    float dx = v.x - mu, dy = v.y - mu, dz = v.z - mu, dw = v.w - mu;
    float s2 = dx * dx + dy * dy + dz * dz + dw * dw;
#pragma unroll
    for (int o = 16; o; o >>= 1) s2 += __shfl_xor_sync(0xffffffffu, s2, o);
    __syncthreads();
    if ((tid & 31) == 0) red[tid >> 5] = s2;
    __syncthreads();
    float var = (red[0] + red[1] + red[2] + red[3]) * (1.f / DD);
    float inv = rsqrtf(var + EPS);
    float4 gg = ((const float4*)gamma)[tid];
    float4 bb = ((const float4*)beta)[tid];
    float4 o;
    o.x = dx * inv * gg.x + bb.x;
    o.y = dy * inv * gg.y + bb.y;
    o.z = dz * inv * gg.z + bb.z;
    o.w = dw * inv * gg.w + bb.w;
    *(float4*)(out + (size_t)row * DD + tid * 4) = o;
}

// ------------------------------ launch -------------------------------------
extern "C" void kernel_launch(void* const* d_in, const int* in_sizes, int n_in,
                              void* d_out, int out_size)
{
    const float* x   = (const float*)d_in[0];
    const void*  mask = d_in[1];
    const float* Wq  = (const float*)d_in[2];
    const float* bq  = (const float*)d_in[3];
    const float* Wk  = (const float*)d_in[4];
    const float* bk  = (const float*)d_in[5];
    const float* Wv  = (const float*)d_in[6];
    const float* bv  = (const float*)d_in[7];
    const float* Wo  = (const float*)d_in[8];
    const float* bo  = (const float*)d_in[9];
    const float* ln1g = (const float*)d_in[10];
    const float* ln1b = (const float*)d_in[11];
    const float* W1  = (const float*)d_in[12];
    const float* b1  = (const float*)d_in[13];
    const float* W2  = (const float*)d_in[14];
    const float* b2  = (const float*)d_in[15];
    const float* ln2g = (const float*)d_in[16];
    const float* ln2b = (const float*)d_in[17];

    float* out = (float*)d_out;
    const long OUT_ELEMS = (long)BB * SS_ * DD;
    const long ATTN_ELEMS = (long)BB * HH * SS_ * SS_;
    float* attn_ptr = ((long)out_size >= OUT_ELEMS + ATTN_ELEMS)
                        ? (out + OUT_ELEMS) : nullptr;

    float *qp, *kp, *vp, *ctxp, *t1p, *aop, *hp, *t2p;
    cudaGetSymbolAddress((void**)&qp, g_qb);
    cudaGetSymbolAddress((void**)&kp, g_kb);
    cudaGetSymbolAddress((void**)&vp, g_vb);
    cudaGetSymbolAddress((void**)&ctxp, g_ctx);
    cudaGetSymbolAddress((void**)&t1p, g_t1);
    cudaGetSymbolAddress((void**)&aop, g_ao);
    cudaGetSymbolAddress((void**)&hp, g_h);
    cudaGetSymbolAddress((void**)&t2p, g_t2);

    cudaFuncSetAttribute(attn_kernel,
                         cudaFuncAttributeMaxDynamicSharedMemorySize,
                         ATTN_SMEM_BYTES);

    dim3 blk(256);
    detect_mask_kernel<<<1, 32>>>((const unsigned int*)mask);
    qkv_kernel<<<dim3(12, 32), blk>>>(x, Wq, bq, Wk, bk, Wv, bv, qp, kp, vp);
    attn_kernel<<<dim3(SS_ / 16, BB * HH), blk, ATTN_SMEM_BYTES>>>(
        qp, kp, vp, mask, attn_ptr, ctxp);
    sgemm_kernel<<<dim3(4, 32), blk>>>(ctxp, Wo, bo, x, t1p, DD, DD, 0, 0);
    ln_kernel<<<NTOK, 128>>>(t1p, ln1g, ln1b, aop);
    sgemm_kernel<<<dim3(16, 32), blk>>>(aop, W1, b1, nullptr, hp, DFF, DD, 1, 0);
    sgemm_kernel<<<dim3(4, 32), blk>>>(hp, W2, b2, aop, t2p, DD, DFF, 0, 0);
    ln_kernel<<<NTOK, 128>>>(t2p, ln2g, ln2b, out);
}

// round 9
// speedup vs baseline: 2.2926x; 1.0696x over previous
#include <cuda_runtime.h>
#include <math.h>

#define BB 2
#define SS_ 2048
#define DD 512
#define HH 8
#define DFF 2048
#define NTOK (BB*SS_)          // 4096
#define EPS 1e-5f

typedef unsigned long long ull;
typedef unsigned int u32;

// tf32 mma: HW reads high 19 bits; pass raw fp32 bits (CUTLASS-style).
__device__ __forceinline__ u32 fu(float x) { return __float_as_uint(x); }
__device__ __forceinline__ void mma8(float4& d, u32 a0, u32 a1, u32 a2, u32 a3,
                                     u32 b0, u32 b1) {
    asm("mma.sync.aligned.m16n8k8.row.col.f32.tf32.tf32.f32 "
        "{%0,%1,%2,%3},{%4,%5,%6,%7},{%8,%9},{%0,%1,%2,%3};"
        : "+f"(d.x), "+f"(d.y), "+f"(d.z), "+f"(d.w)
        : "r"(a0), "r"(a1), "r"(a2), "r"(a3), "r"(b0), "r"(b1));
}
__device__ __forceinline__ void ld2(u32& lo, u32& hi, const u32* p) {
    ull v = *(const ull*)p; lo = (u32)v; hi = (u32)(v >> 32);
}

// ------------------------------ scratch ------------------------------------
__device__ float g_qb[BB*HH*SS_*64];
__device__ float g_kb[BB*HH*SS_*64];
__device__ float g_vb[BB*HH*SS_*64];
__device__ float g_ctx[NTOK*DD];
__device__ float g_t1[NTOK*DD];
__device__ float g_ao[NTOK*DD];
__device__ float g_h[NTOK*DFF];
__device__ float g_t2[NTOK*DD];
__device__ int   g_maskmode;               // 0 = int32 mask, 1 = uint8 mask

__global__ void detect_mask_kernel(const unsigned int* __restrict__ m)
{
    if (threadIdx.x == 0 && blockIdx.x == 0) {
        int mode = 0;
        for (int i = 0; i < 4096; i++) {
            if (m[i] > 1u) { mode = 1; break; }
        }
        g_maskmode = mode;
    }
}

// ------------------------------ tf32 GEMM (2-stage smem pipeline) ----------
#define APS 130     // Ap row stride (u32)
#define BPS 10      // Bp row stride (u32)
#define ABUF (16*APS)
#define BBUF (256*BPS)

__device__ __forceinline__ void gemm_tc_body(
    const float* __restrict__ A, const float* __restrict__ W,
    const float* __restrict__ bias, const float* __restrict__ resid,
    float* __restrict__ C, int N, int K, int doRelu, int headStore,
    int rowBase, int colBase, u32* Ap, u32* Bp)
{
    int tid = threadIdx.x;
    int w = tid >> 5, t = tid & 31;
    int wr = w >> 1, wc = w & 1;
    int tq = t >> 2, tr = t & 3;

    float4 acc[2][8];
#pragma unroll
    for (int f = 0; f < 2; f++)
#pragma unroll
        for (int nf = 0; nf < 8; nf++) acc[f][nf] = make_float4(0.f,0.f,0.f,0.f);

    int ar = tid >> 1;
    int akh = (tid & 1) * 8;
    int aslot = 2 * ((ar >> 4) * 8 + (ar & 7)) + ((ar >> 3) & 1);
    const float* Aptr = A + (size_t)(rowBase + ar) * K + akh;
    int bn = tid & 127;
    int bkh = tid >> 7;
    const float* Wptr = W + (size_t)(bkh * 8) * N + colBase + bn;

    float4 av0 = *(const float4*)(Aptr);
    float4 av1 = *(const float4*)(Aptr + 4);
    float bv[8];
#pragma unroll
    for (int i = 0; i < 8; i++) bv[i] = Wptr[(size_t)i * N];

    int buf = 0;
    for (int k0 = 0; k0 < K; k0 += 16) {
        u32* Ab = Ap + buf * ABUF;
        u32* Bb = Bp + buf * BBUF;
        Ab[(akh + 0) * APS + aslot] = fu(av0.x);
        Ab[(akh + 1) * APS + aslot] = fu(av0.y);
        Ab[(akh + 2) * APS + aslot] = fu(av0.z);
        Ab[(akh + 3) * APS + aslot] = fu(av0.w);
        Ab[(akh + 4) * APS + aslot] = fu(av1.x);
        Ab[(akh + 5) * APS + aslot] = fu(av1.y);
        Ab[(akh + 6) * APS + aslot] = fu(av1.z);
        Ab[(akh + 7) * APS + aslot] = fu(av1.w);
#pragma unroll
        for (int i = 0; i < 8; i++)
            Bb[(bkh * 128 + bn) * BPS + 2 * (i & 3) + (i >> 2)] = fu(bv[i]);
        __syncthreads();

        int kn = (k0 + 16 < K) ? (k0 + 16) : k0;
        av0 = *(const float4*)(Aptr + kn);
        av1 = *(const float4*)(Aptr + kn + 4);
#pragma unroll
        for (int i = 0; i < 8; i++) bv[i] = Wptr[(size_t)(kn + i) * N];

#pragma unroll
        for (int kh = 0; kh < 2; kh++) {
            u32 a0[2], a1[2], a2[2], a3[2];
#pragma unroll
            for (int f = 0; f < 2; f++) {
                int gp = (wr * 2 + f) * 8 + tq;
                ld2(a0[f], a1[f], &Ab[(kh * 8 + tr) * APS + 2 * gp]);
                ld2(a2[f], a3[f], &Ab[(kh * 8 + tr + 4) * APS + 2 * gp]);
            }
#pragma unroll
            for (int nf = 0; nf < 8; nf++) {
                int n = wc * 64 + nf * 8 + tq;
                u32 b0, b1;
                ld2(b0, b1, &Bb[(kh * 128 + n) * BPS + 2 * tr]);
#pragma unroll
                for (int f = 0; f < 2; f++)
                    mma8(acc[f][nf], a0[f], a1[f], a2[f], a3[f], b0, b1);
            }
        }
        buf ^= 1;
    }

#pragma unroll
    for (int f = 0; f < 2; f++) {
        int row = rowBase + wr * 32 + f * 16 + tq;
#pragma unroll
        for (int nf = 0; nf < 8; nf++) {
            int col = colBase + wc * 64 + nf * 8 + tr * 2;
            float b0 = bias[col], b1 = bias[col + 1];
            float c00 = acc[f][nf].x + b0, c01 = acc[f][nf].y + b1;
            float c10 = acc[f][nf].z + b0, c11 = acc[f][nf].w + b1;
            if (resid) {
                float2 r0 = *(const float2*)(resid + (size_t)row * N + col);
                float2 r1 = *(const float2*)(resid + (size_t)(row + 8) * N + col);
                c00 += r0.x; c01 += r0.y; c10 += r1.x; c11 += r1.y;
            }
            if (doRelu) {
                c00 = fmaxf(c00, 0.f); c01 = fmaxf(c01, 0.f);
                c10 = fmaxf(c10, 0.f); c11 = fmaxf(c11, 0.f);
            }
            if (headStore) {
                int h_ = col >> 6, d_ = col & 63;
                int b0_ = row / SS_, s0_ = row % SS_;
                *(float2*)&C[(((size_t)(b0_ * HH + h_)) * SS_ + s0_) * 64 + d_] =
                    make_float2(c00, c01);
                int b1_ = (row + 8) / SS_, s1_ = (row + 8) % SS_;
                *(float2*)&C[(((size_t)(b1_ * HH + h_)) * SS_ + s1_) * 64 + d_] =
                    make_float2(c10, c11);
            } else {
                *(float2*)&C[(size_t)row * N + col] = make_float2(c00, c01);
                *(float2*)&C[(size_t)(row + 8) * N + col] = make_float2(c10, c11);
            }
        }
    }
}

__global__ __launch_bounds__(256, 2) void sgemm_kernel(
    const float* __restrict__ A, const float* __restrict__ W,
    const float* __restrict__ bias, const float* __restrict__ resid,
    float* __restrict__ C, int N, int K, int doRelu, int headStore)
{
    __shared__ u32 Ap[2 * ABUF];
    __shared__ u32 Bp[2 * BBUF];
    gemm_tc_body(A, W, bias, resid, C, N, K, doRelu, headStore,
                 blockIdx.y * 128, blockIdx.x * 128, Ap, Bp);
}

__global__ __launch_bounds__(256, 2) void qkv_kernel(
    const float* __restrict__ A,
    const float* __restrict__ Wq, const float* __restrict__ bq,
    const float* __restrict__ Wk, const float* __restrict__ bk,
    const float* __restrict__ Wv, const float* __restrict__ bv,
    float* __restrict__ q, float* __restrict__ k, float* __restrict__ v)
{
    __shared__ u32 Ap[2 * ABUF];
    __shared__ u32 Bp[2 * BBUF];
    int sel = blockIdx.x >> 2;
    const float* W = (sel == 0) ? Wq : (sel == 1) ? Wk : Wv;
    const float* bias = (sel == 0) ? bq : (sel == 1) ? bk : bv;
    float* C = (sel == 0) ? q : (sel == 1) ? k : v;
    gemm_tc_body(A, W, bias, nullptr, C, DD, DD, 0, 1,
                 blockIdx.y * 128, (blockIdx.x & 3) * 128, Ap, Bp);
}

// ------------------------------ fused attention ----------------------------
// grid (S/16, B*H), 256 thr = 8 warps. Wide coalesced LDG -> smem-staged
// K/V tiles (double-buffered, 1 sync/tile); mask packed to smem bits.
#define SSP 2052
#define KROW 68      // K tile row stride (words): conflict-free LDS frags
#define VROW 72      // V tile row stride (words): banks 8*tr+tq distinct
#define KBUF (128*KROW)     // 8704
#define VBUF (128*VROW)     // 9216
#define KV_FLOATS (2*VBUF)  // 18432 (covers 2*KBUF too)
#define ATTN_SMEM_FLOATS (16*SSP + 16*68 + 16 + 1024 + KV_FLOATS)
#define ATTN_SMEM_BYTES  (ATTN_SMEM_FLOATS * 4)

__global__ __launch_bounds__(256) void attn_kernel(
    const float* __restrict__ q, const float* __restrict__ k,
    const float* __restrict__ v, const void* __restrict__ mask,
    float* __restrict__ attn, float* __restrict__ ctx)
{
    extern __shared__ float smem[];
    float* ss   = smem;                      // 16 x 2052 scores
    float* qs   = smem + 16 * SSP;           // 16 x 68 staged q
    float* invs = qs + 16 * 68;              // 16
    u32*  mb    = (u32*)(invs + 16);         // 1024 words: 16x2048 mask bits
    float* kv   = (float*)(mb + 1024);       // K/V tile double buffer

    int tid = threadIdx.x;
    int w = tid >> 5, t = tid & 31;
    int tq = t >> 2, tr = t & 3;
    int bh = blockIdx.y, b_ = bh >> 3, h_ = bh & 7;
    int row0 = blockIdx.x * 16;
    int mm = g_maskmode;

    const float* qptr = q + ((size_t)bh * SS_ + row0) * 64;
    const float* kptr = k + (size_t)bh * SS_ * 64;
    const float* vptr = v + (size_t)bh * SS_ * 64;

    // stage Q 16x64
    {
        int r = tid >> 4, c = tid & 15;
        ((float4*)(qs + r * 68))[c] = ((const float4*)(qptr + r * 64))[c];
    }

    // ---- pack 16x2048 mask block into smem bits (coalesced int4 loads) ----
    if (mm == 0) {
        const int4* mp4 = (const int4*)((const int*)mask +
                          (size_t)b_ * SS_ * SS_ + (size_t)row0 * SS_);
#pragma unroll
        for (int j = 0; j < 32; j++) {
            int idx = j * 256 + tid;             // int4 index (4 elems)
            int4 m = mp4[idx];
            u32 nib = (m.x ? 1u : 0u) | (m.y ? 2u : 0u) |
                      (m.z ? 4u : 0u) | (m.w ? 8u : 0u);
            u32 oth = __shfl_down_sync(0xffffffffu, nib, 1);
            u32 byt = (nib | (oth << 4)) & 0xffu;   // valid on even lanes
            u32 c1 = __shfl_down_sync(0xffffffffu, byt, 2);
            u32 c2 = __shfl_down_sync(0xffffffffu, byt, 4);
            u32 c3 = __shfl_down_sync(0xffffffffu, byt, 6);
            if ((t & 7) == 0)
                mb[idx >> 3] = byt | (c1 << 8) | (c2 << 16) | (c3 << 24);
        }
    } else {
        const int4* mp4 = (const int4*)((const unsigned char*)mask +
                          (size_t)b_ * SS_ * SS_ + (size_t)row0 * SS_);
#pragma unroll
        for (int j = 0; j < 8; j++) {
            int idx = j * 256 + tid;             // int4 index (16 bytes)
            int4 m = mp4[idx];
            u32 bits = 0;
            u32 vv[4] = {(u32)m.x, (u32)m.y, (u32)m.z, (u32)m.w};
#pragma unroll
            for (int e = 0; e < 4; e++) {
                u32 x = vv[e];
                bits |= ((x & 0x000000ffu) ? 1u : 0u) << (e * 4 + 0);
                bits |= ((x & 0x0000ff00u) ? 1u : 0u) << (e * 4 + 1);
                bits |= ((x & 0x00ff0000u) ? 1u : 0u) << (e * 4 + 2);
                bits |= ((x & 0xff000000u) ? 1u : 0u) << (e * 4 + 3);
            }
            u32 hi = __shfl_down_sync(0xffffffffu, bits, 1);
            if ((t & 1) == 0)
                mb[idx >> 1] = (bits & 0xffffu) | (hi << 16);
        }
    }
    __syncthreads();

    // Q fragments in registers (raw fp32 bits)
    u32 qa0[8], qa1[8], qa2[8], qa3[8];
#pragma unroll
    for (int j = 0; j < 8; j++) {
        qa0[j] = fu(qs[tq * 68 + j * 8 + tr]);
        qa1[j] = fu(qs[(tq + 8) * 68 + j * 8 + tr]);
        qa2[j] = fu(qs[tq * 68 + j * 8 + tr + 4]);
        qa3[j] = fu(qs[(tq + 8) * 68 + j * 8 + tr + 4]);
    }

    // ---------------- phase 1: scores; K staged, double-buffered -----------
    const float4* kg = (const float4*)kptr;     // tile nb at nb*2048 float4
    float4 kreg[8];
#pragma unroll
    for (int i = 0; i < 8; i++) kreg[i] = kg[tid + i * 256];

    int kb0 = w * 16 + tq, kb1 = w * 16 + 8 + tq;
    for (int nb = 0; nb < 16; nb++) {
        float* Kb = kv + (nb & 1) * KBUF;
#pragma unroll
        for (int i = 0; i < 8; i++) {
            int f = tid + i * 256;
            *(float4*)&Kb[(f >> 4) * KROW + (f & 15) * 4] = kreg[i];
        }
        __syncthreads();
        int nbn = (nb < 15) ? nb + 1 : nb;
#pragma unroll
        for (int i = 0; i < 8; i++) kreg[i] = kg[nbn * 2048 + tid + i * 256];

        const u32* Kw = (const u32*)Kb;
        float4 A0 = make_float4(0.f,0.f,0.f,0.f), A1 = A0;
#pragma unroll
        for (int j = 0; j < 8; j++) {
            u32 b0 = Kw[kb0 * KROW + j * 8 + tr];
            u32 b1 = Kw[kb0 * KROW + j * 8 + tr + 4];
            u32 c0 = Kw[kb1 * KROW + j * 8 + tr];
            u32 c1 = Kw[kb1 * KROW + j * 8 + tr + 4];
            mma8(A0, qa0[j], qa1[j], qa2[j], qa3[j], b0, b1);
            mma8(A1, qa0[j], qa1[j], qa2[j], qa3[j], c0, c1);
        }
#pragma unroll
        for (int s = 0; s < 2; s++) {
            float4 a = s ? A1 : A0;
            int c = nb * 128 + w * 16 + s * 8 + tr * 2;
            u32 mw0 = mb[tq * 64 + (c >> 5)];
            u32 mw1 = mb[(tq + 8) * 64 + (c >> 5)];
            int sh = c & 31;
            float2 s0, s1;
            s0.x = ((mw0 >> sh) & 1u)       ? -1e9f : a.x * 0.125f;
            s0.y = ((mw0 >> (sh + 1)) & 1u) ? -1e9f : a.y * 0.125f;
            s1.x = ((mw1 >> sh) & 1u)       ? -1e9f : a.z * 0.125f;
            s1.y = ((mw1 >> (sh + 1)) & 1u) ? -1e9f : a.w * 0.125f;
            *(float2*)&ss[tq * SSP + c] = s0;
            *(float2*)&ss[(tq + 8) * SSP + c] = s1;
        }
    }
    __syncthreads();

    // ---------------- phase 2: softmax (warp owns rows w, w+8) -------------
    {
        int wy = w, lx = t;
        float mx0 = -1e30f, mx1 = -1e30f;
#pragma unroll
        for (int ct = 0; ct < 16; ct++) {
            int c0 = ct * 128 + lx * 4;
            float4 x0 = *(float4*)&ss[wy * SSP + c0];
            float4 x1 = *(float4*)&ss[(wy + 8) * SSP + c0];
            mx0 = fmaxf(mx0, fmaxf(fmaxf(x0.x, x0.y), fmaxf(x0.z, x0.w)));
            mx1 = fmaxf(mx1, fmaxf(fmaxf(x1.x, x1.y), fmaxf(x1.z, x1.w)));
        }
#pragma unroll
        for (int o = 16; o; o >>= 1) {
            mx0 = fmaxf(mx0, __shfl_xor_sync(0xffffffffu, mx0, o));
            mx1 = fmaxf(mx1, __shfl_xor_sync(0xffffffffu, mx1, o));
        }
        float sm0 = 0.f, sm1 = 0.f;
#pragma unroll
        for (int ct = 0; ct < 16; ct++) {
            int c0 = ct * 128 + lx * 4;
            float4 x0 = *(float4*)&ss[wy * SSP + c0];
            float4 x1 = *(float4*)&ss[(wy + 8) * SSP + c0];
            x0.x = __expf(x0.x - mx0); x0.y = __expf(x0.y - mx0);
            x0.z = __expf(x0.z - mx0); x0.w = __expf(x0.w - mx0);
            x1.x = __expf(x1.x - mx1); x1.y = __expf(x1.y - mx1);
            x1.z = __expf(x1.z - mx1); x1.w = __expf(x1.w - mx1);
            sm0 += x0.x + x0.y + x0.z + x0.w;
            sm1 += x1.x + x1.y + x1.z + x1.w;
            *(float4*)&ss[wy * SSP + c0] = x0;   // keep e (unnormalized)
            *(float4*)&ss[(wy + 8) * SSP + c0] = x1;
        }
#pragma unroll
        for (int o = 16; o; o >>= 1) {
            sm0 += __shfl_xor_sync(0xffffffffu, sm0, o);
            sm1 += __shfl_xor_sync(0xffffffffu, sm1, o);
        }
        float inv0 = 1.f / sm0, inv1 = 1.f / sm1;
        if (lx == 0) { invs[wy] = inv0; invs[wy + 8] = inv1; }
        if (attn) {
#pragma unroll
            for (int ct = 0; ct < 16; ct++) {
                int c0 = ct * 128 + lx * 4;
                float4 x0 = *(float4*)&ss[wy * SSP + c0];
                float4 x1 = *(float4*)&ss[(wy + 8) * SSP + c0];
                x0.x *= inv0; x0.y *= inv0; x0.z *= inv0; x0.w *= inv0;
                x1.x *= inv1; x1.y *= inv1; x1.z *= inv1; x1.w *= inv1;
                *(float4*)(attn + ((size_t)bh * SS_ + row0 + wy) * SS_ + c0) = x0;
                *(float4*)(attn + ((size_t)bh * SS_ + row0 + wy + 8) * SS_ + c0) = x1;
            }
        }
    }
    __syncthreads();   // ss final; kv free for V staging

    // ---------------- phase 3: P @ V; V staged, double-buffered ------------
    {
        const float4* vg = (const float4*)vptr;
        float4 vreg[8];
#pragma unroll
        for (int i = 0; i < 8; i++) vreg[i] = vg[tid + i * 256];

        int d0 = w * 8;
        float4 aA = make_float4(0.f,0.f,0.f,0.f), aB = aA;
        for (int nb = 0; nb < 16; nb++) {
            float* Vb = kv + (nb & 1) * VBUF;
#pragma unroll
            for (int i = 0; i < 8; i++) {
                int f = tid + i * 256;
                *(float4*)&Vb[(f >> 4) * VROW + (f & 15) * 4] = vreg[i];
            }
            __syncthreads();
            int nbn = (nb < 15) ? nb + 1 : nb;
#pragma unroll
            for (int i = 0; i < 8; i++)
                vreg[i] = vg[nbn * 2048 + tid + i * 256];

            const u32* Vw = (const u32*)Vb;
#pragma unroll
            for (int ch = 0; ch < 16; ch += 2) {
                int kc = nb * 128 + ch * 8;
                int kl = ch * 8;
                u32 a0 = fu(ss[tq * SSP + kc + tr]);
                u32 a1 = fu(ss[(tq + 8) * SSP + kc + tr]);
                u32 a2 = fu(ss[tq * SSP + kc + tr + 4]);
                u32 a3 = fu(ss[(tq + 8) * SSP + kc + tr + 4]);
                u32 b0 = Vw[(kl + tr) * VROW + d0 + tq];
                u32 b1 = Vw[(kl + tr + 4) * VROW + d0 + tq];
                mma8(aA, a0, a1, a2, a3, b0, b1);
                u32 c0 = fu(ss[tq * SSP + kc + 8 + tr]);
                u32 c1 = fu(ss[(tq + 8) * SSP + kc + 8 + tr]);
                u32 c2 = fu(ss[tq * SSP + kc + 8 + tr + 4]);
                u32 c3 = fu(ss[(tq + 8) * SSP + kc + 8 + tr + 4]);
                u32 e0 = Vw[(kl + 8 + tr) * VROW + d0 + tq];
                u32 e1 = Vw[(kl + 8 + tr + 4) * VROW + d0 + tq];
                mma8(aB, c0, c1, c2, c3, e0, e1);
            }
        }
        float4 acc = make_float4(aA.x + aB.x, aA.y + aB.y,
                                 aA.z + aB.z, aA.w + aB.w);
        float i0 = invs[tq], i1 = invs[tq + 8];
        int col = h_ * 64 + d0 + tr * 2;
        *(float2*)&ctx[((size_t)(b_ * SS_ + row0 + tq)) * DD + col] =
            make_float2(acc.x * i0, acc.y * i0);
        *(float2*)&ctx[((size_t)(b_ * SS_ + row0 + tq + 8)) * DD + col] =
            make_float2(acc.z * i1, acc.w * i1);
    }
}

// ------------------------------ layernorm ----------------------------------
__global__ __launch_bounds__(128) void ln_kernel(
    const float* __restrict__ x, const float* __restrict__ gamma,
    const float* __restrict__ beta, float* __restrict__ out)
{
    int row = blockIdx.x;
    int tid = threadIdx.x;
    __shared__ float red[4];
    float4 v = ((const float4*)(x + (size_t)row * DD))[tid];
    float s = v.x + v.y + v.z + v.w;
#pragma unroll
    for (int o = 16; o; o >>= 1) s += __shfl_xor_sync(0xffffffffu, s, o);
    if ((tid & 31) == 0) red[tid >> 5] = s;
    __syncthreads();
    float mu = (red[0] + red[1] + red[2] + red[3]) * (1.f / DD);
    float dx = v.x - mu, dy = v.y - mu, dz = v.z - mu, dw = v.w - mu;
    float s2 = dx * dx + dy * dy + dz * dz + dw * dw;
#pragma unroll
    for (int o = 16; o; o >>= 1) s2 += __shfl_xor_sync(0xffffffffu, s2, o);
    __syncthreads();
    if ((tid & 31) == 0) red[tid >> 5] = s2;
    __syncthreads();
    float var = (red[0] + red[1] + red[2] + red[3]) * (1.f / DD);
    float inv = rsqrtf(var + EPS);
    float4 gg = ((const float4*)gamma)[tid];
    float4 bb = ((const float4*)beta)[tid];
    float4 o;
    o.x = dx * inv * gg.x + bb.x;
    o.y = dy * inv * gg.y + bb.y;
    o.z = dz * inv * gg.z + bb.z;
    o.w = dw * inv * gg.w + bb.w;
    *(float4*)(out + (size_t)row * DD + tid * 4) = o;
}

// ------------------------------ launch -------------------------------------
extern "C" void kernel_launch(void* const* d_in, const int* in_sizes, int n_in,
                              void* d_out, int out_size)
{
    const float* x   = (const float*)d_in[0];
    const void*  mask = d_in[1];
    const float* Wq  = (const float*)d_in[2];
    const float* bq  = (const float*)d_in[3];
    const float* Wk  = (const float*)d_in[4];
    const float* bk  = (const float*)d_in[5];
    const float* Wv  = (const float*)d_in[6];
    const float* bv  = (const float*)d_in[7];
    const float* Wo  = (const float*)d_in[8];
    const float* bo  = (const float*)d_in[9];
    const float* ln1g = (const float*)d_in[10];
    const float* ln1b = (const float*)d_in[11];
    const float* W1  = (const float*)d_in[12];
    const float* b1  = (const float*)d_in[13];
    const float* W2  = (const float*)d_in[14];
    const float* b2  = (const float*)d_in[15];
    const float* ln2g = (const float*)d_in[16];
    const float* ln2b = (const float*)d_in[17];

    float* out = (float*)d_out;
    const long OUT_ELEMS = (long)BB * SS_ * DD;
    const long ATTN_ELEMS = (long)BB * HH * SS_ * SS_;
    float* attn_ptr = ((long)out_size >= OUT_ELEMS + ATTN_ELEMS)
                        ? (out + OUT_ELEMS) : nullptr;

    float *qp, *kp, *vp, *ctxp, *t1p, *aop, *hp, *t2p;
    cudaGetSymbolAddress((void**)&qp, g_qb);
    cudaGetSymbolAddress((void**)&kp, g_kb);
    cudaGetSymbolAddress((void**)&vp, g_vb);
    cudaGetSymbolAddress((void**)&ctxp, g_ctx);
    cudaGetSymbolAddress((void**)&t1p, g_t1);
    cudaGetSymbolAddress((void**)&aop, g_ao);
    cudaGetSymbolAddress((void**)&hp, g_h);
    cudaGetSymbolAddress((void**)&t2p, g_t2);

    cudaFuncSetAttribute(attn_kernel,
                         cudaFuncAttributeMaxDynamicSharedMemorySize,
                         ATTN_SMEM_BYTES);

    dim3 blk(256);
    detect_mask_kernel<<<1, 32>>>((const unsigned int*)mask);
    qkv_kernel<<<dim3(12, 32), blk>>>(x, Wq, bq, Wk, bk, Wv, bv, qp, kp, vp);
    attn_kernel<<<dim3(SS_ / 16, BB * HH), blk, ATTN_SMEM_BYTES>>>(
        qp, kp, vp, mask, attn_ptr, ctxp);
    sgemm_kernel<<<dim3(4, 32), blk>>>(ctxp, Wo, bo, x, t1p, DD, DD, 0, 0);
    ln_kernel<<<NTOK, 128>>>(t1p, ln1g, ln1b, aop);
    sgemm_kernel<<<dim3(16, 32), blk>>>(aop, W1, b1, nullptr, hp, DFF, DD, 1, 0);
    sgemm_kernel<<<dim3(4, 32), blk>>>(hp, W2, b2, aop, t2p, DD, DFF, 0, 0);
    ln_kernel<<<NTOK, 128>>>(t2p, ln2g, ln2b, out);
}

// round 10
// speedup vs baseline: 2.4345x; 1.0619x over previous
#include <cuda_runtime.h>
#include <math.h>

#define BB 2
#define SS_ 2048
#define DD 512
#define HH 8
#define DFF 2048
#define NTOK (BB*SS_)          // 4096
#define EPS 1e-5f

typedef unsigned long long ull;
typedef unsigned int u32;

// tf32 mma: HW reads high 19 bits; pass raw fp32 bits (CUTLASS-style).
__device__ __forceinline__ u32 fu(float x) { return __float_as_uint(x); }
__device__ __forceinline__ void mma8(float4& d, u32 a0, u32 a1, u32 a2, u32 a3,
                                     u32 b0, u32 b1) {
    asm("mma.sync.aligned.m16n8k8.row.col.f32.tf32.tf32.f32 "
        "{%0,%1,%2,%3},{%4,%5,%6,%7},{%8,%9},{%0,%1,%2,%3};"
        : "+f"(d.x), "+f"(d.y), "+f"(d.z), "+f"(d.w)
        : "r"(a0), "r"(a1), "r"(a2), "r"(a3), "r"(b0), "r"(b1));
}
__device__ __forceinline__ void ld2(u32& lo, u32& hi, const u32* p) {
    ull v = *(const ull*)p; lo = (u32)v; hi = (u32)(v >> 32);
}

// ------------------------------ scratch ------------------------------------
__device__ float g_qb[BB*HH*SS_*64];
__device__ float g_kb[BB*HH*SS_*64];
__device__ float g_vb[BB*HH*SS_*64];
__device__ float g_ctx[NTOK*DD];
__device__ float g_t1[NTOK*DD];
__device__ float g_ao[NTOK*DD];
__device__ float g_h[NTOK*DFF];
__device__ float g_t2[NTOK*DD];
__device__ float g_attn[(size_t)BB*HH*SS_*SS_];   // fallback if attn not in d_out
__device__ int   g_maskmode;               // 0 = int32 mask, 1 = uint8 mask

__global__ void detect_mask_kernel(const unsigned int* __restrict__ m)
{
    if (threadIdx.x == 0 && blockIdx.x == 0) {
        int mode = 0;
        for (int i = 0; i < 4096; i++) {
            if (m[i] > 1u) { mode = 1; break; }
        }
        g_maskmode = mode;
    }
}

// ------------------------------ tf32 GEMM (2-stage smem pipeline) ----------
#define APS 130     // Ap row stride (u32)
#define BPS 10      // Bp row stride (u32)
#define ABUF (16*APS)
#define BBUF (256*BPS)

__device__ __forceinline__ void gemm_tc_body(
    const float* __restrict__ A, const float* __restrict__ W,
    const float* __restrict__ bias, const float* __restrict__ resid,
    float* __restrict__ C, int N, int K, int doRelu, int headStore,
    int rowBase, int colBase, u32* Ap, u32* Bp)
{
    int tid = threadIdx.x;
    int w = tid >> 5, t = tid & 31;
    int wr = w >> 1, wc = w & 1;
    int tq = t >> 2, tr = t & 3;

    float4 acc[2][8];
#pragma unroll
    for (int f = 0; f < 2; f++)
#pragma unroll
        for (int nf = 0; nf < 8; nf++) acc[f][nf] = make_float4(0.f,0.f,0.f,0.f);

    int ar = tid >> 1;
    int akh = (tid & 1) * 8;
    int aslot = 2 * ((ar >> 4) * 8 + (ar & 7)) + ((ar >> 3) & 1);
    const float* Aptr = A + (size_t)(rowBase + ar) * K + akh;
    int bn = tid & 127;
    int bkh = tid >> 7;
    const float* Wptr = W + (size_t)(bkh * 8) * N + colBase + bn;

    float4 av0 = *(const float4*)(Aptr);
    float4 av1 = *(const float4*)(Aptr + 4);
    float bv[8];
#pragma unroll
    for (int i = 0; i < 8; i++) bv[i] = Wptr[(size_t)i * N];

    int buf = 0;
    for (int k0 = 0; k0 < K; k0 += 16) {
        u32* Ab = Ap + buf * ABUF;
        u32* Bb = Bp + buf * BBUF;
        Ab[(akh + 0) * APS + aslot] = fu(av0.x);
        Ab[(akh + 1) * APS + aslot] = fu(av0.y);
        Ab[(akh + 2) * APS + aslot] = fu(av0.z);
        Ab[(akh + 3) * APS + aslot] = fu(av0.w);
        Ab[(akh + 4) * APS + aslot] = fu(av1.x);
        Ab[(akh + 5) * APS + aslot] = fu(av1.y);
        Ab[(akh + 6) * APS + aslot] = fu(av1.z);
        Ab[(akh + 7) * APS + aslot] = fu(av1.w);
#pragma unroll
        for (int i = 0; i < 8; i++)
            Bb[(bkh * 128 + bn) * BPS + 2 * (i & 3) + (i >> 2)] = fu(bv[i]);
        __syncthreads();

        int kn = (k0 + 16 < K) ? (k0 + 16) : k0;
        av0 = *(const float4*)(Aptr + kn);
        av1 = *(const float4*)(Aptr + kn + 4);
#pragma unroll
        for (int i = 0; i < 8; i++) bv[i] = Wptr[(size_t)(kn + i) * N];

#pragma unroll
        for (int kh = 0; kh < 2; kh++) {
            u32 a0[2], a1[2], a2[2], a3[2];
#pragma unroll
            for (int f = 0; f < 2; f++) {
                int gp = (wr * 2 + f) * 8 + tq;
                ld2(a0[f], a1[f], &Ab[(kh * 8 + tr) * APS + 2 * gp]);
                ld2(a2[f], a3[f], &Ab[(kh * 8 + tr + 4) * APS + 2 * gp]);
            }
#pragma unroll
            for (int nf = 0; nf < 8; nf++) {
                int n = wc * 64 + nf * 8 + tq;
                u32 b0, b1;
                ld2(b0, b1, &Bb[(kh * 128 + n) * BPS + 2 * tr]);
#pragma unroll
                for (int f = 0; f < 2; f++)
                    mma8(acc[f][nf], a0[f], a1[f], a2[f], a3[f], b0, b1);
            }
        }
        buf ^= 1;
    }

#pragma unroll
    for (int f = 0; f < 2; f++) {
        int row = rowBase + wr * 32 + f * 16 + tq;
#pragma unroll
        for (int nf = 0; nf < 8; nf++) {
            int col = colBase + wc * 64 + nf * 8 + tr * 2;
            float b0 = bias[col], b1 = bias[col + 1];
            float c00 = acc[f][nf].x + b0, c01 = acc[f][nf].y + b1;
            float c10 = acc[f][nf].z + b0, c11 = acc[f][nf].w + b1;
            if (resid) {
                float2 r0 = *(const float2*)(resid + (size_t)row * N + col);
                float2 r1 = *(const float2*)(resid + (size_t)(row + 8) * N + col);
                c00 += r0.x; c01 += r0.y; c10 += r1.x; c11 += r1.y;
            }
            if (doRelu) {
                c00 = fmaxf(c00, 0.f); c01 = fmaxf(c01, 0.f);
                c10 = fmaxf(c10, 0.f); c11 = fmaxf(c11, 0.f);
            }
            if (headStore) {
                int h_ = col >> 6, d_ = col & 63;
                int b0_ = row / SS_, s0_ = row % SS_;
                *(float2*)&C[(((size_t)(b0_ * HH + h_)) * SS_ + s0_) * 64 + d_] =
                    make_float2(c00, c01);
                int b1_ = (row + 8) / SS_, s1_ = (row + 8) % SS_;
                *(float2*)&C[(((size_t)(b1_ * HH + h_)) * SS_ + s1_) * 64 + d_] =
                    make_float2(c10, c11);
            } else {
                *(float2*)&C[(size_t)row * N + col] = make_float2(c00, c01);
                *(float2*)&C[(size_t)(row + 8) * N + col] = make_float2(c10, c11);
            }
        }
    }
}

__global__ __launch_bounds__(256, 2) void sgemm_kernel(
    const float* __restrict__ A, const float* __restrict__ W,
    const float* __restrict__ bias, const float* __restrict__ resid,
    float* __restrict__ C, int N, int K, int doRelu, int headStore)
{
    __shared__ u32 Ap[2 * ABUF];
    __shared__ u32 Bp[2 * BBUF];
    gemm_tc_body(A, W, bias, resid, C, N, K, doRelu, headStore,
                 blockIdx.y * 128, blockIdx.x * 128, Ap, Bp);
}

__global__ __launch_bounds__(256, 2) void qkv_kernel(
    const float* __restrict__ A,
    const float* __restrict__ Wq, const float* __restrict__ bq,
    const float* __restrict__ Wk, const float* __restrict__ bk,
    const float* __restrict__ Wv, const float* __restrict__ bv,
    float* __restrict__ q, float* __restrict__ k, float* __restrict__ v)
{
    __shared__ u32 Ap[2 * ABUF];
    __shared__ u32 Bp[2 * BBUF];
    int sel = blockIdx.x >> 2;
    const float* W = (sel == 0) ? Wq : (sel == 1) ? Wk : Wv;
    const float* bias = (sel == 0) ? bq : (sel == 1) ? bk : bv;
    float* C = (sel == 0) ? q : (sel == 1) ? k : v;
    gemm_tc_body(A, W, bias, nullptr, C, DD, DD, 0, 1,
                 blockIdx.y * 128, (blockIdx.x & 3) * 128, Ap, Bp);
}

// ------------------------------ attention kernel A -------------------------
// scores + mask + softmax + normalized attn write. NO P@V (separate kernel).
// grid (S/16, B*H), 256 thr = 8 warps.
#define SSP 2052
#define KROW 68      // K tile row stride (words): conflict-free LDS frags
#define KBUF (128*KROW)     // 8704
#define ATTN_SMEM_FLOATS (16*SSP + 16*68 + 16 + 1024 + 2*KBUF)
#define ATTN_SMEM_BYTES  (ATTN_SMEM_FLOATS * 4)

__global__ __launch_bounds__(256) void attn_kernel(
    const float* __restrict__ q, const float* __restrict__ k,
    const void* __restrict__ mask, float* __restrict__ attn)
{
    extern __shared__ float smem[];
    float* ss   = smem;                      // 16 x 2052 scores
    float* qs   = smem + 16 * SSP;           // 16 x 68 staged q
    float* invs = qs + 16 * 68;              // 16
    u32*  mb    = (u32*)(invs + 16);         // 1024 words: 16x2048 mask bits
    float* kv   = (float*)(mb + 1024);       // K tile double buffer

    int tid = threadIdx.x;
    int w = tid >> 5, t = tid & 31;
    int tq = t >> 2, tr = t & 3;
    int bh = blockIdx.y, b_ = bh >> 3;
    int row0 = blockIdx.x * 16;
    int mm = g_maskmode;

    const float* qptr = q + ((size_t)bh * SS_ + row0) * 64;
    const float* kptr = k + (size_t)bh * SS_ * 64;

    // stage Q 16x64
    {
        int r = tid >> 4, c = tid & 15;
        ((float4*)(qs + r * 68))[c] = ((const float4*)(qptr + r * 64))[c];
    }

    // ---- pack 16x2048 mask block into smem bits (coalesced int4 loads) ----
    if (mm == 0) {
        const int4* mp4 = (const int4*)((const int*)mask +
                          (size_t)b_ * SS_ * SS_ + (size_t)row0 * SS_);
#pragma unroll
        for (int j = 0; j < 32; j++) {
            int idx = j * 256 + tid;             // int4 index (4 elems)
            int4 m = mp4[idx];
            u32 nib = (m.x ? 1u : 0u) | (m.y ? 2u : 0u) |
                      (m.z ? 4u : 0u) | (m.w ? 8u : 0u);
            u32 oth = __shfl_down_sync(0xffffffffu, nib, 1);
            u32 byt = (nib | (oth << 4)) & 0xffu;   // valid on even lanes
            u32 c1 = __shfl_down_sync(0xffffffffu, byt, 2);
            u32 c2 = __shfl_down_sync(0xffffffffu, byt, 4);
            u32 c3 = __shfl_down_sync(0xffffffffu, byt, 6);
            if ((t & 7) == 0)
                mb[idx >> 3] = byt | (c1 << 8) | (c2 << 16) | (c3 << 24);
        }
    } else {
        const int4* mp4 = (const int4*)((const unsigned char*)mask +
                          (size_t)b_ * SS_ * SS_ + (size_t)row0 * SS_);
#pragma unroll
        for (int j = 0; j < 8; j++) {
            int idx = j * 256 + tid;             // int4 index (16 bytes)
            int4 m = mp4[idx];
            u32 bits = 0;
            u32 vv[4] = {(u32)m.x, (u32)m.y, (u32)m.z, (u32)m.w};
#pragma unroll
            for (int e = 0; e < 4; e++) {
                u32 x = vv[e];
                bits |= ((x & 0x000000ffu) ? 1u : 0u) << (e * 4 + 0);
                bits |= ((x & 0x0000ff00u) ? 1u : 0u) << (e * 4 + 1);
                bits |= ((x & 0x00ff0000u) ? 1u : 0u) << (e * 4 + 2);
                bits |= ((x & 0xff000000u) ? 1u : 0u) << (e * 4 + 3);
            }
            u32 hi = __shfl_down_sync(0xffffffffu, bits, 1);
            if ((t & 1) == 0)
                mb[idx >> 1] = (bits & 0xffffu) | (hi << 16);
        }
    }
    __syncthreads();

    // Q fragments in registers (raw fp32 bits)
    u32 qa0[8], qa1[8], qa2[8], qa3[8];
#pragma unroll
    for (int j = 0; j < 8; j++) {
        qa0[j] = fu(qs[tq * 68 + j * 8 + tr]);
        qa1[j] = fu(qs[(tq + 8) * 68 + j * 8 + tr]);
        qa2[j] = fu(qs[tq * 68 + j * 8 + tr + 4]);
        qa3[j] = fu(qs[(tq + 8) * 68 + j * 8 + tr + 4]);
    }

    // ---------------- phase 1: scores; K staged, double-buffered -----------
    const float4* kg = (const float4*)kptr;     // tile nb at nb*2048 float4
    float4 kreg[8];
#pragma unroll
    for (int i = 0; i < 8; i++) kreg[i] = kg[tid + i * 256];

    int kb0 = w * 16 + tq, kb1 = w * 16 + 8 + tq;
    for (int nb = 0; nb < 16; nb++) {
        float* Kb = kv + (nb & 1) * KBUF;
#pragma unroll
        for (int i = 0; i < 8; i++) {
            int f = tid + i * 256;
            *(float4*)&Kb[(f >> 4) * KROW + (f & 15) * 4] = kreg[i];
        }
        __syncthreads();
        int nbn = (nb < 15) ? nb + 1 : nb;
#pragma unroll
        for (int i = 0; i < 8; i++) kreg[i] = kg[nbn * 2048 + tid + i * 256];

        const u32* Kw = (const u32*)Kb;
        float4 A0 = make_float4(0.f,0.f,0.f,0.f), A1 = A0;
#pragma unroll
        for (int j = 0; j < 8; j++) {
            u32 b0 = Kw[kb0 * KROW + j * 8 + tr];
            u32 b1 = Kw[kb0 * KROW + j * 8 + tr + 4];
            u32 c0 = Kw[kb1 * KROW + j * 8 + tr];
            u32 c1 = Kw[kb1 * KROW + j * 8 + tr + 4];
            mma8(A0, qa0[j], qa1[j], qa2[j], qa3[j], b0, b1);
            mma8(A1, qa0[j], qa1[j], qa2[j], qa3[j], c0, c1);
        }
#pragma unroll
        for (int s = 0; s < 2; s++) {
            float4 a = s ? A1 : A0;
            int c = nb * 128 + w * 16 + s * 8 + tr * 2;
            u32 mw0 = mb[tq * 64 + (c >> 5)];
            u32 mw1 = mb[(tq + 8) * 64 + (c >> 5)];
            int sh = c & 31;
            float2 s0, s1;
            s0.x = ((mw0 >> sh) & 1u)       ? -1e9f : a.x * 0.125f;
            s0.y = ((mw0 >> (sh + 1)) & 1u) ? -1e9f : a.y * 0.125f;
            s1.x = ((mw1 >> sh) & 1u)       ? -1e9f : a.z * 0.125f;
            s1.y = ((mw1 >> (sh + 1)) & 1u) ? -1e9f : a.w * 0.125f;
            *(float2*)&ss[tq * SSP + c] = s0;
            *(float2*)&ss[(tq + 8) * SSP + c] = s1;
        }
    }
    __syncthreads();

    // ---------------- phase 2: softmax + normalized attn write -------------
    {
        int wy = w, lx = t;
        float mx0 = -1e30f, mx1 = -1e30f;
#pragma unroll
        for (int ct = 0; ct < 16; ct++) {
            int c0 = ct * 128 + lx * 4;
            float4 x0 = *(float4*)&ss[wy * SSP + c0];
            float4 x1 = *(float4*)&ss[(wy + 8) * SSP + c0];
            mx0 = fmaxf(mx0, fmaxf(fmaxf(x0.x, x0.y), fmaxf(x0.z, x0.w)));
            mx1 = fmaxf(mx1, fmaxf(fmaxf(x1.x, x1.y), fmaxf(x1.z, x1.w)));
        }
#pragma unroll
        for (int o = 16; o; o >>= 1) {
            mx0 = fmaxf(mx0, __shfl_xor_sync(0xffffffffu, mx0, o));
            mx1 = fmaxf(mx1, __shfl_xor_sync(0xffffffffu, mx1, o));
        }
        float sm0 = 0.f, sm1 = 0.f;
#pragma unroll
        for (int ct = 0; ct < 16; ct++) {
            int c0 = ct * 128 + lx * 4;
            float4 x0 = *(float4*)&ss[wy * SSP + c0];
            float4 x1 = *(float4*)&ss[(wy + 8) * SSP + c0];
            x0.x = __expf(x0.x - mx0); x0.y = __expf(x0.y - mx0);
            x0.z = __expf(x0.z - mx0); x0.w = __expf(x0.w - mx0);
            x1.x = __expf(x1.x - mx1); x1.y = __expf(x1.y - mx1);
            x1.z = __expf(x1.z - mx1); x1.w = __expf(x1.w - mx1);
            sm0 += x0.x + x0.y + x0.z + x0.w;
            sm1 += x1.x + x1.y + x1.z + x1.w;
            *(float4*)&ss[wy * SSP + c0] = x0;
            *(float4*)&ss[(wy + 8) * SSP + c0] = x1;
        }
#pragma unroll
        for (int o = 16; o; o >>= 1) {
            sm0 += __shfl_xor_sync(0xffffffffu, sm0, o);
            sm1 += __shfl_xor_sync(0xffffffffu, sm1, o);
        }
        float inv0 = 1.f / sm0, inv1 = 1.f / sm1;
        int bh2 = blockIdx.y;
#pragma unroll
        for (int ct = 0; ct < 16; ct++) {
            int c0 = ct * 128 + lx * 4;
            float4 x0 = *(float4*)&ss[wy * SSP + c0];
            float4 x1 = *(float4*)&ss[(wy + 8) * SSP + c0];
            x0.x *= inv0; x0.y *= inv0; x0.z *= inv0; x0.w *= inv0;
            x1.x *= inv1; x1.y *= inv1; x1.z *= inv1; x1.w *= inv1;
            *(float4*)(attn + ((size_t)bh2 * SS_ + row0 + wy) * SS_ + c0) = x0;
            *(float4*)(attn + ((size_t)bh2 * SS_ + row0 + wy + 8) * SS_ + c0) = x1;
        }
    }
}

// ------------------------------ attention kernel B: ctx = attn @ V ---------
// grid (16 row-tiles, 16 bh), 256 thr = 8 warps. CTA tile 128 tokens x 64
// dims, K=2048 keys, double-buffered. attn streamed from gmem (DRAM/L2).
__global__ __launch_bounds__(256, 2) void pv_kernel(
    const float* __restrict__ attn, const float* __restrict__ v,
    float* __restrict__ ctx)
{
    __shared__ u32 Ap[2 * ABUF];
    __shared__ u32 Bp[2 * (128 * BPS)];

    int tid = threadIdx.x;
    int w = tid >> 5, t = tid & 31;
    int tq = t >> 2, tr = t & 3;
    int bh = blockIdx.y, b_ = bh >> 3, h_ = bh & 7;
    int row0 = blockIdx.x * 128;

    const float* P = attn + (size_t)bh * SS_ * SS_ + (size_t)row0 * SS_;
    const float* V = v + (size_t)bh * SS_ * 64;

    float4 acc[8];
#pragma unroll
    for (int nf = 0; nf < 8; nf++) acc[nf] = make_float4(0.f,0.f,0.f,0.f);

    // A staging (identical layout to gemm): 128 rows x 16 k
    int ar = tid >> 1;
    int akh = (tid & 1) * 8;
    int aslot = 2 * ((ar >> 4) * 8 + (ar & 7)) + ((ar >> 3) & 1);
    const float* Aptr = P + (size_t)ar * SS_ + akh;
    // B staging: 16 k x 64 n; thread loads 4 k's for col bn
    int bn = tid & 63;
    int bkh = tid >> 6;          // 0..3
    const float* Vptr = V + (size_t)(bkh * 4) * 64 + bn;

    float4 av0 = *(const float4*)(Aptr);
    float4 av1 = *(const float4*)(Aptr + 4);
    float bv[4];
#pragma unroll
    for (int i = 0; i < 4; i++) bv[i] = Vptr[(size_t)i * 64];

    int buf = 0;
    for (int k0 = 0; k0 < SS_; k0 += 16) {
        u32* Ab = Ap + buf * ABUF;
        u32* Bb = Bp + buf * (128 * BPS);
        Ab[(akh + 0) * APS + aslot] = fu(av0.x);
        Ab[(akh + 1) * APS + aslot] = fu(av0.y);
        Ab[(akh + 2) * APS + aslot] = fu(av0.z);
        Ab[(akh + 3) * APS + aslot] = fu(av0.w);
        Ab[(akh + 4) * APS + aslot] = fu(av1.x);
        Ab[(akh + 5) * APS + aslot] = fu(av1.y);
        Ab[(akh + 6) * APS + aslot] = fu(av1.z);
        Ab[(akh + 7) * APS + aslot] = fu(av1.w);
#pragma unroll
        for (int i = 0; i < 4; i++) {
            int kg = bkh * 4 + i;
            int kh = kg >> 3, kl = kg & 7;
            Bb[(kh * 64 + bn) * BPS + 2 * (kl & 3) + (kl >> 2)] = fu(bv[i]);
        }
        __syncthreads();

        int kn = (k0 + 16 < SS_) ? (k0 + 16) : k0;
        av0 = *(const float4*)(Aptr + kn);
        av1 = *(const float4*)(Aptr + kn + 4);
#pragma unroll
        for (int i = 0; i < 4; i++) bv[i] = Vptr[(size_t)(kn + i) * 64];

#pragma unroll
        for (int kh = 0; kh < 2; kh++) {
            u32 a0, a1, a2, a3;
            int gp = w * 8 + tq;
            ld2(a0, a1, &Ab[(kh * 8 + tr) * APS + 2 * gp]);
            ld2(a2, a3, &Ab[(kh * 8 + tr + 4) * APS + 2 * gp]);
#pragma unroll
            for (int nf = 0; nf < 8; nf++) {
                int n = nf * 8 + tq;
                u32 b0, b1;
                ld2(b0, b1, &Bb[(kh * 64 + n) * BPS + 2 * tr]);
                mma8(acc[nf], a0, a1, a2, a3, b0, b1);
            }
        }
        buf ^= 1;
    }

    // epilogue: ctx[token][h*64 + col]
    int r0 = row0 + w * 16 + tq;
#pragma unroll
    for (int nf = 0; nf < 8; nf++) {
        int col = h_ * 64 + nf * 8 + tr * 2;
        *(float2*)&ctx[((size_t)(b_ * SS_ + r0)) * DD + col] =
            make_float2(acc[nf].x, acc[nf].y);
        *(float2*)&ctx[((size_t)(b_ * SS_ + r0 + 8)) * DD + col] =
            make_float2(acc[nf].z, acc[nf].w);
    }
}

// ------------------------------ layernorm ----------------------------------
__global__ __launch_bounds__(128) void ln_kernel(
    const float* __restrict__ x, const float* __restrict__ gamma,
    const float* __restrict__ beta, float* __restrict__ out)
{
    int row = blockIdx.x;
    int tid = threadIdx.x;
    __shared__ float red[4];
    float4 v = ((const float4*)(x + (size_t)row * DD))[tid];
    float s = v.x + v.y + v.z + v.w;
#pragma unroll
    for (int o = 16; o; o >>= 1) s += __shfl_xor_sync(0xffffffffu, s, o);
    if ((tid & 31) == 0) red[tid >> 5] = s;
    __syncthreads();
    float mu = (red[0] + red[1] + red[2] + red[3]) * (1.f / DD);
    float dx = v.x - mu, dy = v.y - mu, dz = v.z - mu, dw = v.w - mu;
    float s2 = dx * dx + dy * dy + dz * dz + dw * dw;
#pragma unroll
    for (int o = 16; o; o >>= 1) s2 += __shfl_xor_sync(0xffffffffu, s2, o);
    __syncthreads();
    if ((tid & 31) == 0) red[tid >> 5] = s2;
    __syncthreads();
    float var = (red[0] + red[1] + red[2] + red[3]) * (1.f / DD);
    float inv = rsqrtf(var + EPS);
    float4 gg = ((const float4*)gamma)[tid];
    float4 bb = ((const float4*)beta)[tid];
    float4 o;
    o.x = dx * inv * gg.x + bb.x;
    o.y = dy * inv * gg.y + bb.y;
    o.z = dz * inv * gg.z + bb.z;
    o.w = dw * inv * gg.w + bb.w;
    *(float4*)(out + (size_t)row * DD + tid * 4) = o;
}

// ------------------------------ launch -------------------------------------
extern "C" void kernel_launch(void* const* d_in, const int* in_sizes, int n_in,
                              void* d_out, int out_size)
{
    const float* x   = (const float*)d_in[0];
    const void*  mask = d_in[1];
    const float* Wq  = (const float*)d_in[2];
    const float* bq  = (const float*)d_in[3];
    const float* Wk  = (const float*)d_in[4];
    const float* bk  = (const float*)d_in[5];
    const float* Wv  = (const float*)d_in[6];
    const float* bv  = (const float*)d_in[7];
    const float* Wo  = (const float*)d_in[8];
    const float* bo  = (const float*)d_in[9];
    const float* ln1g = (const float*)d_in[10];
    const float* ln1b = (const float*)d_in[11];
    const float* W1  = (const float*)d_in[12];
    const float* b1  = (const float*)d_in[13];
    const float* W2  = (const float*)d_in[14];
    const float* b2  = (const float*)d_in[15];
    const float* ln2g = (const float*)d_in[16];
    const float* ln2b = (const float*)d_in[17];

    float* out = (float*)d_out;
    const long OUT_ELEMS = (long)BB * SS_ * DD;
    const long ATTN_ELEMS = (long)BB * HH * SS_ * SS_;

    float *qp, *kp, *vp, *ctxp, *t1p, *aop, *hp, *t2p, *attnScratch;
    cudaGetSymbolAddress((void**)&qp, g_qb);
    cudaGetSymbolAddress((void**)&kp, g_kb);
    cudaGetSymbolAddress((void**)&vp, g_vb);
    cudaGetSymbolAddress((void**)&ctxp, g_ctx);
    cudaGetSymbolAddress((void**)&t1p, g_t1);
    cudaGetSymbolAddress((void**)&aop, g_ao);
    cudaGetSymbolAddress((void**)&hp, g_h);
    cudaGetSymbolAddress((void**)&t2p, g_t2);
    cudaGetSymbolAddress((void**)&attnScratch, g_attn);

    float* attn_ptr = ((long)out_size >= OUT_ELEMS + ATTN_ELEMS)
                        ? (out + OUT_ELEMS) : attnScratch;

    cudaFuncSetAttribute(attn_kernel,
                         cudaFuncAttributeMaxDynamicSharedMemorySize,
                         ATTN_SMEM_BYTES);

    dim3 blk(256);
    detect_mask_kernel<<<1, 32>>>((const unsigned int*)mask);
    qkv_kernel<<<dim3(12, 32), blk>>>(x, Wq, bq, Wk, bk, Wv, bv, qp, kp, vp);
    attn_kernel<<<dim3(SS_ / 16, BB * HH), blk, ATTN_SMEM_BYTES>>>(
        qp, kp, mask, attn_ptr);
    pv_kernel<<<dim3(16, BB * HH), blk>>>(attn_ptr, vp, ctxp);
    sgemm_kernel<<<dim3(4, 32), blk>>>(ctxp, Wo, bo, x, t1p, DD, DD, 0, 0);
    ln_kernel<<<NTOK, 128>>>(t1p, ln1g, ln1b, aop);
    sgemm_kernel<<<dim3(16, 32), blk>>>(aop, W1, b1, nullptr, hp, DFF, DD, 1, 0);
    sgemm_kernel<<<dim3(4, 32), blk>>>(hp, W2, b2, aop, t2p, DD, DFF, 0, 0);
    ln_kernel<<<NTOK, 128>>>(t2p, ln2g, ln2b, out);
}

// round 13
// speedup vs baseline: 3.0888x; 1.2688x over previous
#include <cuda_runtime.h>
#include <math.h>

#define BB 2
#define SS_ 2048
#define DD 512
#define HH 8
#define DFF 2048
#define NTOK (BB*SS_)          // 4096
#define EPS 1e-5f

typedef unsigned long long ull;
typedef unsigned int u32;

// tf32 mma: HW reads high 19 bits; pass raw fp32 bits (CUTLASS-style).
__device__ __forceinline__ u32 fu(float x) { return __float_as_uint(x); }
__device__ __forceinline__ void mma8(float4& d, u32 a0, u32 a1, u32 a2, u32 a3,
                                     u32 b0, u32 b1) {
    asm("mma.sync.aligned.m16n8k8.row.col.f32.tf32.tf32.f32 "
        "{%0,%1,%2,%3},{%4,%5,%6,%7},{%8,%9},{%0,%1,%2,%3};"
        : "+f"(d.x), "+f"(d.y), "+f"(d.z), "+f"(d.w)
        : "r"(a0), "r"(a1), "r"(a2), "r"(a3), "r"(b0), "r"(b1));
}
__device__ __forceinline__ u32 s2u(const void* p) {
    return (u32)__cvta_generic_to_shared(p);
}
__device__ __forceinline__ void cpa(u32 dst, const void* src) {
    asm volatile("cp.async.cg.shared.global [%0], [%1], 16;"
                 :: "r"(dst), "l"(src));
}
#define CP_COMMIT() asm volatile("cp.async.commit_group;" ::: "memory")
#define CP_WAIT2()  asm volatile("cp.async.wait_group 2;" ::: "memory")

// ------------------------------ scratch ------------------------------------
__device__ float g_qb[BB*HH*SS_*64];
__device__ float g_kb[BB*HH*SS_*64];
__device__ float g_vb[BB*HH*SS_*64];
__device__ float g_ctx[NTOK*DD];
__device__ float g_t1[NTOK*DD];
__device__ float g_ao[NTOK*DD];
__device__ float g_h[NTOK*DFF];
__device__ float g_t2[NTOK*DD];
__device__ float g_attn[(size_t)BB*HH*SS_*SS_];   // fallback if attn not in d_out
__device__ int   g_maskmode;               // 0 = int32 mask, 1 = uint8 mask

__global__ void detect_mask_kernel(const unsigned int* __restrict__ m)
{
    if (threadIdx.x == 0 && blockIdx.x == 0) {
        int mode = 0;
        for (int i = 0; i < 4096; i++) {
            if (m[i] > 1u) { mode = 1; break; }
        }
        g_maskmode = mode;
    }
}

// ------------------------------ tf32 GEMM (4-stage cp.async) ---------------
// C[M,N] = A[M,K] @ W[K,N]. CTA 128x128, chunk BK=16, 8 warps (4x2),
// warp 32x64. Stages in natural layouts; fragments via conflict-free LDS.
#define AST 20                       // A stage row stride (words)
#define WST 136                      // W stage row stride (words)
#define A_STG (128*AST)              // 2560 words
#define W_STG (16*WST)               // 2176 words
#define STG_WORDS (A_STG + W_STG)    // 4736 words
#define GEMM_SMEM_BYTES (4*STG_WORDS*4)   // 75776 B

__device__ __forceinline__ void gemm_issue(
    u32 sb, int c, int NCH, const float* A, const float* W,
    int K, int N, int rowBase, int colBase, int tid)
{
    if (c < NCH) {
        int k0 = c * 16;
        u32 as = sb + (u32)((c & 3) * STG_WORDS) * 4u;
        u32 ws = as + A_STG * 4u;
        int f0 = tid, f1 = tid + 256;
        cpa(as + (u32)((f0 >> 2) * AST + (f0 & 3) * 4) * 4u,
            A + (size_t)(rowBase + (f0 >> 2)) * K + k0 + (f0 & 3) * 4);
        cpa(as + (u32)((f1 >> 2) * AST + (f1 & 3) * 4) * 4u,
            A + (size_t)(rowBase + (f1 >> 2)) * K + k0 + (f1 & 3) * 4);
        cpa(ws + (u32)((f0 >> 5) * WST + (f0 & 31) * 4) * 4u,
            W + (size_t)(k0 + (f0 >> 5)) * N + colBase + (f0 & 31) * 4);
        cpa(ws + (u32)((f1 >> 5) * WST + (f1 & 31) * 4) * 4u,
            W + (size_t)(k0 + (f1 >> 5)) * N + colBase + (f1 & 31) * 4);
    }
    CP_COMMIT();
}

__device__ __forceinline__ void gemm_tc_body(
    const float* __restrict__ A, const float* __restrict__ W,
    const float* __restrict__ bias, const float* __restrict__ resid,
    float* __restrict__ C, int N, int K, int doRelu, int headStore,
    int rowBase, int colBase, float* smem)
{
    int tid = threadIdx.x;
    int w = tid >> 5, t = tid & 31;
    int wr = w >> 1, wc = w & 1;
    int tq = t >> 2, tr = t & 3;
    u32 sb = s2u(smem);
    int NCH = K >> 4;

    float4 acc[2][8];
#pragma unroll
    for (int f = 0; f < 2; f++)
#pragma unroll
        for (int nf = 0; nf < 8; nf++) acc[f][nf] = make_float4(0.f,0.f,0.f,0.f);

    gemm_issue(sb, 0, NCH, A, W, K, N, rowBase, colBase, tid);
    gemm_issue(sb, 1, NCH, A, W, K, N, rowBase, colBase, tid);
    gemm_issue(sb, 2, NCH, A, W, K, N, rowBase, colBase, tid);

    for (int i = 0; i < NCH; i++) {
        CP_WAIT2();
        __syncthreads();
        gemm_issue(sb, i + 3, NCH, A, W, K, N, rowBase, colBase, tid);

        const float* As = smem + (i & 3) * STG_WORDS;
        const float* Ws = As + A_STG;
#pragma unroll
        for (int kh = 0; kh < 2; kh++) {
            u32 a0[2], a1[2], a2[2], a3[2];
#pragma unroll
            for (int f = 0; f < 2; f++) {
                int rb = wr * 32 + f * 16;
                a0[f] = fu(As[(rb + tq) * AST + kh * 8 + tr]);
                a1[f] = fu(As[(rb + tq + 8) * AST + kh * 8 + tr]);
                a2[f] = fu(As[(rb + tq) * AST + kh * 8 + tr + 4]);
                a3[f] = fu(As[(rb + tq + 8) * AST + kh * 8 + tr + 4]);
            }
#pragma unroll
            for (int nf = 0; nf < 8; nf++) {
                int n = wc * 64 + nf * 8 + tq;
                u32 b0 = fu(Ws[(kh * 8 + tr) * WST + n]);
                u32 b1 = fu(Ws[(kh * 8 + tr + 4) * WST + n]);
#pragma unroll
                for (int f = 0; f < 2; f++)
                    mma8(acc[f][nf], a0[f], a1[f], a2[f], a3[f], b0, b1);
            }
        }
    }

#pragma unroll
    for (int f = 0; f < 2; f++) {
        int row = rowBase + wr * 32 + f * 16 + tq;
#pragma unroll
        for (int nf = 0; nf < 8; nf++) {
            int col = colBase + wc * 64 + nf * 8 + tr * 2;
            float b0 = bias[col], b1 = bias[col + 1];
            float c00 = acc[f][nf].x + b0, c01 = acc[f][nf].y + b1;
            float c10 = acc[f][nf].z + b0, c11 = acc[f][nf].w + b1;
            if (resid) {
                float2 r0 = *(const float2*)(resid + (size_t)row * N + col);
                float2 r1 = *(const float2*)(resid + (size_t)(row + 8) * N + col);
                c00 += r0.x; c01 += r0.y; c10 += r1.x; c11 += r1.y;
            }
            if (doRelu) {
                c00 = fmaxf(c00, 0.f); c01 = fmaxf(c01, 0.f);
                c10 = fmaxf(c10, 0.f); c11 = fmaxf(c11, 0.f);
            }
            if (headStore) {
                int h_ = col >> 6, d_ = col & 63;
                int b0_ = row / SS_, s0_ = row % SS_;
                *(float2*)&C[(((size_t)(b0_ * HH + h_)) * SS_ + s0_) * 64 + d_] =
                    make_float2(c00, c01);
                int b1_ = (row + 8) / SS_, s1_ = (row + 8) % SS_;
                *(float2*)&C[(((size_t)(b1_ * HH + h_)) * SS_ + s1_) * 64 + d_] =
                    make_float2(c10, c11);
            } else {
                *(float2*)&C[(size_t)row * N + col] = make_float2(c00, c01);
                *(float2*)&C[(size_t)(row + 8) * N + col] = make_float2(c10, c11);
            }
        }
    }
}

__global__ __launch_bounds__(256, 2) void sgemm_kernel(
    const float* __restrict__ A, const float* __restrict__ W,
    const float* __restrict__ bias, const float* __restrict__ resid,
    float* __restrict__ C, int N, int K, int doRelu, int headStore)
{
    extern __shared__ float smem[];
    gemm_tc_body(A, W, bias, resid, C, N, K, doRelu, headStore,
                 blockIdx.y * 128, blockIdx.x * 128, smem);
}

__global__ __launch_bounds__(256, 2) void qkv_kernel(
    const float* __restrict__ A,
    const float* __restrict__ Wq, const float* __restrict__ bq,
    const float* __restrict__ Wk, const float* __restrict__ bk,
    const float* __restrict__ Wv, const float* __restrict__ bv,
    float* __restrict__ q, float* __restrict__ k, float* __restrict__ v)
{
    extern __shared__ float smem[];
    int sel = blockIdx.x >> 2;
    const float* W = (sel == 0) ? Wq : (sel == 1) ? Wk : Wv;
    const float* bias = (sel == 0) ? bq : (sel == 1) ? bk : bv;
    float* C = (sel == 0) ? q : (sel == 1) ? k : v;
    gemm_tc_body(A, W, bias, nullptr, C, DD, DD, 0, 1,
                 blockIdx.y * 128, (blockIdx.x & 3) * 128, smem);
}

// ------------------------------ attention kernel A -------------------------
// scores + mask + softmax + normalized attn write. NO P@V (separate kernel).
#define SSP 2052
#define KROW 68
#define KBUF (128*KROW)
#define ATTN_SMEM_FLOATS (16*SSP + 16*68 + 16 + 1024 + 2*KBUF)
#define ATTN_SMEM_BYTES  (ATTN_SMEM_FLOATS * 4)

__global__ __launch_bounds__(256) void attn_kernel(
    const float* __restrict__ q, const float* __restrict__ k,
    const void* __restrict__ mask, float* __restrict__ attn)
{
    extern __shared__ float smem[];
    float* ss   = smem;
    float* qs   = smem + 16 * SSP;
    float* invs = qs + 16 * 68;
    u32*  mb    = (u32*)(invs + 16);
    float* kv   = (float*)(mb + 1024);

    int tid = threadIdx.x;
    int w = tid >> 5, t = tid & 31;
    int tq = t >> 2, tr = t & 3;
    int bh = blockIdx.y, b_ = bh >> 3;
    int row0 = blockIdx.x * 16;
    int mm = g_maskmode;

    const float* qptr = q + ((size_t)bh * SS_ + row0) * 64;
    const float* kptr = k + (size_t)bh * SS_ * 64;

    {
        int r = tid >> 4, c = tid & 15;
        ((float4*)(qs + r * 68))[c] = ((const float4*)(qptr + r * 64))[c];
    }

    if (mm == 0) {
        const int4* mp4 = (const int4*)((const int*)mask +
                          (size_t)b_ * SS_ * SS_ + (size_t)row0 * SS_);
#pragma unroll
        for (int j = 0; j < 32; j++) {
            int idx = j * 256 + tid;
            int4 m = mp4[idx];
            u32 nib = (m.x ? 1u : 0u) | (m.y ? 2u : 0u) |
                      (m.z ? 4u : 0u) | (m.w ? 8u : 0u);
            u32 oth = __shfl_down_sync(0xffffffffu, nib, 1);
            u32 byt = (nib | (oth << 4)) & 0xffu;
            u32 c1 = __shfl_down_sync(0xffffffffu, byt, 2);
            u32 c2 = __shfl_down_sync(0xffffffffu, byt, 4);
            u32 c3 = __shfl_down_sync(0xffffffffu, byt, 6);
            if ((t & 7) == 0)
                mb[idx >> 3] = byt | (c1 << 8) | (c2 << 16) | (c3 << 24);
        }
    } else {
        const int4* mp4 = (const int4*)((const unsigned char*)mask +
                          (size_t)b_ * SS_ * SS_ + (size_t)row0 * SS_);
#pragma unroll
        for (int j = 0; j < 8; j++) {
            int idx = j * 256 + tid;
            int4 m = mp4[idx];
            u32 bits = 0;
            u32 vv[4] = {(u32)m.x, (u32)m.y, (u32)m.z, (u32)m.w};
#pragma unroll
            for (int e = 0; e < 4; e++) {
                u32 x = vv[e];
                bits |= ((x & 0x000000ffu) ? 1u : 0u) << (e * 4 + 0);
                bits |= ((x & 0x0000ff00u) ? 1u : 0u) << (e * 4 + 1);
                bits |= ((x & 0x00ff0000u) ? 1u : 0u) << (e * 4 + 2);
                bits |= ((x & 0xff000000u) ? 1u : 0u) << (e * 4 + 3);
            }
            u32 hi = __shfl_down_sync(0xffffffffu, bits, 1);
            if ((t & 1) == 0)
                mb[idx >> 1] = (bits & 0xffffu) | (hi << 16);
        }
    }
    __syncthreads();

    u32 qa0[8], qa1[8], qa2[8], qa3[8];
#pragma unroll
    for (int j = 0; j < 8; j++) {
        qa0[j] = fu(qs[tq * 68 + j * 8 + tr]);
        qa1[j] = fu(qs[(tq + 8) * 68 + j * 8 + tr]);
        qa2[j] = fu(qs[tq * 68 + j * 8 + tr + 4]);
        qa3[j] = fu(qs[(tq + 8) * 68 + j * 8 + tr + 4]);
    }

    const float4* kg = (const float4*)kptr;
    float4 kreg[8];
#pragma unroll
    for (int i = 0; i < 8; i++) kreg[i] = kg[tid + i * 256];

    int kb0 = w * 16 + tq, kb1 = w * 16 + 8 + tq;
    for (int nb = 0; nb < 16; nb++) {
        float* Kb = kv + (nb & 1) * KBUF;
#pragma unroll
        for (int i = 0; i < 8; i++) {
            int f = tid + i * 256;
            *(float4*)&Kb[(f >> 4) * KROW + (f & 15) * 4] = kreg[i];
        }
        __syncthreads();
        int nbn = (nb < 15) ? nb + 1 : nb;
#pragma unroll
        for (int i = 0; i < 8; i++) kreg[i] = kg[nbn * 2048 + tid + i * 256];

        const u32* Kw = (const u32*)Kb;
        float4 A0 = make_float4(0.f,0.f,0.f,0.f), A1 = A0;
#pragma unroll
        for (int j = 0; j < 8; j++) {
            u32 b0 = Kw[kb0 * KROW + j * 8 + tr];
            u32 b1 = Kw[kb0 * KROW + j * 8 + tr + 4];
            u32 c0 = Kw[kb1 * KROW + j * 8 + tr];
            u32 c1 = Kw[kb1 * KROW + j * 8 + tr + 4];
            mma8(A0, qa0[j], qa1[j], qa2[j], qa3[j], b0, b1);
            mma8(A1, qa0[j], qa1[j], qa2[j], qa3[j], c0, c1);
        }
#pragma unroll
        for (int s = 0; s < 2; s++) {
            float4 a = s ? A1 : A0;
            int c = nb * 128 + w * 16 + s * 8 + tr * 2;
            u32 mw0 = mb[tq * 64 + (c >> 5)];
            u32 mw1 = mb[(tq + 8) * 64 + (c >> 5)];
            int sh = c & 31;
            float2 s0, s1;
            s0.x = ((mw0 >> sh) & 1u)       ? -1e9f : a.x * 0.125f;
            s0.y = ((mw0 >> (sh + 1)) & 1u) ? -1e9f : a.y * 0.125f;
            s1.x = ((mw1 >> sh) & 1u)       ? -1e9f : a.z * 0.125f;
            s1.y = ((mw1 >> (sh + 1)) & 1u) ? -1e9f : a.w * 0.125f;
            *(float2*)&ss[tq * SSP + c] = s0;
            *(float2*)&ss[(tq + 8) * SSP + c] = s1;
        }
    }
    __syncthreads();

    {
        int wy = w, lx = t;
        float mx0 = -1e30f, mx1 = -1e30f;
#pragma unroll
        for (int ct = 0; ct < 16; ct++) {
            int c0 = ct * 128 + lx * 4;
            float4 x0 = *(float4*)&ss[wy * SSP + c0];
            float4 x1 = *(float4*)&ss[(wy + 8) * SSP + c0];
            mx0 = fmaxf(mx0, fmaxf(fmaxf(x0.x, x0.y), fmaxf(x0.z, x0.w)));
            mx1 = fmaxf(mx1, fmaxf(fmaxf(x1.x, x1.y), fmaxf(x1.z, x1.w)));
        }
#pragma unroll
        for (int o = 16; o; o >>= 1) {
            mx0 = fmaxf(mx0, __shfl_xor_sync(0xffffffffu, mx0, o));
            mx1 = fmaxf(mx1, __shfl_xor_sync(0xffffffffu, mx1, o));
        }
        float sm0 = 0.f, sm1 = 0.f;
#pragma unroll
        for (int ct = 0; ct < 16; ct++) {
            int c0 = ct * 128 + lx * 4;
            float4 x0 = *(float4*)&ss[wy * SSP + c0];
            float4 x1 = *(float4*)&ss[(wy + 8) * SSP + c0];
            x0.x = __expf(x0.x - mx0); x0.y = __expf(x0.y - mx0);
            x0.z = __expf(x0.z - mx0); x0.w = __expf(x0.w - mx0);
            x1.x = __expf(x1.x - mx1); x1.y = __expf(x1.y - mx1);
            x1.z = __expf(x1.z - mx1); x1.w = __expf(x1.w - mx1);
            sm0 += x0.x + x0.y + x0.z + x0.w;
            sm1 += x1.x + x1.y + x1.z + x1.w;
            *(float4*)&ss[wy * SSP + c0] = x0;
            *(float4*)&ss[(wy + 8) * SSP + c0] = x1;
        }
#pragma unroll
        for (int o = 16; o; o >>= 1) {
            sm0 += __shfl_xor_sync(0xffffffffu, sm0, o);
            sm1 += __shfl_xor_sync(0xffffffffu, sm1, o);
        }
        float inv0 = 1.f / sm0, inv1 = 1.f / sm1;
        int bh2 = blockIdx.y;
#pragma unroll
        for (int ct = 0; ct < 16; ct++) {
            int c0 = ct * 128 + lx * 4;
            float4 x0 = *(float4*)&ss[wy * SSP + c0];
            float4 x1 = *(float4*)&ss[(wy + 8) * SSP + c0];
            x0.x *= inv0; x0.y *= inv0; x0.z *= inv0; x0.w *= inv0;
            x1.x *= inv1; x1.y *= inv1; x1.z *= inv1; x1.w *= inv1;
            *(float4*)(attn + ((size_t)bh2 * SS_ + row0 + wy) * SS_ + c0) = x0;
            *(float4*)(attn + ((size_t)bh2 * SS_ + row0 + wy + 8) * SS_ + c0) = x1;
        }
    }
}

// ------------------------------ pv: ctx = attn @ V (4-stage cp.async) ------
// grid (16 row-tiles, 16 bh), 256 thr = 8 warps, warp = 16 rows x 64 dims.
#define PAST 20
#define PA_STG (128*PAST)           // 2560 words
#define PVST 72
#define PV_STG (16*PVST)            // 1152 words
#define PSTG_WORDS (PA_STG + PV_STG)   // 3712 words
#define PV_SMEM_BYTES (4*PSTG_WORDS*4) // 59392 B

__device__ __forceinline__ void pv_issue(
    u32 sb, int c, const float* P, const float* V, int tid)
{
    if (c < 128) {
        int k0 = c * 16;
        u32 as = sb + (u32)((c & 3) * PSTG_WORDS) * 4u;
        u32 vs = as + PA_STG * 4u;
        int f0 = tid, f1 = tid + 256;
        cpa(as + (u32)((f0 >> 2) * PAST + (f0 & 3) * 4) * 4u,
            P + (size_t)(f0 >> 2) * SS_ + k0 + (f0 & 3) * 4);
        cpa(as + (u32)((f1 >> 2) * PAST + (f1 & 3) * 4) * 4u,
            P + (size_t)(f1 >> 2) * SS_ + k0 + (f1 & 3) * 4);
        cpa(vs + (u32)((tid >> 4) * PVST + (tid & 15) * 4) * 4u,
            V + (size_t)(k0 + (tid >> 4)) * 64 + (tid & 15) * 4);
    }
    CP_COMMIT();
}

__global__ __launch_bounds__(256, 2) void pv_kernel(
    const float* __restrict__ attn, const float* __restrict__ v,
    float* __restrict__ ctx)
{
    extern __shared__ float smem[];
    int tid = threadIdx.x;
    int w = tid >> 5, t = tid & 31;
    int tq = t >> 2, tr = t & 3;
    int bh = blockIdx.y, b_ = bh >> 3, h_ = bh & 7;
    int row0 = blockIdx.x * 128;
    u32 sb = s2u(smem);

    const float* P = attn + (size_t)bh * SS_ * SS_ + (size_t)row0 * SS_;
    const float* V = v + (size_t)bh * SS_ * 64;

    float4 acc[8];
#pragma unroll
    for (int nf = 0; nf < 8; nf++) acc[nf] = make_float4(0.f,0.f,0.f,0.f);

    pv_issue(sb, 0, P, V, tid);
    pv_issue(sb, 1, P, V, tid);
    pv_issue(sb, 2, P, V, tid);

    for (int i = 0; i < 128; i++) {
        CP_WAIT2();
        __syncthreads();
        pv_issue(sb, i + 3, P, V, tid);

        const float* As = smem + (i & 3) * PSTG_WORDS;
        const float* Vs = As + PA_STG;
        int rb = w * 16;
#pragma unroll
        for (int kh = 0; kh < 2; kh++) {
            u32 a0 = fu(As[(rb + tq) * PAST + kh * 8 + tr]);
            u32 a1 = fu(As[(rb + tq + 8) * PAST + kh * 8 + tr]);
            u32 a2 = fu(As[(rb + tq) * PAST + kh * 8 + tr + 4]);
            u32 a3 = fu(As[(rb + tq + 8) * PAST + kh * 8 + tr + 4]);
#pragma unroll
            for (int nf = 0; nf < 8; nf++) {
                int n = nf * 8 + tq;
                u32 b0 = fu(Vs[(kh * 8 + tr) * PVST + n]);
                u32 b1 = fu(Vs[(kh * 8 + tr + 4) * PVST + n]);
                mma8(acc[nf], a0, a1, a2, a3, b0, b1);
            }
        }
    }

    int r0 = row0 + w * 16 + tq;
#pragma unroll
    for (int nf = 0; nf < 8; nf++) {
        int col = h_ * 64 + nf * 8 + tr * 2;
        *(float2*)&ctx[((size_t)(b_ * SS_ + r0)) * DD + col] =
            make_float2(acc[nf].x, acc[nf].y);
        *(float2*)&ctx[((size_t)(b_ * SS_ + r0 + 8)) * DD + col] =
            make_float2(acc[nf].z, acc[nf].w);
    }
}

// ------------------------------ layernorm ----------------------------------
__global__ __launch_bounds__(128) void ln_kernel(
    const float* __restrict__ x, const float* __restrict__ gamma,
    const float* __restrict__ beta, float* __restrict__ out)
{
    int row = blockIdx.x;
    int tid = threadIdx.x;
    __shared__ float red[4];
    float4 v = ((const float4*)(x + (size_t)row * DD))[tid];
    float s = v.x + v.y + v.z + v.w;
#pragma unroll
    for (int o = 16; o; o >>= 1) s += __shfl_xor_sync(0xffffffffu, s, o);
    if ((tid & 31) == 0) red[tid >> 5] = s;
    __syncthreads();
    float mu = (red[0] + red[1] + red[2] + red[3]) * (1.f / DD);
    float dx = v.x - mu, dy = v.y - mu, dz = v.z - mu, dw = v.w - mu;
    float s2 = dx * dx + dy * dy + dz * dz + dw * dw;
#pragma unroll
    for (int o = 16; o; o >>= 1) s2 += __shfl_xor_sync(0xffffffffu, s2, o);
    __syncthreads();
    if ((tid & 31) == 0) red[tid >> 5] = s2;
    __syncthreads();
    float var = (red[0] + red[1] + red[2] + red[3]) * (1.f / DD);
    float inv = rsqrtf(var + EPS);
    float4 gg = ((const float4*)gamma)[tid];
    float4 bb = ((const float4*)beta)[tid];
    float4 o;
    o.x = dx * inv * gg.x + bb.x;
    o.y = dy * inv * gg.y + bb.y;
    o.z = dz * inv * gg.z + bb.z;
    o.w = dw * inv * gg.w + bb.w;
    *(float4*)(out + (size_t)row * DD + tid * 4) = o;
}

// ------------------------------ launch -------------------------------------
extern "C" void kernel_launch(void* const* d_in, const int* in_sizes, int n_in,
                              void* d_out, int out_size)
{
    const float* x   = (const float*)d_in[0];
    const void*  mask = d_in[1];
    const float* Wq  = (const float*)d_in[2];
    const float* bq  = (const float*)d_in[3];
    const float* Wk  = (const float*)d_in[4];
    const float* bk  = (const float*)d_in[5];
    const float* Wv  = (const float*)d_in[6];
    const float* bv  = (const float*)d_in[7];
    const float* Wo  = (const float*)d_in[8];
    const float* bo  = (const float*)d_in[9];
    const float* ln1g = (const float*)d_in[10];
    const float* ln1b = (const float*)d_in[11];
    const float* W1  = (const float*)d_in[12];
    const float* b1  = (const float*)d_in[13];
    const float* W2  = (const float*)d_in[14];
    const float* b2  = (const float*)d_in[15];
    const float* ln2g = (const float*)d_in[16];
    const float* ln2b = (const float*)d_in[17];

    float* out = (float*)d_out;
    const long OUT_ELEMS = (long)BB * SS_ * DD;
    const long ATTN_ELEMS = (long)BB * HH * SS_ * SS_;

    float *qp, *kp, *vp, *ctxp, *t1p, *aop, *hp, *t2p, *attnScratch;
    cudaGetSymbolAddress((void**)&qp, g_qb);
    cudaGetSymbolAddress((void**)&kp, g_kb);
    cudaGetSymbolAddress((void**)&vp, g_vb);
    cudaGetSymbolAddress((void**)&ctxp, g_ctx);
    cudaGetSymbolAddress((void**)&t1p, g_t1);
    cudaGetSymbolAddress((void**)&aop, g_ao);
    cudaGetSymbolAddress((void**)&hp, g_h);
    cudaGetSymbolAddress((void**)&t2p, g_t2);
    cudaGetSymbolAddress((void**)&attnScratch, g_attn);

    float* attn_ptr = ((long)out_size >= OUT_ELEMS + ATTN_ELEMS)
                        ? (out + OUT_ELEMS) : attnScratch;

    cudaFuncSetAttribute(attn_kernel,
                         cudaFuncAttributeMaxDynamicSharedMemorySize,
                         ATTN_SMEM_BYTES);
    cudaFuncSetAttribute(sgemm_kernel,
                         cudaFuncAttributeMaxDynamicSharedMemorySize,
                         GEMM_SMEM_BYTES);
    cudaFuncSetAttribute(qkv_kernel,
                         cudaFuncAttributeMaxDynamicSharedMemorySize,
                         GEMM_SMEM_BYTES);
    cudaFuncSetAttribute(pv_kernel,
                         cudaFuncAttributeMaxDynamicSharedMemorySize,
                         PV_SMEM_BYTES);

    dim3 blk(256);
    detect_mask_kernel<<<1, 32>>>((const unsigned int*)mask);
    qkv_kernel<<<dim3(12, 32), blk, GEMM_SMEM_BYTES>>>(
        x, Wq, bq, Wk, bk, Wv, bv, qp, kp, vp);
    attn_kernel<<<dim3(SS_ / 16, BB * HH), blk, ATTN_SMEM_BYTES>>>(
        qp, kp, mask, attn_ptr);
    pv_kernel<<<dim3(16, BB * HH), blk, PV_SMEM_BYTES>>>(attn_ptr, vp, ctxp);
    sgemm_kernel<<<dim3(4, 32), blk, GEMM_SMEM_BYTES>>>(
        ctxp, Wo, bo, x, t1p, DD, DD, 0, 0);
    ln_kernel<<<NTOK, 128>>>(t1p, ln1g, ln1b, aop);
    sgemm_kernel<<<dim3(16, 32), blk, GEMM_SMEM_BYTES>>>(
        aop, W1, b1, nullptr, hp, DFF, DD, 1, 0);
    sgemm_kernel<<<dim3(4, 32), blk, GEMM_SMEM_BYTES>>>(
        hp, W2, b2, aop, t2p, DD, DFF, 0, 0);
    ln_kernel<<<NTOK, 128>>>(t2p, ln2g, ln2b, out);
}

// round 14
// speedup vs baseline: 3.4278x; 1.1098x over previous
#include <cuda_runtime.h>
#include <math.h>

#define BB 2
#define SS_ 2048
#define DD 512
#define HH 8
#define DFF 2048
#define NTOK (BB*SS_)          // 4096
#define EPS 1e-5f

typedef unsigned long long ull;
typedef unsigned int u32;

// tf32 mma: HW reads high 19 bits; pass raw fp32 bits (CUTLASS-style).
__device__ __forceinline__ u32 fu(float x) { return __float_as_uint(x); }
__device__ __forceinline__ void mma8(float4& d, u32 a0, u32 a1, u32 a2, u32 a3,
                                     u32 b0, u32 b1) {
    asm("mma.sync.aligned.m16n8k8.row.col.f32.tf32.tf32.f32 "
        "{%0,%1,%2,%3},{%4,%5,%6,%7},{%8,%9},{%0,%1,%2,%3};"
        : "+f"(d.x), "+f"(d.y), "+f"(d.z), "+f"(d.w)
        : "r"(a0), "r"(a1), "r"(a2), "r"(a3), "r"(b0), "r"(b1));
}
__device__ __forceinline__ u32 s2u(const void* p) {
    return (u32)__cvta_generic_to_shared(p);
}
__device__ __forceinline__ void cpa(u32 dst, const void* src) {
    asm volatile("cp.async.cg.shared.global [%0], [%1], 16;"
                 :: "r"(dst), "l"(src));
}
#define CP_COMMIT() asm volatile("cp.async.commit_group;" ::: "memory")
#define CP_WAIT2()  asm volatile("cp.async.wait_group 2;" ::: "memory")
#define CP_WAIT0()  asm volatile("cp.async.wait_group 0;" ::: "memory")

// ------------------------------ scratch ------------------------------------
__device__ float g_qb[BB*HH*SS_*64];
__device__ float g_kb[BB*HH*SS_*64];
__device__ float g_vb[BB*HH*SS_*64];
__device__ float g_ctx[NTOK*DD];
__device__ float g_t1[NTOK*DD];
__device__ float g_ao[NTOK*DD];
__device__ float g_h[NTOK*DFF];
__device__ float g_t2[NTOK*DD];
__device__ float g_attn[(size_t)BB*HH*SS_*SS_];   // fallback if attn not in d_out
__device__ int   g_maskmode;               // 0 = int32 mask, 1 = uint8 mask

__global__ void detect_mask_kernel(const unsigned int* __restrict__ m)
{
    if (threadIdx.x == 0 && blockIdx.x == 0) {
        int mode = 0;
        for (int i = 0; i < 4096; i++) {
            if (m[i] > 1u) { mode = 1; break; }
        }
        g_maskmode = mode;
    }
}

// ------------------------------ tf32 GEMM (4-stage cp.async) ---------------
#define AST 20
#define WST 136
#define A_STG (128*AST)
#define W_STG (16*WST)
#define STG_WORDS (A_STG + W_STG)
#define GEMM_SMEM_BYTES (4*STG_WORDS*4)

__device__ __forceinline__ void gemm_issue(
    u32 sb, int c, int NCH, const float* A, const float* W,
    int K, int N, int rowBase, int colBase, int tid)
{
    if (c < NCH) {
        int k0 = c * 16;
        u32 as = sb + (u32)((c & 3) * STG_WORDS) * 4u;
        u32 ws = as + A_STG * 4u;
        int f0 = tid, f1 = tid + 256;
        cpa(as + (u32)((f0 >> 2) * AST + (f0 & 3) * 4) * 4u,
            A + (size_t)(rowBase + (f0 >> 2)) * K + k0 + (f0 & 3) * 4);
        cpa(as + (u32)((f1 >> 2) * AST + (f1 & 3) * 4) * 4u,
            A + (size_t)(rowBase + (f1 >> 2)) * K + k0 + (f1 & 3) * 4);
        cpa(ws + (u32)((f0 >> 5) * WST + (f0 & 31) * 4) * 4u,
            W + (size_t)(k0 + (f0 >> 5)) * N + colBase + (f0 & 31) * 4);
        cpa(ws + (u32)((f1 >> 5) * WST + (f1 & 31) * 4) * 4u,
            W + (size_t)(k0 + (f1 >> 5)) * N + colBase + (f1 & 31) * 4);
    }
    CP_COMMIT();
}

__device__ __forceinline__ void gemm_tc_body(
    const float* __restrict__ A, const float* __restrict__ W,
    const float* __restrict__ bias, const float* __restrict__ resid,
    float* __restrict__ C, int N, int K, int doRelu, int headStore,
    int rowBase, int colBase, float* smem)
{
    int tid = threadIdx.x;
    int w = tid >> 5, t = tid & 31;
    int wr = w >> 1, wc = w & 1;
    int tq = t >> 2, tr = t & 3;
    u32 sb = s2u(smem);
    int NCH = K >> 4;

    float4 acc[2][8];
#pragma unroll
    for (int f = 0; f < 2; f++)
#pragma unroll
        for (int nf = 0; nf < 8; nf++) acc[f][nf] = make_float4(0.f,0.f,0.f,0.f);

    gemm_issue(sb, 0, NCH, A, W, K, N, rowBase, colBase, tid);
    gemm_issue(sb, 1, NCH, A, W, K, N, rowBase, colBase, tid);
    gemm_issue(sb, 2, NCH, A, W, K, N, rowBase, colBase, tid);

    for (int i = 0; i < NCH; i++) {
        CP_WAIT2();
        __syncthreads();
        gemm_issue(sb, i + 3, NCH, A, W, K, N, rowBase, colBase, tid);

        const float* As = smem + (i & 3) * STG_WORDS;
        const float* Ws = As + A_STG;
#pragma unroll
        for (int kh = 0; kh < 2; kh++) {
            u32 a0[2], a1[2], a2[2], a3[2];
#pragma unroll
            for (int f = 0; f < 2; f++) {
                int rb = wr * 32 + f * 16;
                a0[f] = fu(As[(rb + tq) * AST + kh * 8 + tr]);
                a1[f] = fu(As[(rb + tq + 8) * AST + kh * 8 + tr]);
                a2[f] = fu(As[(rb + tq) * AST + kh * 8 + tr + 4]);
                a3[f] = fu(As[(rb + tq + 8) * AST + kh * 8 + tr + 4]);
            }
#pragma unroll
            for (int nf = 0; nf < 8; nf++) {
                int n = wc * 64 + nf * 8 + tq;
                u32 b0 = fu(Ws[(kh * 8 + tr) * WST + n]);
                u32 b1 = fu(Ws[(kh * 8 + tr + 4) * WST + n]);
#pragma unroll
                for (int f = 0; f < 2; f++)
                    mma8(acc[f][nf], a0[f], a1[f], a2[f], a3[f], b0, b1);
            }
        }
    }

#pragma unroll
    for (int f = 0; f < 2; f++) {
        int row = rowBase + wr * 32 + f * 16 + tq;
#pragma unroll
        for (int nf = 0; nf < 8; nf++) {
            int col = colBase + wc * 64 + nf * 8 + tr * 2;
            float b0 = bias[col], b1 = bias[col + 1];
            float c00 = acc[f][nf].x + b0, c01 = acc[f][nf].y + b1;
            float c10 = acc[f][nf].z + b0, c11 = acc[f][nf].w + b1;
            if (resid) {
                float2 r0 = *(const float2*)(resid + (size_t)row * N + col);
                float2 r1 = *(const float2*)(resid + (size_t)(row + 8) * N + col);
                c00 += r0.x; c01 += r0.y; c10 += r1.x; c11 += r1.y;
            }
            if (doRelu) {
                c00 = fmaxf(c00, 0.f); c01 = fmaxf(c01, 0.f);
                c10 = fmaxf(c10, 0.f); c11 = fmaxf(c11, 0.f);
            }
            if (headStore) {
                int h_ = col >> 6, d_ = col & 63;
                int b0_ = row / SS_, s0_ = row % SS_;
                *(float2*)&C[(((size_t)(b0_ * HH + h_)) * SS_ + s0_) * 64 + d_] =
                    make_float2(c00, c01);
                int b1_ = (row + 8) / SS_, s1_ = (row + 8) % SS_;
                *(float2*)&C[(((size_t)(b1_ * HH + h_)) * SS_ + s1_) * 64 + d_] =
                    make_float2(c10, c11);
            } else {
                *(float2*)&C[(size_t)row * N + col] = make_float2(c00, c01);
                *(float2*)&C[(size_t)(row + 8) * N + col] = make_float2(c10, c11);
            }
        }
    }
}

__global__ __launch_bounds__(256, 2) void sgemm_kernel(
    const float* __restrict__ A, const float* __restrict__ W,
    const float* __restrict__ bias, const float* __restrict__ resid,
    float* __restrict__ C, int N, int K, int doRelu, int headStore)
{
    extern __shared__ float smem[];
    gemm_tc_body(A, W, bias, resid, C, N, K, doRelu, headStore,
                 blockIdx.y * 128, blockIdx.x * 128, smem);
}

__global__ __launch_bounds__(256, 2) void qkv_kernel(
    const float* __restrict__ A,
    const float* __restrict__ Wq, const float* __restrict__ bq,
    const float* __restrict__ Wk, const float* __restrict__ bk,
    const float* __restrict__ Wv, const float* __restrict__ bv,
    float* __restrict__ q, float* __restrict__ k, float* __restrict__ v)
{
    extern __shared__ float smem[];
    int sel = blockIdx.x >> 2;
    const float* W = (sel == 0) ? Wq : (sel == 1) ? Wk : Wv;
    const float* bias = (sel == 0) ? bq : (sel == 1) ? bk : bv;
    float* C = (sel == 0) ? q : (sel == 1) ? k : v;
    gemm_tc_body(A, W, bias, nullptr, C, DD, DD, 0, 1,
                 blockIdx.y * 128, (blockIdx.x & 3) * 128, smem);
}

// ------------------------------ qk: S = mask(Q K^T / 8) --------------------
// grid (16 key-tiles, 16 row-tiles, 16 bh), 256 thr = 8 warps (4x2).
// K-depth = 64: load both tiles once via cp.async, single sync, no k-loop.
#define QKT 68                        // tile row stride (words)
#define QK_TILE (128*QKT)             // 8704 words per tile
#define QK_SMEM_BYTES (2*QK_TILE*4)   // 69632 B

__global__ __launch_bounds__(256, 2) void qk_kernel(
    const float* __restrict__ q, const float* __restrict__ k,
    const void* __restrict__ mask, float* __restrict__ attn)
{
    extern __shared__ float smem[];
    float* Qs = smem;                 // [128][68]
    float* Ks = smem + QK_TILE;       // [128][68]

    int tid = threadIdx.x;
    int w = tid >> 5, t = tid & 31;
    int wr = w >> 1, wc = w & 1;
    int tq = t >> 2, tr = t & 3;
    int bh = blockIdx.z, b_ = bh >> 3;
    int row0 = blockIdx.y * 128;
    int col0 = blockIdx.x * 128;
    int mm = g_maskmode;

    const float* qptr = q + ((size_t)bh * SS_ + row0) * 64;
    const float* kptr = k + ((size_t)bh * SS_ + col0) * 64;
    u32 sb = s2u(smem);

    // load Q and K tiles (128x64 each) via cp.async
#pragma unroll
    for (int i = 0; i < 8; i++) {
        int f = tid + i * 256;
        int r = f >> 4, c4 = (f & 15) * 4;
        cpa(sb + (u32)(r * QKT + c4) * 4u, qptr + (size_t)r * 64 + c4);
        cpa(sb + (u32)(QK_TILE + r * QKT + c4) * 4u, kptr + (size_t)r * 64 + c4);
    }
    CP_COMMIT();
    CP_WAIT0();
    __syncthreads();

    float4 acc[2][8];
#pragma unroll
    for (int f = 0; f < 2; f++)
#pragma unroll
        for (int nf = 0; nf < 8; nf++) acc[f][nf] = make_float4(0.f,0.f,0.f,0.f);

#pragma unroll
    for (int j = 0; j < 8; j++) {
        u32 a0[2], a1[2], a2[2], a3[2];
#pragma unroll
        for (int f = 0; f < 2; f++) {
            int rb = wr * 32 + f * 16;
            a0[f] = fu(Qs[(rb + tq) * QKT + j * 8 + tr]);
            a1[f] = fu(Qs[(rb + tq + 8) * QKT + j * 8 + tr]);
            a2[f] = fu(Qs[(rb + tq) * QKT + j * 8 + tr + 4]);
            a3[f] = fu(Qs[(rb + tq + 8) * QKT + j * 8 + tr + 4]);
        }
#pragma unroll
        for (int nf = 0; nf < 8; nf++) {
            int n = wc * 64 + nf * 8 + tq;
            u32 b0 = fu(Ks[n * QKT + j * 8 + tr]);
            u32 b1 = fu(Ks[n * QKT + j * 8 + tr + 4]);
#pragma unroll
            for (int f = 0; f < 2; f++)
                mma8(acc[f][nf], a0[f], a1[f], a2[f], a3[f], b0, b1);
        }
    }

    // epilogue: scale, mask, write raw scores
    const int* mp32 = (const int*)mask + (size_t)b_ * SS_ * SS_;
    const unsigned char* mp8 = (const unsigned char*)mask + (size_t)b_ * SS_ * SS_;
#pragma unroll
    for (int f = 0; f < 2; f++) {
        int row = row0 + wr * 32 + f * 16 + tq;
#pragma unroll
        for (int nf = 0; nf < 8; nf++) {
            int col = col0 + wc * 64 + nf * 8 + tr * 2;
            float4 a = acc[f][nf];
            int m0a, m0b, m1a, m1b;
            if (mm == 0) {
                int2 u = *(const int2*)(mp32 + (size_t)row * SS_ + col);
                int2 v2 = *(const int2*)(mp32 + (size_t)(row + 8) * SS_ + col);
                m0a = u.x; m0b = u.y; m1a = v2.x; m1b = v2.y;
            } else {
                uchar2 u = *(const uchar2*)(mp8 + (size_t)row * SS_ + col);
                uchar2 v2 = *(const uchar2*)(mp8 + (size_t)(row + 8) * SS_ + col);
                m0a = u.x; m0b = u.y; m1a = v2.x; m1b = v2.y;
            }
            float2 s0, s1;
            s0.x = m0a ? -1e9f : a.x * 0.125f;
            s0.y = m0b ? -1e9f : a.y * 0.125f;
            s1.x = m1a ? -1e9f : a.z * 0.125f;
            s1.y = m1b ? -1e9f : a.w * 0.125f;
            *(float2*)&attn[((size_t)bh * SS_ + row) * SS_ + col] = s0;
            *(float2*)&attn[((size_t)bh * SS_ + row + 8) * SS_ + col] = s1;
        }
    }
}

// ------------------------------ softmax: normalize rows in place -----------
// One warp per row (2048 floats = 64/lane in registers). grid 4096 x 256thr.
__global__ __launch_bounds__(256) void softmax_kernel(float* __restrict__ attn)
{
    int w = threadIdx.x >> 5, lane = threadIdx.x & 31;
    size_t row = (size_t)blockIdx.x * 8 + w;      // 0 .. 32767
    float4* p = (float4*)(attn + row * SS_);

    float4 v[16];
#pragma unroll
    for (int i = 0; i < 16; i++) v[i] = p[lane + i * 32];

    float mx = -1e30f;
#pragma unroll
    for (int i = 0; i < 16; i++) {
        mx = fmaxf(mx, fmaxf(fmaxf(v[i].x, v[i].y), fmaxf(v[i].z, v[i].w)));
    }
#pragma unroll
    for (int o = 16; o; o >>= 1)
        mx = fmaxf(mx, __shfl_xor_sync(0xffffffffu, mx, o));

    float sm = 0.f;
#pragma unroll
    for (int i = 0; i < 16; i++) {
        v[i].x = __expf(v[i].x - mx); v[i].y = __expf(v[i].y - mx);
        v[i].z = __expf(v[i].z - mx); v[i].w = __expf(v[i].w - mx);
        sm += v[i].x + v[i].y + v[i].z + v[i].w;
    }
#pragma unroll
    for (int o = 16; o; o >>= 1)
        sm += __shfl_xor_sync(0xffffffffu, sm, o);
    float inv = 1.f / sm;

#pragma unroll
    for (int i = 0; i < 16; i++) {
        v[i].x *= inv; v[i].y *= inv; v[i].z *= inv; v[i].w *= inv;
        p[lane + i * 32] = v[i];
    }
}

// ------------------------------ pv: ctx = attn @ V (4-stage cp.async) ------
#define PAST 20
#define PA_STG (128*PAST)
#define PVST 72
#define PV_STG (16*PVST)
#define PSTG_WORDS (PA_STG + PV_STG)
#define PV_SMEM_BYTES (4*PSTG_WORDS*4)

__device__ __forceinline__ void pv_issue(
    u32 sb, int c, const float* P, const float* V, int tid)
{
    if (c < 128) {
        int k0 = c * 16;
        u32 as = sb + (u32)((c & 3) * PSTG_WORDS) * 4u;
        u32 vs = as + PA_STG * 4u;
        int f0 = tid, f1 = tid + 256;
        cpa(as + (u32)((f0 >> 2) * PAST + (f0 & 3) * 4) * 4u,
            P + (size_t)(f0 >> 2) * SS_ + k0 + (f0 & 3) * 4);
        cpa(as + (u32)((f1 >> 2) * PAST + (f1 & 3) * 4) * 4u,
            P + (size_t)(f1 >> 2) * SS_ + k0 + (f1 & 3) * 4);
        cpa(vs + (u32)((tid >> 4) * PVST + (tid & 15) * 4) * 4u,
            V + (size_t)(k0 + (tid >> 4)) * 64 + (tid & 15) * 4);
    }
    CP_COMMIT();
}

__global__ __launch_bounds__(256, 2) void pv_kernel(
    const float* __restrict__ attn, const float* __restrict__ v,
    float* __restrict__ ctx)
{
    extern __shared__ float smem[];
    int tid = threadIdx.x;
    int w = tid >> 5, t = tid & 31;
    int tq = t >> 2, tr = t & 3;
    int bh = blockIdx.y, b_ = bh >> 3, h_ = bh & 7;
    int row0 = blockIdx.x * 128;
    u32 sb = s2u(smem);

    const float* P = attn + (size_t)bh * SS_ * SS_ + (size_t)row0 * SS_;
    const float* V = v + (size_t)bh * SS_ * 64;

    float4 acc[8];
#pragma unroll
    for (int nf = 0; nf < 8; nf++) acc[nf] = make_float4(0.f,0.f,0.f,0.f);

    pv_issue(sb, 0, P, V, tid);
    pv_issue(sb, 1, P, V, tid);
    pv_issue(sb, 2, P, V, tid);

    for (int i = 0; i < 128; i++) {
        CP_WAIT2();
        __syncthreads();
        pv_issue(sb, i + 3, P, V, tid);

        const float* As = smem + (i & 3) * PSTG_WORDS;
        const float* Vs = As + PA_STG;
        int rb = w * 16;
#pragma unroll
        for (int kh = 0; kh < 2; kh++) {
            u32 a0 = fu(As[(rb + tq) * PAST + kh * 8 + tr]);
            u32 a1 = fu(As[(rb + tq + 8) * PAST + kh * 8 + tr]);
            u32 a2 = fu(As[(rb + tq) * PAST + kh * 8 + tr + 4]);
            u32 a3 = fu(As[(rb + tq + 8) * PAST + kh * 8 + tr + 4]);
#pragma unroll
            for (int nf = 0; nf < 8; nf++) {
                int n = nf * 8 + tq;
                u32 b0 = fu(Vs[(kh * 8 + tr) * PVST + n]);
                u32 b1 = fu(Vs[(kh * 8 + tr + 4) * PVST + n]);
                mma8(acc[nf], a0, a1, a2, a3, b0, b1);
            }
        }
    }

    int r0 = row0 + w * 16 + tq;
#pragma unroll
    for (int nf = 0; nf < 8; nf++) {
        int col = h_ * 64 + nf * 8 + tr * 2;
        *(float2*)&ctx[((size_t)(b_ * SS_ + r0)) * DD + col] =
            make_float2(acc[nf].x, acc[nf].y);
        *(float2*)&ctx[((size_t)(b_ * SS_ + r0 + 8)) * DD + col] =
            make_float2(acc[nf].z, acc[nf].w);
    }
}

// ------------------------------ layernorm ----------------------------------
__global__ __launch_bounds__(128) void ln_kernel(
    const float* __restrict__ x, const float* __restrict__ gamma,
    const float* __restrict__ beta, float* __restrict__ out)
{
    int row = blockIdx.x;
    int tid = threadIdx.x;
    __shared__ float red[4];
    float4 v = ((const float4*)(x + (size_t)row * DD))[tid];
    float s = v.x + v.y + v.z + v.w;
#pragma unroll
    for (int o = 16; o; o >>= 1) s += __shfl_xor_sync(0xffffffffu, s, o);
    if ((tid & 31) == 0) red[tid >> 5] = s;
    __syncthreads();
    float mu = (red[0] + red[1] + red[2] + red[3]) * (1.f / DD);
    float dx = v.x - mu, dy = v.y - mu, dz = v.z - mu, dw = v.w - mu;
    float s2 = dx * dx + dy * dy + dz * dz + dw * dw;
#pragma unroll
    for (int o = 16; o; o >>= 1) s2 += __shfl_xor_sync(0xffffffffu, s2, o);
    __syncthreads();
    if ((tid & 31) == 0) red[tid >> 5] = s2;
    __syncthreads();
    float var = (red[0] + red[1] + red[2] + red[3]) * (1.f / DD);
    float inv = rsqrtf(var + EPS);
    float4 gg = ((const float4*)gamma)[tid];
    float4 bb = ((const float4*)beta)[tid];
    float4 o;
    o.x = dx * inv * gg.x + bb.x;
    o.y = dy * inv * gg.y + bb.y;
    o.z = dz * inv * gg.z + bb.z;
    o.w = dw * inv * gg.w + bb.w;
    *(float4*)(out + (size_t)row * DD + tid * 4) = o;
}

// ------------------------------ launch -------------------------------------
extern "C" void kernel_launch(void* const* d_in, const int* in_sizes, int n_in,
                              void* d_out, int out_size)
{
    const float* x   = (const float*)d_in[0];
    const void*  mask = d_in[1];
    const float* Wq  = (const float*)d_in[2];
    const float* bq  = (const float*)d_in[3];
    const float* Wk  = (const float*)d_in[4];
    const float* bk  = (const float*)d_in[5];
    const float* Wv  = (const float*)d_in[6];
    const float* bv  = (const float*)d_in[7];
    const float* Wo  = (const float*)d_in[8];
    const float* bo  = (const float*)d_in[9];
    const float* ln1g = (const float*)d_in[10];
    const float* ln1b = (const float*)d_in[11];
    const float* W1  = (const float*)d_in[12];
    const float* b1  = (const float*)d_in[13];
    const float* W2  = (const float*)d_in[14];
    const float* b2  = (const float*)d_in[15];
    const float* ln2g = (const float*)d_in[16];
    const float* ln2b = (const float*)d_in[17];

    float* out = (float*)d_out;
    const long OUT_ELEMS = (long)BB * SS_ * DD;
    const long ATTN_ELEMS = (long)BB * HH * SS_ * SS_;

    float *qp, *kp, *vp, *ctxp, *t1p, *aop, *hp, *t2p, *attnScratch;
    cudaGetSymbolAddress((void**)&qp, g_qb);
    cudaGetSymbolAddress((void**)&kp, g_kb);
    cudaGetSymbolAddress((void**)&vp, g_vb);
    cudaGetSymbolAddress((void**)&ctxp, g_ctx);
    cudaGetSymbolAddress((void**)&t1p, g_t1);
    cudaGetSymbolAddress((void**)&aop, g_ao);
    cudaGetSymbolAddress((void**)&hp, g_h);
    cudaGetSymbolAddress((void**)&t2p, g_t2);
    cudaGetSymbolAddress((void**)&attnScratch, g_attn);

    float* attn_ptr = ((long)out_size >= OUT_ELEMS + ATTN_ELEMS)
                        ? (out + OUT_ELEMS) : attnScratch;

    cudaFuncSetAttribute(sgemm_kernel,
                         cudaFuncAttributeMaxDynamicSharedMemorySize,
                         GEMM_SMEM_BYTES);
    cudaFuncSetAttribute(qkv_kernel,
                         cudaFuncAttributeMaxDynamicSharedMemorySize,
                         GEMM_SMEM_BYTES);
    cudaFuncSetAttribute(qk_kernel,
                         cudaFuncAttributeMaxDynamicSharedMemorySize,
                         QK_SMEM_BYTES);
    cudaFuncSetAttribute(pv_kernel,
                         cudaFuncAttributeMaxDynamicSharedMemorySize,
                         PV_SMEM_BYTES);

    dim3 blk(256);
    detect_mask_kernel<<<1, 32>>>((const unsigned int*)mask);
    qkv_kernel<<<dim3(12, 32), blk, GEMM_SMEM_BYTES>>>(
        x, Wq, bq, Wk, bk, Wv, bv, qp, kp, vp);
    qk_kernel<<<dim3(16, 16, BB * HH), blk, QK_SMEM_BYTES>>>(
        qp, kp, mask, attn_ptr);
    softmax_kernel<<<BB * HH * SS_ / 8, blk>>>(attn_ptr);
    pv_kernel<<<dim3(16, BB * HH), blk, PV_SMEM_BYTES>>>(attn_ptr, vp, ctxp);
    sgemm_kernel<<<dim3(4, 32), blk, GEMM_SMEM_BYTES>>>(
        ctxp, Wo, bo, x, t1p, DD, DD, 0, 0);
    ln_kernel<<<NTOK, 128>>>(t1p, ln1g, ln1b, aop);
    sgemm_kernel<<<dim3(16, 32), blk, GEMM_SMEM_BYTES>>>(
        aop, W1, b1, nullptr, hp, DFF, DD, 1, 0);
    sgemm_kernel<<<dim3(4, 32), blk, GEMM_SMEM_BYTES>>>(
        hp, W2, b2, aop, t2p, DD, DFF, 0, 0);
    ln_kernel<<<NTOK, 128>>>(t2p, ln2g, ln2b, out);
}